// round 4
// baseline (speedup 1.0000x reference)
#include <cuda_runtime.h>
#include <math.h>

#define NQ 1024
#define NB 8
#define MM 1024
#define CC 640
#define RR 8192
#define NITER 100
#define EPS_INV 20.0f
#define NU_P (1.0f/1024.0f + 1e-8f)

__device__ float g_q[RR*CC];
__device__ float g_k[RR*CC];
__device__ float g_v[RR*CC];
__device__ float g_x[RR*CC];
__device__ float g_sim[NB*MM*NQ];
__device__ float g_E[NB*MM*NQ];
__device__ float g_c[(NITER+1)*RR];
__device__ float g_a[RR];
__device__ float g_mu[RR];
__device__ float g_bfin[RR];
__device__ unsigned char g_maskb[RR];
__device__ int g_counts[NB];
__device__ int g_mfmt;

__device__ __forceinline__ int getmask_raw(const void* m, int idx, int fmt) {
    if (fmt == 1) return ((const int*)m)[idx] != 0;
    if (fmt == 2) return ((const float*)m)[idx] != 0.0f;
    return ((const unsigned char*)m)[idx] != 0;
}

// classify mask dtype by byte pattern over the first RR bytes:
// int32 bools -> only bytes i%4==0 nonzero; float32 (1.0f) -> only bytes
// i%4 in {2,3} nonzero; byte/bool -> nonzeros in mixed positions.
__global__ void k_detect(const unsigned char* m) {
    __shared__ int cA, cB;
    if (threadIdx.x == 0) { cA = 0; cB = 0; }
    __syncthreads();
    int a = 0, b = 0;
    for (int i = threadIdx.x; i < RR; i += blockDim.x) {
        if (m[i] != 0) { if ((i & 3) == 0) a = 1; else b = 1; }
    }
    if (a) atomicOr(&cA, 1);
    if (b) atomicOr(&cB, 1);
    __syncthreads();
    if (threadIdx.x == 0) g_mfmt = (cB == 0) ? 1 : ((cA == 0) ? 2 : 0);
}

__global__ void k_counts(const void* mask) {
    __shared__ int sh[256];
    int fmt = g_mfmt, bb = blockIdx.x, s = 0;
    for (int m = threadIdx.x; m < MM; m += 256) s += getmask_raw(mask, bb*MM + m, fmt);
    sh[threadIdx.x] = s; __syncthreads();
    for (int o = 128; o; o >>= 1) { if (threadIdx.x < o) sh[threadIdx.x] += sh[threadIdx.x + o]; __syncthreads(); }
    if (threadIdx.x == 0) g_counts[bb] = (sh[0] > 0) ? sh[0] : 1;
}

__global__ void k_init(const void* mask) {
    int idx = blockIdx.x * blockDim.x + threadIdx.x;
    if (idx < (NITER+1)*RR) g_c[idx] = (idx < RR) ? NU_P : 0.0f;
    if (idx < RR) {
        int fmt = g_mfmt;
        int mk = getmask_raw(mask, idx, fmt);
        g_maskb[idx] = (unsigned char)mk;
        g_mu[idx] = mk ? (1.0f/(float)g_counts[idx >> 10] + 1e-8f) : 0.0f;
    }
}

// C[r][j] = sum_t A[r][t]*B[j][t] + bias[j]; A: rows x 640, B: 640 x 640
__global__ __launch_bounds__(256) void k_gemm_nt(const float* __restrict__ A,
                                                 const float* __restrict__ Bw,
                                                 const float* __restrict__ bias,
                                                 float* __restrict__ Co) {
    __shared__ float As[8][128];
    __shared__ float Bs[8][128];
    const int i0 = blockIdx.x * 128, j0 = blockIdx.y * 128;
    const int tid = threadIdx.x, tx = tid & 15, ty = tid >> 4;
    const int li = tid >> 1, lk = (tid & 1) * 4;
    float acc[8][8];
    #pragma unroll
    for (int i = 0; i < 8; i++)
        #pragma unroll
        for (int j = 0; j < 8; j++) acc[i][j] = 0.0f;
    const float* Ap = A  + (size_t)(i0 + li) * CC + lk;
    const float* Bp = Bw + (size_t)(j0 + li) * CC + lk;
    for (int k0 = 0; k0 < CC; k0 += 8) {
        float4 va = *(const float4*)(Ap + k0);
        float4 vb = *(const float4*)(Bp + k0);
        As[lk+0][li]=va.x; As[lk+1][li]=va.y; As[lk+2][li]=va.z; As[lk+3][li]=va.w;
        Bs[lk+0][li]=vb.x; Bs[lk+1][li]=vb.y; Bs[lk+2][li]=vb.z; Bs[lk+3][li]=vb.w;
        __syncthreads();
        #pragma unroll
        for (int kk = 0; kk < 8; kk++) {
            float ar[8], br[8];
            *(float4*)(ar)   = *(const float4*)&As[kk][ty*8];
            *(float4*)(ar+4) = *(const float4*)&As[kk][ty*8+4];
            *(float4*)(br)   = *(const float4*)&Bs[kk][tx*8];
            *(float4*)(br+4) = *(const float4*)&Bs[kk][tx*8+4];
            #pragma unroll
            for (int i = 0; i < 8; i++)
                #pragma unroll
                for (int j = 0; j < 8; j++) acc[i][j] += ar[i]*br[j];
        }
        __syncthreads();
    }
    #pragma unroll
    for (int i = 0; i < 8; i++) {
        int row = i0 + ty*8 + i;
        #pragma unroll
        for (int j = 0; j < 8; j++) {
            int col = j0 + tx*8 + j;
            Co[(size_t)row * CC + col] = acc[i][j] + bias[col];
        }
    }
}

__global__ void k_l2norm(float* p) {
    __shared__ float sh[256];
    float* row = p + (size_t)blockIdx.x * CC;
    float s = 0.0f;
    for (int i = threadIdx.x; i < CC; i += 256) { float v = row[i]; s += v*v; }
    sh[threadIdx.x] = s; __syncthreads();
    for (int o = 128; o; o >>= 1) { if (threadIdx.x < o) sh[threadIdx.x] += sh[threadIdx.x + o]; __syncthreads(); }
    float inv = 1.0f / fmaxf(sqrtf(sh[0]), 1e-12f);
    for (int i = threadIdx.x; i < CC; i += 256) row[i] *= inv;
}

// sim[b][m][n] = k[b][m].q[n][b]; E = mask_m ? exp((sim-1)/eps) : 0
__global__ __launch_bounds__(256) void k_simE() {
    __shared__ float As[8][128];
    __shared__ float Bs[8][128];
    const int bb = blockIdx.z, m0 = blockIdx.x * 128, n0 = blockIdx.y * 128;
    const int tid = threadIdx.x, tx = tid & 15, ty = tid >> 4;
    const int li = tid >> 1, lk = (tid & 1) * 4;
    float acc[8][8];
    #pragma unroll
    for (int i = 0; i < 8; i++)
        #pragma unroll
        for (int j = 0; j < 8; j++) acc[i][j] = 0.0f;
    const float* Ap = g_k + (size_t)bb*MM*CC + (size_t)(m0 + li)*CC + lk;
    const float* Bp = g_q + (size_t)bb*CC    + (size_t)(n0 + li)*(NB*CC) + lk;
    for (int k0 = 0; k0 < CC; k0 += 8) {
        float4 va = *(const float4*)(Ap + k0);
        float4 vb = *(const float4*)(Bp + k0);
        As[lk+0][li]=va.x; As[lk+1][li]=va.y; As[lk+2][li]=va.z; As[lk+3][li]=va.w;
        Bs[lk+0][li]=vb.x; Bs[lk+1][li]=vb.y; Bs[lk+2][li]=vb.z; Bs[lk+3][li]=vb.w;
        __syncthreads();
        #pragma unroll
        for (int kk = 0; kk < 8; kk++) {
            float ar[8], br[8];
            *(float4*)(ar)   = *(const float4*)&As[kk][ty*8];
            *(float4*)(ar+4) = *(const float4*)&As[kk][ty*8+4];
            *(float4*)(br)   = *(const float4*)&Bs[kk][tx*8];
            *(float4*)(br+4) = *(const float4*)&Bs[kk][tx*8+4];
            #pragma unroll
            for (int i = 0; i < 8; i++)
                #pragma unroll
                for (int j = 0; j < 8; j++) acc[i][j] += ar[i]*br[j];
        }
        __syncthreads();
    }
    #pragma unroll
    for (int i = 0; i < 8; i++) {
        int m = m0 + ty*8 + i;
        int mk = g_maskb[bb*MM + m];
        size_t base = ((size_t)bb*MM + m) * NQ + n0 + tx*8;
        #pragma unroll
        for (int j = 0; j < 8; j++) {
            float s = acc[i][j];
            g_sim[base + j] = s;
            g_E[base + j] = mk ? expf((s - 1.0f) * EPS_INV) : 0.0f;
        }
    }
}

// one Sinkhorn iteration: b = nu'/c[it-1]; a_m = mu'_m / (E b)_m; c[it] += a^T E
__global__ __launch_bounds__(256) void k_sinkhorn(int it) {
    __shared__ float sh[8*1024];
    const int bb = blockIdx.x >> 4, rb = blockIdx.x & 15;
    const int warp = threadIdx.x >> 5, lane = threadIdx.x & 31;
    const float* cp = g_c + (size_t)(it-1)*RR + bb*NQ;
    float bv[32];
    #pragma unroll
    for (int g = 0; g < 8; g++) {
        float4 t = *(const float4*)(cp + g*128 + lane*4);
        bv[g*4+0]=NU_P/t.x; bv[g*4+1]=NU_P/t.y; bv[g*4+2]=NU_P/t.z; bv[g*4+3]=NU_P/t.w;
    }
    float cacc[32];
    #pragma unroll
    for (int q = 0; q < 32; q++) cacc[q] = 0.0f;
    const float* Eb = g_E + (size_t)bb*MM*NQ;
    const int m0 = rb*64 + warp*8;
    #pragma unroll
    for (int rr = 0; rr < 8; rr++) {
        int m = m0 + rr;
        if (!g_maskb[bb*MM + m]) { if (lane == 0) g_a[bb*MM + m] = 0.0f; continue; }
        const float4* er = (const float4*)(Eb + (size_t)m * NQ);
        float e[32], s = 0.0f;
        #pragma unroll
        for (int g = 0; g < 8; g++) {
            float4 v = er[g*32 + lane];
            e[g*4+0]=v.x; e[g*4+1]=v.y; e[g*4+2]=v.z; e[g*4+3]=v.w;
            s += v.x*bv[g*4+0] + v.y*bv[g*4+1] + v.z*bv[g*4+2] + v.w*bv[g*4+3];
        }
        #pragma unroll
        for (int o = 16; o; o >>= 1) s += __shfl_xor_sync(0xffffffffu, s, o);
        float a = g_mu[bb*MM + m] / s;
        if (lane == 0) g_a[bb*MM + m] = a;
        #pragma unroll
        for (int q = 0; q < 32; q++) cacc[q] += a * e[q];
    }
    #pragma unroll
    for (int g = 0; g < 8; g++)
        *(float4*)&sh[warp*1024 + g*128 + lane*4] =
            make_float4(cacc[g*4], cacc[g*4+1], cacc[g*4+2], cacc[g*4+3]);
    __syncthreads();
    float* cn = g_c + (size_t)it*RR + bb*NQ;
    int col = threadIdx.x * 4;
    float s0=0, s1=0, s2=0, s3=0;
    #pragma unroll
    for (int w = 0; w < 8; w++) {
        float4 v = *(const float4*)&sh[w*1024 + col];
        s0 += v.x; s1 += v.y; s2 += v.z; s3 += v.w;
    }
    atomicAdd(&cn[col+0], s0); atomicAdd(&cn[col+1], s1);
    atomicAdd(&cn[col+2], s2); atomicAdd(&cn[col+3], s3);
}

__global__ void k_bfinal() {
    int i = blockIdx.x * blockDim.x + threadIdx.x;
    if (i < RR) g_bfin[i] = NU_P / g_c[(size_t)NITER*RR + i];
}

// x[n][b][c] = bfin_n * sum_m E[b][m][n] * (a_m * v[b][m][c])
__global__ __launch_bounds__(256) void k_xgemm() {
    __shared__ float As[8][128];
    __shared__ float Bs[8][128];
    const int bb = blockIdx.z, n0 = blockIdx.x * 128, c0 = blockIdx.y * 128;
    const int tid = threadIdx.x, tx = tid & 15, ty = tid >> 4;
    const int lr = tid >> 5, lc = (tid & 31) * 4;
    float acc[8][8];
    #pragma unroll
    for (int i = 0; i < 8; i++)
        #pragma unroll
        for (int j = 0; j < 8; j++) acc[i][j] = 0.0f;
    const float* Eb = g_E + (size_t)bb*MM*NQ;
    const float* Vb = g_v + (size_t)bb*MM*CC;
    for (int k0 = 0; k0 < MM; k0 += 8) {
        float4 ea = *(const float4*)(Eb + (size_t)(k0 + lr)*NQ + n0 + lc);
        float am = g_a[bb*MM + k0 + lr];
        float4 vb = *(const float4*)(Vb + (size_t)(k0 + lr)*CC + c0 + lc);
        *(float4*)&As[lr][lc] = ea;
        Bs[lr][lc+0]=vb.x*am; Bs[lr][lc+1]=vb.y*am; Bs[lr][lc+2]=vb.z*am; Bs[lr][lc+3]=vb.w*am;
        __syncthreads();
        #pragma unroll
        for (int kk = 0; kk < 8; kk++) {
            float ar[8], br[8];
            *(float4*)(ar)   = *(const float4*)&As[kk][ty*8];
            *(float4*)(ar+4) = *(const float4*)&As[kk][ty*8+4];
            *(float4*)(br)   = *(const float4*)&Bs[kk][tx*8];
            *(float4*)(br+4) = *(const float4*)&Bs[kk][tx*8+4];
            #pragma unroll
            for (int i = 0; i < 8; i++)
                #pragma unroll
                for (int j = 0; j < 8; j++) acc[i][j] += ar[i]*br[j];
        }
        __syncthreads();
    }
    #pragma unroll
    for (int i = 0; i < 8; i++) {
        int n = n0 + ty*8 + i;
        float bn = g_bfin[bb*NQ + n];
        #pragma unroll
        for (int j = 0; j < 8; j++)
            g_x[((size_t)n*NB + bb)*CC + c0 + tx*8 + j] = acc[i][j] * bn;
    }
}

// attn_save[b][m] = mask ? M*Nq * a_m * sum_n sim*E*bfin_n : 0
__global__ void k_attn(float* outp) {
    const int warp = threadIdx.x >> 5, lane = threadIdx.x & 31;
    int r = blockIdx.x * 8 + warp;
    if (r >= RR) return;
    int bb = r >> 10;
    float val = 0.0f;
    if (g_maskb[r]) {
        const float* S = g_sim + (size_t)r * NQ;
        const float* E = g_E + (size_t)r * NQ;
        const float* bf = g_bfin + bb * NQ;
        float s = 0.0f;
        #pragma unroll
        for (int g = 0; g < 8; g++) {
            int n = g*128 + lane*4;
            float4 sv = *(const float4*)(S + n);
            float4 ev = *(const float4*)(E + n);
            float4 bv = *(const float4*)(bf + n);
            s += sv.x*ev.x*bv.x + sv.y*ev.y*bv.y + sv.z*ev.z*bv.z + sv.w*ev.w*bv.w;
        }
        #pragma unroll
        for (int o = 16; o; o >>= 1) s += __shfl_xor_sync(0xffffffffu, s, o);
        val = 1048576.0f * g_a[r] * s;
    }
    if (lane == 0) outp[r] = val;
}

extern "C" void kernel_launch(void* const* d_in, const int* in_sizes, int n_in,
                              void* d_out, int out_size) {
    const float* xq = (const float*)d_in[0];
    const float* xk = (const float*)d_in[1];
    const float* xv = (const float*)d_in[2];
    const void*  mk = d_in[3];
    const float* Wq = (const float*)d_in[4];
    const float* bq = (const float*)d_in[5];
    const float* Wk = (const float*)d_in[6];
    const float* bk = (const float*)d_in[7];
    const float* Wv = (const float*)d_in[8];
    const float* bv = (const float*)d_in[9];
    const float* Wp = (const float*)d_in[10];
    const float* bp = (const float*)d_in[11];
    float *qp, *kp, *vp, *xp;
    cudaGetSymbolAddress((void**)&qp, g_q);
    cudaGetSymbolAddress((void**)&kp, g_k);
    cudaGetSymbolAddress((void**)&vp, g_v);
    cudaGetSymbolAddress((void**)&xp, g_x);

    k_detect<<<1, 256>>>((const unsigned char*)mk);
    k_counts<<<NB, 256>>>(mk);
    k_init<<<((NITER+1)*RR + 255)/256, 256>>>(mk);

    dim3 gproj(RR/128, CC/128);
    k_gemm_nt<<<gproj, 256>>>(xq, Wq, bq, qp);
    k_gemm_nt<<<gproj, 256>>>(xk, Wk, bk, kp);
    k_gemm_nt<<<gproj, 256>>>(xv, Wv, bv, vp);
    k_l2norm<<<RR, 256>>>(qp);
    k_l2norm<<<RR, 256>>>(kp);

    k_simE<<<dim3(MM/128, NQ/128, NB), 256>>>();

    for (int it = 1; it <= NITER; it++)
        k_sinkhorn<<<NB*16, 256>>>(it);
    k_bfinal<<<RR/256, 256>>>();

    k_xgemm<<<dim3(NQ/128, CC/128, NB), 256>>>();
    k_gemm_nt<<<gproj, 256>>>(xp, Wp, bp, (float*)d_out);

    if (out_size >= RR*CC + RR)
        k_attn<<<RR/8, 256>>>((float*)d_out + (size_t)RR*CC);
}

// round 5
// speedup vs baseline: 1.1843x; 1.1843x over previous
#include <cuda_runtime.h>
#include <math.h>

#define NQ 1024
#define NB 8
#define MM 1024
#define CC 640
#define RR 8192
#define NITER 100
#define EPS_INV 20.0f
#define NU_P (1.0f/1024.0f + 1e-8f)

__device__ float g_q[RR*CC];
__device__ float g_k[RR*CC];
__device__ float g_v[RR*CC];
__device__ float g_x[RR*CC];
__device__ float g_sim[NB*MM*NQ];
__device__ float g_E[NB*MM*NQ];
__device__ float g_cpart[128*NQ];    // per-block partial column sums
__device__ float g_a[RR];
__device__ float g_mu[RR];
__device__ float g_bfin[RR];
__device__ unsigned char g_maskb[RR];
__device__ int g_counts[NB];
__device__ int g_mfmt;
__device__ unsigned int g_bar;

__device__ __forceinline__ int getmask_raw(const void* m, int idx, int fmt) {
    if (fmt == 1) return ((const int*)m)[idx] != 0;
    if (fmt == 2) return ((const float*)m)[idx] != 0.0f;
    return ((const unsigned char*)m)[idx] != 0;
}

// classify mask dtype by byte pattern over the first RR bytes:
// int32 bools -> nonzero only at i%4==0; float32 (1.0f) -> nonzero only at
// i%4 in {2,3}; byte/bool -> mixed positions.
__global__ void k_detect(const unsigned char* m) {
    __shared__ int cA, cB;
    if (threadIdx.x == 0) { cA = 0; cB = 0; }
    __syncthreads();
    int a = 0, b = 0;
    for (int i = threadIdx.x; i < RR; i += blockDim.x) {
        if (m[i] != 0) { if ((i & 3) == 0) a = 1; else b = 1; }
    }
    if (a) atomicOr(&cA, 1);
    if (b) atomicOr(&cB, 1);
    __syncthreads();
    if (threadIdx.x == 0) g_mfmt = (cB == 0) ? 1 : ((cA == 0) ? 2 : 0);
}

__global__ void k_counts(const void* mask) {
    __shared__ int sh[256];
    int fmt = g_mfmt, bb = blockIdx.x, s = 0;
    for (int m = threadIdx.x; m < MM; m += 256) s += getmask_raw(mask, bb*MM + m, fmt);
    sh[threadIdx.x] = s; __syncthreads();
    for (int o = 128; o; o >>= 1) { if (threadIdx.x < o) sh[threadIdx.x] += sh[threadIdx.x + o]; __syncthreads(); }
    if (threadIdx.x == 0) g_counts[bb] = (sh[0] > 0) ? sh[0] : 1;
}

__global__ void k_init(const void* mask) {
    int idx = blockIdx.x * blockDim.x + threadIdx.x;
    if (idx == 0) g_bar = 0u;
    if (idx < RR) {
        int fmt = g_mfmt;
        int mk = getmask_raw(mask, idx, fmt);
        g_maskb[idx] = (unsigned char)mk;
        g_mu[idx] = mk ? (1.0f/(float)g_counts[idx >> 10] + 1e-8f) : 0.0f;
    }
}

// ---------- double-buffered 128x128 fp32 GEMM core (NT): C=A*B^T+bias ----------
__global__ __launch_bounds__(256) void k_gemm_nt(const float* __restrict__ A,
                                                 const float* __restrict__ Bw,
                                                 const float* __restrict__ bias,
                                                 float* __restrict__ Co) {
    __shared__ float As[2][8][128];
    __shared__ float Bs[2][8][128];
    const int i0 = blockIdx.x * 128, j0 = blockIdx.y * 128;
    const int tid = threadIdx.x, tx = tid & 15, ty = tid >> 4;
    const int li = tid >> 1, lk = (tid & 1) * 4;
    float acc[8][8];
    #pragma unroll
    for (int i = 0; i < 8; i++)
        #pragma unroll
        for (int j = 0; j < 8; j++) acc[i][j] = 0.0f;
    const float* Ap = A  + (size_t)(i0 + li) * CC + lk;
    const float* Bp = Bw + (size_t)(j0 + li) * CC + lk;
    {
        float4 va = *(const float4*)(Ap);
        float4 vb = *(const float4*)(Bp);
        As[0][lk+0][li]=va.x; As[0][lk+1][li]=va.y; As[0][lk+2][li]=va.z; As[0][lk+3][li]=va.w;
        Bs[0][lk+0][li]=vb.x; Bs[0][lk+1][li]=vb.y; Bs[0][lk+2][li]=vb.z; Bs[0][lk+3][li]=vb.w;
    }
    __syncthreads();
    int buf = 0;
    for (int k0 = 8; k0 < CC; k0 += 8) {
        float4 na = *(const float4*)(Ap + k0);
        float4 nb = *(const float4*)(Bp + k0);
        #pragma unroll
        for (int kk = 0; kk < 8; kk++) {
            float ar[8], br[8];
            *(float4*)(ar)   = *(const float4*)&As[buf][kk][ty*8];
            *(float4*)(ar+4) = *(const float4*)&As[buf][kk][ty*8+4];
            *(float4*)(br)   = *(const float4*)&Bs[buf][kk][tx*8];
            *(float4*)(br+4) = *(const float4*)&Bs[buf][kk][tx*8+4];
            #pragma unroll
            for (int i = 0; i < 8; i++)
                #pragma unroll
                for (int j = 0; j < 8; j++) acc[i][j] += ar[i]*br[j];
        }
        int nbuf = buf ^ 1;
        As[nbuf][lk+0][li]=na.x; As[nbuf][lk+1][li]=na.y; As[nbuf][lk+2][li]=na.z; As[nbuf][lk+3][li]=na.w;
        Bs[nbuf][lk+0][li]=nb.x; Bs[nbuf][lk+1][li]=nb.y; Bs[nbuf][lk+2][li]=nb.z; Bs[nbuf][lk+3][li]=nb.w;
        __syncthreads();
        buf = nbuf;
    }
    #pragma unroll
    for (int kk = 0; kk < 8; kk++) {
        float ar[8], br[8];
        *(float4*)(ar)   = *(const float4*)&As[buf][kk][ty*8];
        *(float4*)(ar+4) = *(const float4*)&As[buf][kk][ty*8+4];
        *(float4*)(br)   = *(const float4*)&Bs[buf][kk][tx*8];
        *(float4*)(br+4) = *(const float4*)&Bs[buf][kk][tx*8+4];
        #pragma unroll
        for (int i = 0; i < 8; i++)
            #pragma unroll
            for (int j = 0; j < 8; j++) acc[i][j] += ar[i]*br[j];
    }
    #pragma unroll
    for (int i = 0; i < 8; i++) {
        int row = i0 + ty*8 + i;
        #pragma unroll
        for (int j = 0; j < 8; j++) {
            int col = j0 + tx*8 + j;
            Co[(size_t)row * CC + col] = acc[i][j] + bias[col];
        }
    }
}

__global__ void k_l2norm(float* p) {
    __shared__ float sh[256];
    float* row = p + (size_t)blockIdx.x * CC;
    float s = 0.0f;
    for (int i = threadIdx.x; i < CC; i += 256) { float v = row[i]; s += v*v; }
    sh[threadIdx.x] = s; __syncthreads();
    for (int o = 128; o; o >>= 1) { if (threadIdx.x < o) sh[threadIdx.x] += sh[threadIdx.x + o]; __syncthreads(); }
    float inv = 1.0f / fmaxf(sqrtf(sh[0]), 1e-12f);
    for (int i = threadIdx.x; i < CC; i += 256) row[i] *= inv;
}

// sim[b][m][n] = k[b][m].q[n][b]; E = mask_m ? exp((sim-1)/eps) : 0
__global__ __launch_bounds__(256) void k_simE() {
    __shared__ float As[2][8][128];
    __shared__ float Bs[2][8][128];
    const int bb = blockIdx.z, m0 = blockIdx.x * 128, n0 = blockIdx.y * 128;
    const int tid = threadIdx.x, tx = tid & 15, ty = tid >> 4;
    const int li = tid >> 1, lk = (tid & 1) * 4;
    float acc[8][8];
    #pragma unroll
    for (int i = 0; i < 8; i++)
        #pragma unroll
        for (int j = 0; j < 8; j++) acc[i][j] = 0.0f;
    const float* Ap = g_k + (size_t)bb*MM*CC + (size_t)(m0 + li)*CC + lk;
    const float* Bp = g_q + (size_t)bb*CC    + (size_t)(n0 + li)*(NB*CC) + lk;
    {
        float4 va = *(const float4*)(Ap);
        float4 vb = *(const float4*)(Bp);
        As[0][lk+0][li]=va.x; As[0][lk+1][li]=va.y; As[0][lk+2][li]=va.z; As[0][lk+3][li]=va.w;
        Bs[0][lk+0][li]=vb.x; Bs[0][lk+1][li]=vb.y; Bs[0][lk+2][li]=vb.z; Bs[0][lk+3][li]=vb.w;
    }
    __syncthreads();
    int buf = 0;
    for (int k0 = 8; k0 < CC; k0 += 8) {
        float4 na = *(const float4*)(Ap + k0);
        float4 nb = *(const float4*)(Bp + k0);
        #pragma unroll
        for (int kk = 0; kk < 8; kk++) {
            float ar[8], br[8];
            *(float4*)(ar)   = *(const float4*)&As[buf][kk][ty*8];
            *(float4*)(ar+4) = *(const float4*)&As[buf][kk][ty*8+4];
            *(float4*)(br)   = *(const float4*)&Bs[buf][kk][tx*8];
            *(float4*)(br+4) = *(const float4*)&Bs[buf][kk][tx*8+4];
            #pragma unroll
            for (int i = 0; i < 8; i++)
                #pragma unroll
                for (int j = 0; j < 8; j++) acc[i][j] += ar[i]*br[j];
        }
        int nbuf = buf ^ 1;
        As[nbuf][lk+0][li]=na.x; As[nbuf][lk+1][li]=na.y; As[nbuf][lk+2][li]=na.z; As[nbuf][lk+3][li]=na.w;
        Bs[nbuf][lk+0][li]=nb.x; Bs[nbuf][lk+1][li]=nb.y; Bs[nbuf][lk+2][li]=nb.z; Bs[nbuf][lk+3][li]=nb.w;
        __syncthreads();
        buf = nbuf;
    }
    #pragma unroll
    for (int kk = 0; kk < 8; kk++) {
        float ar[8], br[8];
        *(float4*)(ar)   = *(const float4*)&As[buf][kk][ty*8];
        *(float4*)(ar+4) = *(const float4*)&As[buf][kk][ty*8+4];
        *(float4*)(br)   = *(const float4*)&Bs[buf][kk][tx*8];
        *(float4*)(br+4) = *(const float4*)&Bs[buf][kk][tx*8+4];
        #pragma unroll
        for (int i = 0; i < 8; i++)
            #pragma unroll
            for (int j = 0; j < 8; j++) acc[i][j] += ar[i]*br[j];
    }
    #pragma unroll
    for (int i = 0; i < 8; i++) {
        int m = m0 + ty*8 + i;
        int mk = g_maskb[bb*MM + m];
        size_t base = ((size_t)bb*MM + m) * NQ + n0 + tx*8;
        #pragma unroll
        for (int j = 0; j < 8; j++) {
            float s = acc[i][j];
            g_sim[base + j] = s;
            g_E[base + j] = mk ? expf((s - 1.0f) * EPS_INV) : 0.0f;
        }
    }
}

// ---------- persistent Sinkhorn: 128 co-resident blocks, software grid barrier ----------
// block blk: bb=blk>>4, rb=blk&15, rows m in [rb*64, rb*64+64)
// per iter: a_m = mu_m / (E b)_m ; partial c = a^T E -> g_cpart[blk];
// barrier; b = NU_P / (sum of 16 partials).
__global__ __launch_bounds__(256) void k_sink_pers() {
    __shared__ float sh[8*1024];
    const int blk = blockIdx.x, bb = blk >> 4, rb = blk & 15;
    const int tid = threadIdx.x, warp = tid >> 5, lane = tid & 31;
    const float* Eb = g_E + (size_t)bb*MM*NQ;
    const int m0 = rb*64 + warp*8;
    const int col = tid * 4;
    float bv[32];
    #pragma unroll
    for (int q = 0; q < 32; q++) bv[q] = 1.0f;   // c0 = NU_P -> b = 1
    for (int it = 1; it <= NITER; it++) {
        float cacc[32];
        #pragma unroll
        for (int q = 0; q < 32; q++) cacc[q] = 0.0f;
        #pragma unroll
        for (int rr = 0; rr < 8; rr++) {
            int m = m0 + rr;
            if (!g_maskb[bb*MM + m]) {
                if (it == NITER && lane == 0) g_a[bb*MM + m] = 0.0f;
                continue;
            }
            const float4* er = (const float4*)(Eb + (size_t)m * NQ);
            float e[32], s = 0.0f;
            #pragma unroll
            for (int g = 0; g < 8; g++) {
                float4 v = __ldg(&er[g*32 + lane]);
                e[g*4+0]=v.x; e[g*4+1]=v.y; e[g*4+2]=v.z; e[g*4+3]=v.w;
                s += v.x*bv[g*4+0] + v.y*bv[g*4+1] + v.z*bv[g*4+2] + v.w*bv[g*4+3];
            }
            #pragma unroll
            for (int o = 16; o; o >>= 1) s += __shfl_xor_sync(0xffffffffu, s, o);
            float a = g_mu[bb*MM + m] / s;
            if (it == NITER && lane == 0) g_a[bb*MM + m] = a;
            #pragma unroll
            for (int q = 0; q < 32; q++) cacc[q] += a * e[q];
        }
        // block-level column reduce into g_cpart[blk]
        #pragma unroll
        for (int g = 0; g < 8; g++)
            *(float4*)&sh[warp*1024 + g*128 + lane*4] =
                make_float4(cacc[g*4], cacc[g*4+1], cacc[g*4+2], cacc[g*4+3]);
        __syncthreads();
        float s0=0, s1=0, s2=0, s3=0;
        #pragma unroll
        for (int w = 0; w < 8; w++) {
            float4 v = *(const float4*)&sh[w*1024 + col];
            s0 += v.x; s1 += v.y; s2 += v.z; s3 += v.w;
        }
        *(float4*)&g_cpart[(size_t)blk*NQ + col] = make_float4(s0, s1, s2, s3);
        // grid barrier (cumulative count, no reset)
        __threadfence();
        __syncthreads();
        if (tid == 0) {
            atomicAdd(&g_bar, 1u);
            unsigned int target = (unsigned int)it * 128u;
            while (atomicAdd(&g_bar, 0u) < target) __nanosleep(64);
        }
        __syncthreads();
        __threadfence();
        if (it < NITER) {
            // b for next iter: reduce 16 partials of my batch
            float c0=0, c1=0, c2=0, c3=0;
            #pragma unroll
            for (int w = 0; w < 16; w++) {
                float4 v = *(const float4*)&g_cpart[(size_t)(bb*16 + w)*NQ + col];
                c0 += v.x; c1 += v.y; c2 += v.z; c3 += v.w;
            }
            sh[col+0] = NU_P / c0; sh[col+1] = NU_P / c1;
            sh[col+2] = NU_P / c2; sh[col+3] = NU_P / c3;
            __syncthreads();
            #pragma unroll
            for (int g = 0; g < 8; g++) {
                float4 v = *(const float4*)&sh[g*128 + lane*4];
                bv[g*4+0]=v.x; bv[g*4+1]=v.y; bv[g*4+2]=v.z; bv[g*4+3]=v.w;
            }
            __syncthreads();
        }
    }
    // final b
    if (rb == 0) {
        float c0=0, c1=0, c2=0, c3=0;
        #pragma unroll
        for (int w = 0; w < 16; w++) {
            float4 v = *(const float4*)&g_cpart[(size_t)(bb*16 + w)*NQ + col];
            c0 += v.x; c1 += v.y; c2 += v.z; c3 += v.w;
        }
        g_bfin[bb*NQ+col+0] = NU_P / c0; g_bfin[bb*NQ+col+1] = NU_P / c1;
        g_bfin[bb*NQ+col+2] = NU_P / c2; g_bfin[bb*NQ+col+3] = NU_P / c3;
    }
}

// x[n][b][c] = bfin_n * sum_m E[b][m][n] * (a_m * v[b][m][c])
__global__ __launch_bounds__(256) void k_xgemm() {
    __shared__ float As[2][8][128];
    __shared__ float Bs[2][8][128];
    const int bb = blockIdx.z, n0 = blockIdx.x * 128, c0 = blockIdx.y * 128;
    const int tid = threadIdx.x, tx = tid & 15, ty = tid >> 4;
    const int lr = tid >> 5, lc = (tid & 31) * 4;
    float acc[8][8];
    #pragma unroll
    for (int i = 0; i < 8; i++)
        #pragma unroll
        for (int j = 0; j < 8; j++) acc[i][j] = 0.0f;
    const float* Eb = g_E + (size_t)bb*MM*NQ;
    const float* Vb = g_v + (size_t)bb*MM*CC;
    {
        float4 ea = *(const float4*)(Eb + (size_t)lr*NQ + n0 + lc);
        float am = g_a[bb*MM + lr];
        float4 vb = *(const float4*)(Vb + (size_t)lr*CC + c0 + lc);
        *(float4*)&As[0][lr][lc] = ea;
        Bs[0][lr][lc+0]=vb.x*am; Bs[0][lr][lc+1]=vb.y*am; Bs[0][lr][lc+2]=vb.z*am; Bs[0][lr][lc+3]=vb.w*am;
    }
    __syncthreads();
    int buf = 0;
    for (int k0 = 8; k0 < MM; k0 += 8) {
        float4 ea = *(const float4*)(Eb + (size_t)(k0 + lr)*NQ + n0 + lc);
        float am = g_a[bb*MM + k0 + lr];
        float4 vb = *(const float4*)(Vb + (size_t)(k0 + lr)*CC + c0 + lc);
        #pragma unroll
        for (int kk = 0; kk < 8; kk++) {
            float ar[8], br[8];
            *(float4*)(ar)   = *(const float4*)&As[buf][kk][ty*8];
            *(float4*)(ar+4) = *(const float4*)&As[buf][kk][ty*8+4];
            *(float4*)(br)   = *(const float4*)&Bs[buf][kk][tx*8];
            *(float4*)(br+4) = *(const float4*)&Bs[buf][kk][tx*8+4];
            #pragma unroll
            for (int i = 0; i < 8; i++)
                #pragma unroll
                for (int j = 0; j < 8; j++) acc[i][j] += ar[i]*br[j];
        }
        int nbuf = buf ^ 1;
        *(float4*)&As[nbuf][lr][lc] = ea;
        Bs[nbuf][lr][lc+0]=vb.x*am; Bs[nbuf][lr][lc+1]=vb.y*am; Bs[nbuf][lr][lc+2]=vb.z*am; Bs[nbuf][lr][lc+3]=vb.w*am;
        __syncthreads();
        buf = nbuf;
    }
    #pragma unroll
    for (int kk = 0; kk < 8; kk++) {
        float ar[8], br[8];
        *(float4*)(ar)   = *(const float4*)&As[buf][kk][ty*8];
        *(float4*)(ar+4) = *(const float4*)&As[buf][kk][ty*8+4];
        *(float4*)(br)   = *(const float4*)&Bs[buf][kk][tx*8];
        *(float4*)(br+4) = *(const float4*)&Bs[buf][kk][tx*8+4];
        #pragma unroll
        for (int i = 0; i < 8; i++)
            #pragma unroll
            for (int j = 0; j < 8; j++) acc[i][j] += ar[i]*br[j];
    }
    #pragma unroll
    for (int i = 0; i < 8; i++) {
        int n = n0 + ty*8 + i;
        float bn = g_bfin[bb*NQ + n];
        #pragma unroll
        for (int j = 0; j < 8; j++)
            g_x[((size_t)n*NB + bb)*CC + c0 + tx*8 + j] = acc[i][j] * bn;
    }
}

// attn_save[b][m] = mask ? M*Nq * a_m * sum_n sim*E*bfin_n : 0
__global__ void k_attn(float* outp) {
    const int warp = threadIdx.x >> 5, lane = threadIdx.x & 31;
    int r = blockIdx.x * 8 + warp;
    if (r >= RR) return;
    int bb = r >> 10;
    float val = 0.0f;
    if (g_maskb[r]) {
        const float* S = g_sim + (size_t)r * NQ;
        const float* E = g_E + (size_t)r * NQ;
        const float* bf = g_bfin + bb * NQ;
        float s = 0.0f;
        #pragma unroll
        for (int g = 0; g < 8; g++) {
            int n = g*128 + lane*4;
            float4 sv = *(const float4*)(S + n);
            float4 ev = *(const float4*)(E + n);
            float4 bv = *(const float4*)(bf + n);
            s += sv.x*ev.x*bv.x + sv.y*ev.y*bv.y + sv.z*ev.z*bv.z + sv.w*ev.w*bv.w;
        }
        #pragma unroll
        for (int o = 16; o; o >>= 1) s += __shfl_xor_sync(0xffffffffu, s, o);
        val = 1048576.0f * g_a[r] * s;
    }
    if (lane == 0) outp[r] = val;
}

extern "C" void kernel_launch(void* const* d_in, const int* in_sizes, int n_in,
                              void* d_out, int out_size) {
    const float* xq = (const float*)d_in[0];
    const float* xk = (const float*)d_in[1];
    const float* xv = (const float*)d_in[2];
    const void*  mk = d_in[3];
    const float* Wq = (const float*)d_in[4];
    const float* bq = (const float*)d_in[5];
    const float* Wk = (const float*)d_in[6];
    const float* bk = (const float*)d_in[7];
    const float* Wv = (const float*)d_in[8];
    const float* bv = (const float*)d_in[9];
    const float* Wp = (const float*)d_in[10];
    const float* bp = (const float*)d_in[11];
    float *qp, *kp, *vp, *xp;
    cudaGetSymbolAddress((void**)&qp, g_q);
    cudaGetSymbolAddress((void**)&kp, g_k);
    cudaGetSymbolAddress((void**)&vp, g_v);
    cudaGetSymbolAddress((void**)&xp, g_x);

    k_detect<<<1, 256>>>((const unsigned char*)mk);
    k_counts<<<NB, 256>>>(mk);
    k_init<<<(RR + 255)/256, 256>>>(mk);

    dim3 gproj(RR/128, CC/128);
    k_gemm_nt<<<gproj, 256>>>(xq, Wq, bq, qp);
    k_gemm_nt<<<gproj, 256>>>(xk, Wk, bk, kp);
    k_gemm_nt<<<gproj, 256>>>(xv, Wv, bv, vp);
    k_l2norm<<<RR, 256>>>(qp);
    k_l2norm<<<RR, 256>>>(kp);

    k_simE<<<dim3(MM/128, NQ/128, NB), 256>>>();

    k_sink_pers<<<128, 256>>>();

    k_xgemm<<<dim3(NQ/128, CC/128, NB), 256>>>();
    k_gemm_nt<<<gproj, 256>>>(xp, Wp, bp, (float*)d_out);

    if (out_size >= RR*CC + RR)
        k_attn<<<RR/8, 256>>>((float*)d_out + (size_t)RR*CC);
}

// round 7
// speedup vs baseline: 1.4215x; 1.2003x over previous
#include <cuda_runtime.h>
#include <cuda_bf16.h>
#include <math.h>
#include <stdint.h>

#define NQ 1024
#define NB 8
#define MM 1024
#define CC 640
#define RR 8192
#define NITER 100
#define EPS_INV 20.0f
#define NU_P (1.0f/1024.0f + 1e-8f)

__device__ float g_q[RR*CC];
__device__ float g_k[RR*CC];
__device__ float g_v[RR*CC];
__device__ float g_x[RR*CC];
__device__ float g_sim[NB*MM*NQ];
__device__ float g_E[NB*MM*NQ];
__device__ float g_cpart[128*NQ];
__device__ float g_a[RR];
__device__ float g_mu[RR];
__device__ float g_bfin[RR];
__device__ unsigned char g_maskb[RR];
__device__ int g_counts[NB];
__device__ int g_mfmt;
__device__ unsigned int g_bar;
// bf16 2-way splits for tensor-core GEMMs
__device__ __nv_bfloat16 g_as0[RR*CC];
__device__ __nv_bfloat16 g_as1[RR*CC];
__device__ __nv_bfloat16 g_bs0[CC*CC];
__device__ __nv_bfloat16 g_bs1[CC*CC];

__device__ __forceinline__ int getmask_raw(const void* m, int idx, int fmt) {
    if (fmt == 1) return ((const int*)m)[idx] != 0;
    if (fmt == 2) return ((const float*)m)[idx] != 0.0f;
    return ((const unsigned char*)m)[idx] != 0;
}

__global__ void k_detect(const unsigned char* m) {
    __shared__ int cA, cB;
    if (threadIdx.x == 0) { cA = 0; cB = 0; }
    __syncthreads();
    int a = 0, b = 0;
    for (int i = threadIdx.x; i < RR; i += blockDim.x) {
        if (m[i] != 0) { if ((i & 3) == 0) a = 1; else b = 1; }
    }
    if (a) atomicOr(&cA, 1);
    if (b) atomicOr(&cB, 1);
    __syncthreads();
    if (threadIdx.x == 0) g_mfmt = (cB == 0) ? 1 : ((cA == 0) ? 2 : 0);
}

__global__ void k_counts(const void* mask) {
    __shared__ int sh[256];
    int fmt = g_mfmt, bb = blockIdx.x, s = 0;
    for (int m = threadIdx.x; m < MM; m += 256) s += getmask_raw(mask, bb*MM + m, fmt);
    sh[threadIdx.x] = s; __syncthreads();
    for (int o = 128; o; o >>= 1) { if (threadIdx.x < o) sh[threadIdx.x] += sh[threadIdx.x + o]; __syncthreads(); }
    if (threadIdx.x == 0) g_counts[bb] = (sh[0] > 0) ? sh[0] : 1;
}

__global__ void k_init(const void* mask) {
    int idx = blockIdx.x * blockDim.x + threadIdx.x;
    if (idx == 0) g_bar = 0u;
    if (idx < RR) {
        int fmt = g_mfmt;
        int mk = getmask_raw(mask, idx, fmt);
        g_maskb[idx] = (unsigned char)mk;
        g_mu[idx] = mk ? (1.0f/(float)g_counts[idx >> 10] + 1e-8f) : 0.0f;
    }
}

// 2-way bf16 split: x ~= d0 + d1, ~16-bit effective mantissa
__global__ void k_split2(const float* __restrict__ src,
                         __nv_bfloat16* __restrict__ d0,
                         __nv_bfloat16* __restrict__ d1, int n) {
    int i = blockIdx.x * blockDim.x + threadIdx.x;
    if (i >= n) return;
    float x = src[i];
    __nv_bfloat16 b0 = __float2bfloat16(x);
    float r = x - __bfloat162float(b0);
    d0[i] = b0; d1[i] = __float2bfloat16(r);
}

// ---------- mma.sync bf16x2 NT GEMM: C[r][j] = sum_t A[r][t]*B[j][t] + bias[j] ----------
// 128x128 CTA tile, 8 warps each 64x32; K chunk 32; products A0B0 + A0B1 + A1B0.
#define SPAD 40
__global__ __launch_bounds__(256) void k_gemm_mma(
    const __nv_bfloat16* __restrict__ A0, const __nv_bfloat16* __restrict__ A1,
    const __nv_bfloat16* __restrict__ B0, const __nv_bfloat16* __restrict__ B1,
    const float* __restrict__ bias, float* __restrict__ Co) {
    __shared__ __nv_bfloat16 As[2][128][SPAD];
    __shared__ __nv_bfloat16 Bs[2][128][SPAD];
    const int tid = threadIdx.x, warp = tid >> 5, lane = tid & 31;
    const int g = lane >> 2, tg = lane & 3;
    const int i0 = blockIdx.x * 128, j0 = blockIdx.y * 128;
    const int wm = (warp & 1) * 64, wn = (warp >> 1) * 32;
    float acc[4][4][4];
    #pragma unroll
    for (int mi = 0; mi < 4; mi++)
        #pragma unroll
        for (int ni = 0; ni < 4; ni++)
            #pragma unroll
            for (int e = 0; e < 4; e++) acc[mi][ni][e] = 0.0f;

    const int lrow = tid >> 1;                // 0..127
    const int lseg = (tid & 1) * 2;           // 0 or 2 (two uint4 per thread per row-half)

    for (int k0 = 0; k0 < CC; k0 += 32) {
        // load A0,A1,B0,B1 chunks (128 rows x 32 bf16 each)
        #pragma unroll
        for (int u = 0; u < 2; u++) {
            int seg = lseg + u;               // 0..3, 8 bf16 each
            const __nv_bfloat16* pa0 = A0 + (size_t)(i0 + lrow) * CC + k0 + seg * 8;
            const __nv_bfloat16* pa1 = A1 + (size_t)(i0 + lrow) * CC + k0 + seg * 8;
            const __nv_bfloat16* pb0 = B0 + (size_t)(j0 + lrow) * CC + k0 + seg * 8;
            const __nv_bfloat16* pb1 = B1 + (size_t)(j0 + lrow) * CC + k0 + seg * 8;
            *(uint4*)&As[0][lrow][seg * 8] = *(const uint4*)pa0;
            *(uint4*)&As[1][lrow][seg * 8] = *(const uint4*)pa1;
            *(uint4*)&Bs[0][lrow][seg * 8] = *(const uint4*)pb0;
            *(uint4*)&Bs[1][lrow][seg * 8] = *(const uint4*)pb1;
        }
        __syncthreads();
        #pragma unroll
        for (int kk = 0; kk < 32; kk += 16) {
            uint32_t af[2][4][4], bf[2][4][2];
            #pragma unroll
            for (int s = 0; s < 2; s++) {
                #pragma unroll
                for (int mi = 0; mi < 4; mi++) {
                    int r0 = wm + mi * 16 + g;
                    af[s][mi][0] = *(const uint32_t*)&As[s][r0][kk + tg*2];
                    af[s][mi][1] = *(const uint32_t*)&As[s][r0 + 8][kk + tg*2];
                    af[s][mi][2] = *(const uint32_t*)&As[s][r0][kk + tg*2 + 8];
                    af[s][mi][3] = *(const uint32_t*)&As[s][r0 + 8][kk + tg*2 + 8];
                }
                #pragma unroll
                for (int ni = 0; ni < 4; ni++) {
                    int c0 = wn + ni * 8 + g;
                    bf[s][ni][0] = *(const uint32_t*)&Bs[s][c0][kk + tg*2];
                    bf[s][ni][1] = *(const uint32_t*)&Bs[s][c0][kk + tg*2 + 8];
                }
            }
            #pragma unroll
            for (int p = 0; p < 3; p++) {
                const int sa = (p == 2) ? 1 : 0;
                const int sb = (p == 1) ? 1 : 0;
                #pragma unroll
                for (int mi = 0; mi < 4; mi++)
                    #pragma unroll
                    for (int ni = 0; ni < 4; ni++)
                        asm volatile(
                            "mma.sync.aligned.m16n8k16.row.col.f32.bf16.bf16.f32 "
                            "{%0,%1,%2,%3}, {%4,%5,%6,%7}, {%8,%9}, {%0,%1,%2,%3};"
                            : "+f"(acc[mi][ni][0]), "+f"(acc[mi][ni][1]),
                              "+f"(acc[mi][ni][2]), "+f"(acc[mi][ni][3])
                            : "r"(af[sa][mi][0]), "r"(af[sa][mi][1]),
                              "r"(af[sa][mi][2]), "r"(af[sa][mi][3]),
                              "r"(bf[sb][ni][0]), "r"(bf[sb][ni][1]));
            }
        }
        __syncthreads();
    }
    #pragma unroll
    for (int mi = 0; mi < 4; mi++) {
        int r0 = i0 + wm + mi * 16 + g;
        #pragma unroll
        for (int ni = 0; ni < 4; ni++) {
            int c = j0 + wn + ni * 8 + tg * 2;
            float b0v = bias[c], b1v = bias[c + 1];
            Co[(size_t)r0 * CC + c]       = acc[mi][ni][0] + b0v;
            Co[(size_t)r0 * CC + c + 1]   = acc[mi][ni][1] + b1v;
            Co[(size_t)(r0+8) * CC + c]   = acc[mi][ni][2] + b0v;
            Co[(size_t)(r0+8) * CC + c+1] = acc[mi][ni][3] + b1v;
        }
    }
}

__global__ void k_l2norm(float* p) {
    __shared__ float sh[256];
    float* row = p + (size_t)blockIdx.x * CC;
    float s = 0.0f;
    for (int i = threadIdx.x; i < CC; i += 256) { float v = row[i]; s += v*v; }
    sh[threadIdx.x] = s; __syncthreads();
    for (int o = 128; o; o >>= 1) { if (threadIdx.x < o) sh[threadIdx.x] += sh[threadIdx.x + o]; __syncthreads(); }
    float inv = 1.0f / fmaxf(sqrtf(sh[0]), 1e-12f);
    for (int i = threadIdx.x; i < CC; i += 256) row[i] *= inv;
}

// sim[b][m][n] = k[b][m].q[n][b]; E = mask_m ? exp((sim-1)/eps) : 0
__global__ __launch_bounds__(256) void k_simE() {
    __shared__ float As[2][8][128];
    __shared__ float Bs[2][8][128];
    const int bb = blockIdx.z, m0 = blockIdx.x * 128, n0 = blockIdx.y * 128;
    const int tid = threadIdx.x, tx = tid & 15, ty = tid >> 4;
    const int li = tid >> 1, lk = (tid & 1) * 4;
    float acc[8][8];
    #pragma unroll
    for (int i = 0; i < 8; i++)
        #pragma unroll
        for (int j = 0; j < 8; j++) acc[i][j] = 0.0f;
    const float* Ap = g_k + (size_t)bb*MM*CC + (size_t)(m0 + li)*CC + lk;
    const float* Bp = g_q + (size_t)bb*CC    + (size_t)(n0 + li)*(NB*CC) + lk;
    {
        float4 va = *(const float4*)(Ap);
        float4 vb = *(const float4*)(Bp);
        As[0][lk+0][li]=va.x; As[0][lk+1][li]=va.y; As[0][lk+2][li]=va.z; As[0][lk+3][li]=va.w;
        Bs[0][lk+0][li]=vb.x; Bs[0][lk+1][li]=vb.y; Bs[0][lk+2][li]=vb.z; Bs[0][lk+3][li]=vb.w;
    }
    __syncthreads();
    int buf = 0;
    for (int k0 = 8; k0 < CC; k0 += 8) {
        float4 na = *(const float4*)(Ap + k0);
        float4 nb = *(const float4*)(Bp + k0);
        #pragma unroll
        for (int kk = 0; kk < 8; kk++) {
            float ar[8], br[8];
            *(float4*)(ar)   = *(const float4*)&As[buf][kk][ty*8];
            *(float4*)(ar+4) = *(const float4*)&As[buf][kk][ty*8+4];
            *(float4*)(br)   = *(const float4*)&Bs[buf][kk][tx*8];
            *(float4*)(br+4) = *(const float4*)&Bs[buf][kk][tx*8+4];
            #pragma unroll
            for (int i = 0; i < 8; i++)
                #pragma unroll
                for (int j = 0; j < 8; j++) acc[i][j] += ar[i]*br[j];
        }
        int nbuf = buf ^ 1;
        As[nbuf][lk+0][li]=na.x; As[nbuf][lk+1][li]=na.y; As[nbuf][lk+2][li]=na.z; As[nbuf][lk+3][li]=na.w;
        Bs[nbuf][lk+0][li]=nb.x; Bs[nbuf][lk+1][li]=nb.y; Bs[nbuf][lk+2][li]=nb.z; Bs[nbuf][lk+3][li]=nb.w;
        __syncthreads();
        buf = nbuf;
    }
    #pragma unroll
    for (int kk = 0; kk < 8; kk++) {
        float ar[8], br[8];
        *(float4*)(ar)   = *(const float4*)&As[buf][kk][ty*8];
        *(float4*)(ar+4) = *(const float4*)&As[buf][kk][ty*8+4];
        *(float4*)(br)   = *(const float4*)&Bs[buf][kk][tx*8];
        *(float4*)(br+4) = *(const float4*)&Bs[buf][kk][tx*8+4];
        #pragma unroll
        for (int i = 0; i < 8; i++)
            #pragma unroll
            for (int j = 0; j < 8; j++) acc[i][j] += ar[i]*br[j];
    }
    #pragma unroll
    for (int i = 0; i < 8; i++) {
        int m = m0 + ty*8 + i;
        int mk = g_maskb[bb*MM + m];
        size_t base = ((size_t)bb*MM + m) * NQ + n0 + tx*8;
        #pragma unroll
        for (int j = 0; j < 8; j++) {
            float s = acc[i][j];
            g_sim[base + j] = s;
            g_E[base + j] = mk ? expf((s - 1.0f) * EPS_INV) : 0.0f;
        }
    }
}

// persistent Sinkhorn: 128 co-resident blocks, software grid barrier
__global__ __launch_bounds__(256) void k_sink_pers() {
    __shared__ float sh[8*1024];
    const int blk = blockIdx.x, bb = blk >> 4, rb = blk & 15;
    const int tid = threadIdx.x, warp = tid >> 5, lane = tid & 31;
    const float* Eb = g_E + (size_t)bb*MM*NQ;
    const int m0 = rb*64 + warp*8;
    const int col = tid * 4;
    float bv[32];
    #pragma unroll
    for (int q = 0; q < 32; q++) bv[q] = 1.0f;
    for (int it = 1; it <= NITER; it++) {
        float cacc[32];
        #pragma unroll
        for (int q = 0; q < 32; q++) cacc[q] = 0.0f;
        #pragma unroll
        for (int rr = 0; rr < 8; rr++) {
            int m = m0 + rr;
            if (!g_maskb[bb*MM + m]) {
                if (it == NITER && lane == 0) g_a[bb*MM + m] = 0.0f;
                continue;
            }
            const float4* er = (const float4*)(Eb + (size_t)m * NQ);
            float e[32], s = 0.0f;
            #pragma unroll
            for (int g = 0; g < 8; g++) {
                float4 v = __ldg(&er[g*32 + lane]);
                e[g*4+0]=v.x; e[g*4+1]=v.y; e[g*4+2]=v.z; e[g*4+3]=v.w;
                s += v.x*bv[g*4+0] + v.y*bv[g*4+1] + v.z*bv[g*4+2] + v.w*bv[g*4+3];
            }
            #pragma unroll
            for (int o = 16; o; o >>= 1) s += __shfl_xor_sync(0xffffffffu, s, o);
            float a = g_mu[bb*MM + m] / s;
            if (it == NITER && lane == 0) g_a[bb*MM + m] = a;
            #pragma unroll
            for (int q = 0; q < 32; q++) cacc[q] += a * e[q];
        }
        #pragma unroll
        for (int g = 0; g < 8; g++)
            *(float4*)&sh[warp*1024 + g*128 + lane*4] =
                make_float4(cacc[g*4], cacc[g*4+1], cacc[g*4+2], cacc[g*4+3]);
        __syncthreads();
        float s0=0, s1=0, s2=0, s3=0;
        #pragma unroll
        for (int w = 0; w < 8; w++) {
            float4 v = *(const float4*)&sh[w*1024 + col];
            s0 += v.x; s1 += v.y; s2 += v.z; s3 += v.w;
        }
        *(float4*)&g_cpart[(size_t)blk*NQ + col] = make_float4(s0, s1, s2, s3);
        __threadfence();
        __syncthreads();
        if (tid == 0) {
            atomicAdd(&g_bar, 1u);
            unsigned int target = (unsigned int)it * 128u;
            while (atomicAdd(&g_bar, 0u) < target) __nanosleep(64);
        }
        __syncthreads();
        __threadfence();
        if (it < NITER) {
            float c0=0, c1=0, c2=0, c3=0;
            #pragma unroll
            for (int w = 0; w < 16; w++) {
                float4 v = *(const float4*)&g_cpart[(size_t)(bb*16 + w)*NQ + col];
                c0 += v.x; c1 += v.y; c2 += v.z; c3 += v.w;
            }
            sh[col+0] = NU_P / c0; sh[col+1] = NU_P / c1;
            sh[col+2] = NU_P / c2; sh[col+3] = NU_P / c3;
            __syncthreads();
            #pragma unroll
            for (int g = 0; g < 8; g++) {
                float4 v = *(const float4*)&sh[g*128 + lane*4];
                bv[g*4+0]=v.x; bv[g*4+1]=v.y; bv[g*4+2]=v.z; bv[g*4+3]=v.w;
            }
            __syncthreads();
        }
    }
    if (rb == 0) {
        float c0=0, c1=0, c2=0, c3=0;
        #pragma unroll
        for (int w = 0; w < 16; w++) {
            float4 v = *(const float4*)&g_cpart[(size_t)(bb*16 + w)*NQ + col];
            c0 += v.x; c1 += v.y; c2 += v.z; c3 += v.w;
        }
        g_bfin[bb*NQ+col+0] = NU_P / c0; g_bfin[bb*NQ+col+1] = NU_P / c1;
        g_bfin[bb*NQ+col+2] = NU_P / c2; g_bfin[bb*NQ+col+3] = NU_P / c3;
    }
}

// x[n][b][c] = bfin_n * sum_m E[b][m][n] * (a_m * v[b][m][c])
__global__ __launch_bounds__(256) void k_xgemm() {
    __shared__ float As[2][8][128];
    __shared__ float Bs[2][8][128];
    const int bb = blockIdx.z, n0 = blockIdx.x * 128, c0 = blockIdx.y * 128;
    const int tid = threadIdx.x, tx = tid & 15, ty = tid >> 4;
    const int lr = tid >> 5, lc = (tid & 31) * 4;
    float acc[8][8];
    #pragma unroll
    for (int i = 0; i < 8; i++)
        #pragma unroll
        for (int j = 0; j < 8; j++) acc[i][j] = 0.0f;
    const float* Eb = g_E + (size_t)bb*MM*NQ;
    const float* Vb = g_v + (size_t)bb*MM*CC;
    {
        float4 ea = *(const float4*)(Eb + (size_t)lr*NQ + n0 + lc);
        float am = g_a[bb*MM + lr];
        float4 vb = *(const float4*)(Vb + (size_t)lr*CC + c0 + lc);
        *(float4*)&As[0][lr][lc] = ea;
        Bs[0][lr][lc+0]=vb.x*am; Bs[0][lr][lc+1]=vb.y*am; Bs[0][lr][lc+2]=vb.z*am; Bs[0][lr][lc+3]=vb.w*am;
    }
    __syncthreads();
    int buf = 0;
    for (int k0 = 8; k0 < MM; k0 += 8) {
        float4 ea = *(const float4*)(Eb + (size_t)(k0 + lr)*NQ + n0 + lc);
        float am = g_a[bb*MM + k0 + lr];
        float4 vb = *(const float4*)(Vb + (size_t)(k0 + lr)*CC + c0 + lc);
        #pragma unroll
        for (int kk = 0; kk < 8; kk++) {
            float ar[8], br[8];
            *(float4*)(ar)   = *(const float4*)&As[buf][kk][ty*8];
            *(float4*)(ar+4) = *(const float4*)&As[buf][kk][ty*8+4];
            *(float4*)(br)   = *(const float4*)&Bs[buf][kk][tx*8];
            *(float4*)(br+4) = *(const float4*)&Bs[buf][kk][tx*8+4];
            #pragma unroll
            for (int i = 0; i < 8; i++)
                #pragma unroll
                for (int j = 0; j < 8; j++) acc[i][j] += ar[i]*br[j];
        }
        int nbuf = buf ^ 1;
        *(float4*)&As[nbuf][lr][lc] = ea;
        Bs[nbuf][lr][lc+0]=vb.x*am; Bs[nbuf][lr][lc+1]=vb.y*am; Bs[nbuf][lr][lc+2]=vb.z*am; Bs[nbuf][lr][lc+3]=vb.w*am;
        __syncthreads();
        buf = nbuf;
    }
    #pragma unroll
    for (int kk = 0; kk < 8; kk++) {
        float ar[8], br[8];
        *(float4*)(ar)   = *(const float4*)&As[buf][kk][ty*8];
        *(float4*)(ar+4) = *(const float4*)&As[buf][kk][ty*8+4];
        *(float4*)(br)   = *(const float4*)&Bs[buf][kk][tx*8];
        *(float4*)(br+4) = *(const float4*)&Bs[buf][kk][tx*8+4];
        #pragma unroll
        for (int i = 0; i < 8; i++)
            #pragma unroll
            for (int j = 0; j < 8; j++) acc[i][j] += ar[i]*br[j];
    }
    #pragma unroll
    for (int i = 0; i < 8; i++) {
        int n = n0 + ty*8 + i;
        float bn = g_bfin[bb*NQ + n];
        #pragma unroll
        for (int j = 0; j < 8; j++)
            g_x[((size_t)n*NB + bb)*CC + c0 + tx*8 + j] = acc[i][j] * bn;
    }
}

__global__ void k_attn(float* outp) {
    const int warp = threadIdx.x >> 5, lane = threadIdx.x & 31;
    int r = blockIdx.x * 8 + warp;
    if (r >= RR) return;
    int bb = r >> 10;
    float val = 0.0f;
    if (g_maskb[r]) {
        const float* S = g_sim + (size_t)r * NQ;
        const float* E = g_E + (size_t)r * NQ;
        const float* bf = g_bfin + bb * NQ;
        float s = 0.0f;
        #pragma unroll
        for (int g = 0; g < 8; g++) {
            int n = g*128 + lane*4;
            float4 sv = *(const float4*)(S + n);
            float4 ev = *(const float4*)(E + n);
            float4 bv = *(const float4*)(bf + n);
            s += sv.x*ev.x*bv.x + sv.y*ev.y*bv.y + sv.z*ev.z*bv.z + sv.w*ev.w*bv.w;
        }
        #pragma unroll
        for (int o = 16; o; o >>= 1) s += __shfl_xor_sync(0xffffffffu, s, o);
        val = 1048576.0f * g_a[r] * s;
    }
    if (lane == 0) outp[r] = val;
}

extern "C" void kernel_launch(void* const* d_in, const int* in_sizes, int n_in,
                              void* d_out, int out_size) {
    const float* xq = (const float*)d_in[0];
    const float* xk = (const float*)d_in[1];
    const float* xv = (const float*)d_in[2];
    const void*  mk = d_in[3];
    const float* Wq = (const float*)d_in[4];
    const float* bq = (const float*)d_in[5];
    const float* Wk = (const float*)d_in[6];
    const float* bk = (const float*)d_in[7];
    const float* Wv = (const float*)d_in[8];
    const float* bv = (const float*)d_in[9];
    const float* Wp = (const float*)d_in[10];
    const float* bp = (const float*)d_in[11];
    float *qp, *kp, *vp, *xp;
    __nv_bfloat16 *a0, *a1, *b0, *b1;
    cudaGetSymbolAddress((void**)&qp, g_q);
    cudaGetSymbolAddress((void**)&kp, g_k);
    cudaGetSymbolAddress((void**)&vp, g_v);
    cudaGetSymbolAddress((void**)&xp, g_x);
    cudaGetSymbolAddress((void**)&a0, g_as0);
    cudaGetSymbolAddress((void**)&a1, g_as1);
    cudaGetSymbolAddress((void**)&b0, g_bs0);
    cudaGetSymbolAddress((void**)&b1, g_bs1);

    k_detect<<<1, 256>>>((const unsigned char*)mk);
    k_counts<<<NB, 256>>>(mk);
    k_init<<<(RR + 255)/256, 256>>>(mk);

    const int nA = RR*CC, nW = CC*CC;
    dim3 gmm(RR/128, CC/128);

    k_split2<<<(nA+255)/256, 256>>>(xq, a0, a1, nA);
    k_split2<<<(nW+255)/256, 256>>>(Wq, b0, b1, nW);
    k_gemm_mma<<<gmm, 256>>>(a0, a1, b0, b1, bq, qp);

    k_split2<<<(nA+255)/256, 256>>>(xk, a0, a1, nA);
    k_split2<<<(nW+255)/256, 256>>>(Wk, b0, b1, nW);
    k_gemm_mma<<<gmm, 256>>>(a0, a1, b0, b1, bk, kp);

    k_split2<<<(nA+255)/256, 256>>>(xv, a0, a1, nA);
    k_split2<<<(nW+255)/256, 256>>>(Wv, b0, b1, nW);
    k_gemm_mma<<<gmm, 256>>>(a0, a1, b0, b1, bv, vp);

    k_l2norm<<<RR, 256>>>(qp);
    k_l2norm<<<RR, 256>>>(kp);

    k_simE<<<dim3(MM/128, NQ/128, NB), 256>>>();

    k_sink_pers<<<128, 256>>>();

    k_xgemm<<<dim3(NQ/128, CC/128, NB), 256>>>();

    k_split2<<<(nA+255)/256, 256>>>(xp, a0, a1, nA);
    k_split2<<<(nW+255)/256, 256>>>(Wp, b0, b1, nW);
    k_gemm_mma<<<gmm, 256>>>(a0, a1, b0, b1, bp, (float*)d_out);

    if (out_size >= RR*CC + RR)
        k_attn<<<RR/8, 256>>>((float*)d_out + (size_t)RR*CC);
}

// round 8
// speedup vs baseline: 1.5817x; 1.1127x over previous
#include <cuda_runtime.h>
#include <cuda_bf16.h>
#include <math.h>
#include <stdint.h>

#define NQ 1024
#define NB 8
#define MM 1024
#define CC 640
#define RR 8192
#define NITER 100
#define EPS_INV 20.0f
#define NU_P (1.0f/1024.0f + 1e-8f)

__device__ float g_q[RR*CC];
__device__ float g_k[RR*CC];
__device__ float g_v[RR*CC];
__device__ float g_x[RR*CC];
__device__ float g_sim[NB*MM*NQ];
__device__ float g_E[NB*MM*NQ];
__device__ float g_cpart[128*NQ];
__device__ float g_a[RR];
__device__ float g_mu[RR];
__device__ float g_bfin[RR];
__device__ unsigned char g_maskb[RR];
__device__ int g_counts[NB];
__device__ int g_mfmt;
__device__ unsigned int g_bar;
// bf16 2-way splits
__device__ __nv_bfloat16 g_as0[RR*CC];
__device__ __nv_bfloat16 g_as1[RR*CC];
__device__ __nv_bfloat16 g_bs0[CC*CC];
__device__ __nv_bfloat16 g_bs1[CC*CC];
__device__ __nv_bfloat16 g_qs0[RR*CC];
__device__ __nv_bfloat16 g_qs1[RR*CC];
__device__ __nv_bfloat16 g_ks0[RR*CC];
__device__ __nv_bfloat16 g_ks1[RR*CC];

__device__ __forceinline__ int getmask_raw(const void* m, int idx, int fmt) {
    if (fmt == 1) return ((const int*)m)[idx] != 0;
    if (fmt == 2) return ((const float*)m)[idx] != 0.0f;
    return ((const unsigned char*)m)[idx] != 0;
}

__global__ void k_detect(const unsigned char* m) {
    __shared__ int cA, cB;
    if (threadIdx.x == 0) { cA = 0; cB = 0; }
    __syncthreads();
    int a = 0, b = 0;
    for (int i = threadIdx.x; i < RR; i += blockDim.x) {
        if (m[i] != 0) { if ((i & 3) == 0) a = 1; else b = 1; }
    }
    if (a) atomicOr(&cA, 1);
    if (b) atomicOr(&cB, 1);
    __syncthreads();
    if (threadIdx.x == 0) g_mfmt = (cB == 0) ? 1 : ((cA == 0) ? 2 : 0);
}

__global__ void k_counts(const void* mask) {
    __shared__ int sh[256];
    int fmt = g_mfmt, bb = blockIdx.x, s = 0;
    for (int m = threadIdx.x; m < MM; m += 256) s += getmask_raw(mask, bb*MM + m, fmt);
    sh[threadIdx.x] = s; __syncthreads();
    for (int o = 128; o; o >>= 1) { if (threadIdx.x < o) sh[threadIdx.x] += sh[threadIdx.x + o]; __syncthreads(); }
    if (threadIdx.x == 0) g_counts[bb] = (sh[0] > 0) ? sh[0] : 1;
}

__global__ void k_init(const void* mask) {
    int idx = blockIdx.x * blockDim.x + threadIdx.x;
    if (idx == 0) g_bar = 0u;
    if (idx < RR) {
        int fmt = g_mfmt;
        int mk = getmask_raw(mask, idx, fmt);
        g_maskb[idx] = (unsigned char)mk;
        g_mu[idx] = mk ? (1.0f/(float)g_counts[idx >> 10] + 1e-8f) : 0.0f;
    }
}

__global__ void k_split2(const float* __restrict__ src,
                         __nv_bfloat16* __restrict__ d0,
                         __nv_bfloat16* __restrict__ d1, int n) {
    int i = blockIdx.x * blockDim.x + threadIdx.x;
    if (i >= n) return;
    float x = src[i];
    __nv_bfloat16 b0 = __float2bfloat16(x);
    float r = x - __bfloat162float(b0);
    d0[i] = b0; d1[i] = __float2bfloat16(r);
}

// fused l2-normalize + bf16x2 split (one row per block)
__global__ void k_l2split(const float* __restrict__ src,
                          __nv_bfloat16* __restrict__ d0,
                          __nv_bfloat16* __restrict__ d1) {
    __shared__ float sh[256];
    const float* row = src + (size_t)blockIdx.x * CC;
    float s = 0.0f;
    for (int i = threadIdx.x; i < CC; i += 256) { float v = row[i]; s += v*v; }
    sh[threadIdx.x] = s; __syncthreads();
    for (int o = 128; o; o >>= 1) { if (threadIdx.x < o) sh[threadIdx.x] += sh[threadIdx.x + o]; __syncthreads(); }
    float inv = 1.0f / fmaxf(sqrtf(sh[0]), 1e-12f);
    size_t base = (size_t)blockIdx.x * CC;
    for (int i = threadIdx.x; i < CC; i += 256) {
        float x = row[i] * inv;
        __nv_bfloat16 b0 = __float2bfloat16(x);
        float r = x - __bfloat162float(b0);
        d0[base + i] = b0; d1[base + i] = __float2bfloat16(r);
    }
}

// ---------- mma.sync bf16x2 NT GEMM: C[r][j] = sum_t A[r][t]*B[j][t] + bias[j] ----------
#define SPAD 40
__global__ __launch_bounds__(256) void k_gemm_mma(
    const __nv_bfloat16* __restrict__ A0, const __nv_bfloat16* __restrict__ A1,
    const __nv_bfloat16* __restrict__ B0, const __nv_bfloat16* __restrict__ B1,
    const float* __restrict__ bias, float* __restrict__ Co) {
    __shared__ __nv_bfloat16 As[2][128][SPAD];
    __shared__ __nv_bfloat16 Bs[2][128][SPAD];
    const int tid = threadIdx.x, warp = tid >> 5, lane = tid & 31;
    const int g = lane >> 2, tg = lane & 3;
    const int i0 = blockIdx.x * 128, j0 = blockIdx.y * 128;
    const int wm = (warp & 1) * 64, wn = (warp >> 1) * 32;
    float acc[4][4][4];
    #pragma unroll
    for (int mi = 0; mi < 4; mi++)
        #pragma unroll
        for (int ni = 0; ni < 4; ni++)
            #pragma unroll
            for (int e = 0; e < 4; e++) acc[mi][ni][e] = 0.0f;
    const int lrow = tid >> 1, lseg = (tid & 1) * 2;
    for (int k0 = 0; k0 < CC; k0 += 32) {
        #pragma unroll
        for (int u = 0; u < 2; u++) {
            int seg = lseg + u;
            *(uint4*)&As[0][lrow][seg*8] = *(const uint4*)(A0 + (size_t)(i0+lrow)*CC + k0 + seg*8);
            *(uint4*)&As[1][lrow][seg*8] = *(const uint4*)(A1 + (size_t)(i0+lrow)*CC + k0 + seg*8);
            *(uint4*)&Bs[0][lrow][seg*8] = *(const uint4*)(B0 + (size_t)(j0+lrow)*CC + k0 + seg*8);
            *(uint4*)&Bs[1][lrow][seg*8] = *(const uint4*)(B1 + (size_t)(j0+lrow)*CC + k0 + seg*8);
        }
        __syncthreads();
        #pragma unroll
        for (int kk = 0; kk < 32; kk += 16) {
            uint32_t af[2][4][4], bf[2][4][2];
            #pragma unroll
            for (int s = 0; s < 2; s++) {
                #pragma unroll
                for (int mi = 0; mi < 4; mi++) {
                    int r0 = wm + mi*16 + g;
                    af[s][mi][0] = *(const uint32_t*)&As[s][r0][kk + tg*2];
                    af[s][mi][1] = *(const uint32_t*)&As[s][r0+8][kk + tg*2];
                    af[s][mi][2] = *(const uint32_t*)&As[s][r0][kk + tg*2 + 8];
                    af[s][mi][3] = *(const uint32_t*)&As[s][r0+8][kk + tg*2 + 8];
                }
                #pragma unroll
                for (int ni = 0; ni < 4; ni++) {
                    int c0 = wn + ni*8 + g;
                    bf[s][ni][0] = *(const uint32_t*)&Bs[s][c0][kk + tg*2];
                    bf[s][ni][1] = *(const uint32_t*)&Bs[s][c0][kk + tg*2 + 8];
                }
            }
            #pragma unroll
            for (int p = 0; p < 3; p++) {
                const int sa = (p == 2) ? 1 : 0, sb = (p == 1) ? 1 : 0;
                #pragma unroll
                for (int mi = 0; mi < 4; mi++)
                    #pragma unroll
                    for (int ni = 0; ni < 4; ni++)
                        asm volatile(
                            "mma.sync.aligned.m16n8k16.row.col.f32.bf16.bf16.f32 "
                            "{%0,%1,%2,%3}, {%4,%5,%6,%7}, {%8,%9}, {%0,%1,%2,%3};"
                            : "+f"(acc[mi][ni][0]), "+f"(acc[mi][ni][1]),
                              "+f"(acc[mi][ni][2]), "+f"(acc[mi][ni][3])
                            : "r"(af[sa][mi][0]), "r"(af[sa][mi][1]),
                              "r"(af[sa][mi][2]), "r"(af[sa][mi][3]),
                              "r"(bf[sb][ni][0]), "r"(bf[sb][ni][1]));
            }
        }
        __syncthreads();
    }
    #pragma unroll
    for (int mi = 0; mi < 4; mi++) {
        int r0 = i0 + wm + mi*16 + g;
        #pragma unroll
        for (int ni = 0; ni < 4; ni++) {
            int c = j0 + wn + ni*8 + tg*2;
            float b0v = bias[c], b1v = bias[c+1];
            Co[(size_t)r0*CC + c]       = acc[mi][ni][0] + b0v;
            Co[(size_t)r0*CC + c+1]     = acc[mi][ni][1] + b1v;
            Co[(size_t)(r0+8)*CC + c]   = acc[mi][ni][2] + b0v;
            Co[(size_t)(r0+8)*CC + c+1] = acc[mi][ni][3] + b1v;
        }
    }
}

// ---------- HMMA simE: sim[b][m][n] = k[b][m].q[n][b]; E = mask_m ? exp((sim-1)*20) : 0 ----------
__global__ __launch_bounds__(256) void k_simE_mma() {
    __shared__ __nv_bfloat16 As[2][128][SPAD];
    __shared__ __nv_bfloat16 Bs[2][128][SPAD];
    const int tid = threadIdx.x, warp = tid >> 5, lane = tid & 31;
    const int g = lane >> 2, tg = lane & 3;
    const int bb = blockIdx.z, m0 = blockIdx.x * 128, n0 = blockIdx.y * 128;
    const int wm = (warp & 1) * 64, wn = (warp >> 1) * 32;
    float acc[4][4][4];
    #pragma unroll
    for (int mi = 0; mi < 4; mi++)
        #pragma unroll
        for (int ni = 0; ni < 4; ni++)
            #pragma unroll
            for (int e = 0; e < 4; e++) acc[mi][ni][e] = 0.0f;
    const int lrow = tid >> 1, lseg = (tid & 1) * 2;
    const size_t abase = (size_t)(bb*MM + m0);
    for (int k0 = 0; k0 < CC; k0 += 32) {
        #pragma unroll
        for (int u = 0; u < 2; u++) {
            int seg = lseg + u;
            *(uint4*)&As[0][lrow][seg*8] = *(const uint4*)(g_ks0 + (abase + lrow)*CC + k0 + seg*8);
            *(uint4*)&As[1][lrow][seg*8] = *(const uint4*)(g_ks1 + (abase + lrow)*CC + k0 + seg*8);
            size_t qrow = (size_t)(n0 + lrow)*NB + bb;
            *(uint4*)&Bs[0][lrow][seg*8] = *(const uint4*)(g_qs0 + qrow*CC + k0 + seg*8);
            *(uint4*)&Bs[1][lrow][seg*8] = *(const uint4*)(g_qs1 + qrow*CC + k0 + seg*8);
        }
        __syncthreads();
        #pragma unroll
        for (int kk = 0; kk < 32; kk += 16) {
            uint32_t af[2][4][4], bf[2][4][2];
            #pragma unroll
            for (int s = 0; s < 2; s++) {
                #pragma unroll
                for (int mi = 0; mi < 4; mi++) {
                    int r0 = wm + mi*16 + g;
                    af[s][mi][0] = *(const uint32_t*)&As[s][r0][kk + tg*2];
                    af[s][mi][1] = *(const uint32_t*)&As[s][r0+8][kk + tg*2];
                    af[s][mi][2] = *(const uint32_t*)&As[s][r0][kk + tg*2 + 8];
                    af[s][mi][3] = *(const uint32_t*)&As[s][r0+8][kk + tg*2 + 8];
                }
                #pragma unroll
                for (int ni = 0; ni < 4; ni++) {
                    int c0 = wn + ni*8 + g;
                    bf[s][ni][0] = *(const uint32_t*)&Bs[s][c0][kk + tg*2];
                    bf[s][ni][1] = *(const uint32_t*)&Bs[s][c0][kk + tg*2 + 8];
                }
            }
            #pragma unroll
            for (int p = 0; p < 3; p++) {
                const int sa = (p == 2) ? 1 : 0, sb = (p == 1) ? 1 : 0;
                #pragma unroll
                for (int mi = 0; mi < 4; mi++)
                    #pragma unroll
                    for (int ni = 0; ni < 4; ni++)
                        asm volatile(
                            "mma.sync.aligned.m16n8k16.row.col.f32.bf16.bf16.f32 "
                            "{%0,%1,%2,%3}, {%4,%5,%6,%7}, {%8,%9}, {%0,%1,%2,%3};"
                            : "+f"(acc[mi][ni][0]), "+f"(acc[mi][ni][1]),
                              "+f"(acc[mi][ni][2]), "+f"(acc[mi][ni][3])
                            : "r"(af[sa][mi][0]), "r"(af[sa][mi][1]),
                              "r"(af[sa][mi][2]), "r"(af[sa][mi][3]),
                              "r"(bf[sb][ni][0]), "r"(bf[sb][ni][1]));
            }
        }
        __syncthreads();
    }
    #pragma unroll
    for (int mi = 0; mi < 4; mi++) {
        int mA = m0 + wm + mi*16 + g;
        int mB = mA + 8;
        int mkA = g_maskb[bb*MM + mA], mkB = g_maskb[bb*MM + mB];
        size_t baseA = ((size_t)bb*MM + mA) * NQ;
        size_t baseB = ((size_t)bb*MM + mB) * NQ;
        #pragma unroll
        for (int ni = 0; ni < 4; ni++) {
            int c = n0 + wn + ni*8 + tg*2;
            float s0 = acc[mi][ni][0], s1 = acc[mi][ni][1];
            float s2 = acc[mi][ni][2], s3 = acc[mi][ni][3];
            g_sim[baseA + c]   = s0; g_sim[baseA + c+1] = s1;
            g_sim[baseB + c]   = s2; g_sim[baseB + c+1] = s3;
            g_E[baseA + c]   = mkA ? expf((s0 - 1.0f) * EPS_INV) : 0.0f;
            g_E[baseA + c+1] = mkA ? expf((s1 - 1.0f) * EPS_INV) : 0.0f;
            g_E[baseB + c]   = mkB ? expf((s2 - 1.0f) * EPS_INV) : 0.0f;
            g_E[baseB + c+1] = mkB ? expf((s3 - 1.0f) * EPS_INV) : 0.0f;
        }
    }
}

// persistent Sinkhorn: 128 co-resident blocks, software grid barrier
__global__ __launch_bounds__(256) void k_sink_pers() {
    __shared__ float sh[8*1024];
    const int blk = blockIdx.x, bb = blk >> 4, rb = blk & 15;
    const int tid = threadIdx.x, warp = tid >> 5, lane = tid & 31;
    const float* Eb = g_E + (size_t)bb*MM*NQ;
    const int m0 = rb*64 + warp*8;
    const int col = tid * 4;
    float bv[32];
    #pragma unroll
    for (int q = 0; q < 32; q++) bv[q] = 1.0f;
    for (int it = 1; it <= NITER; it++) {
        float cacc[32];
        #pragma unroll
        for (int q = 0; q < 32; q++) cacc[q] = 0.0f;
        #pragma unroll
        for (int rr = 0; rr < 8; rr++) {
            int m = m0 + rr;
            if (!g_maskb[bb*MM + m]) {
                if (it == NITER && lane == 0) g_a[bb*MM + m] = 0.0f;
                continue;
            }
            const float4* er = (const float4*)(Eb + (size_t)m * NQ);
            float e[32], s = 0.0f;
            #pragma unroll
            for (int g = 0; g < 8; g++) {
                float4 v = __ldg(&er[g*32 + lane]);
                e[g*4+0]=v.x; e[g*4+1]=v.y; e[g*4+2]=v.z; e[g*4+3]=v.w;
                s += v.x*bv[g*4+0] + v.y*bv[g*4+1] + v.z*bv[g*4+2] + v.w*bv[g*4+3];
            }
            #pragma unroll
            for (int o = 16; o; o >>= 1) s += __shfl_xor_sync(0xffffffffu, s, o);
            float a = g_mu[bb*MM + m] / s;
            if (it == NITER && lane == 0) g_a[bb*MM + m] = a;
            #pragma unroll
            for (int q = 0; q < 32; q++) cacc[q] += a * e[q];
        }
        #pragma unroll
        for (int g = 0; g < 8; g++)
            *(float4*)&sh[warp*1024 + g*128 + lane*4] =
                make_float4(cacc[g*4], cacc[g*4+1], cacc[g*4+2], cacc[g*4+3]);
        __syncthreads();
        float s0=0, s1=0, s2=0, s3=0;
        #pragma unroll
        for (int w = 0; w < 8; w++) {
            float4 v = *(const float4*)&sh[w*1024 + col];
            s0 += v.x; s1 += v.y; s2 += v.z; s3 += v.w;
        }
        *(float4*)&g_cpart[(size_t)blk*NQ + col] = make_float4(s0, s1, s2, s3);
        __threadfence();
        __syncthreads();
        if (tid == 0) {
            atomicAdd(&g_bar, 1u);
            unsigned int target = (unsigned int)it * 128u;
            while (atomicAdd(&g_bar, 0u) < target) __nanosleep(64);
        }
        __syncthreads();
        __threadfence();
        if (it < NITER) {
            float c0=0, c1=0, c2=0, c3=0;
            #pragma unroll
            for (int w = 0; w < 16; w++) {
                float4 v = *(const float4*)&g_cpart[(size_t)(bb*16 + w)*NQ + col];
                c0 += v.x; c1 += v.y; c2 += v.z; c3 += v.w;
            }
            sh[col+0] = NU_P / c0; sh[col+1] = NU_P / c1;
            sh[col+2] = NU_P / c2; sh[col+3] = NU_P / c3;
            __syncthreads();
            #pragma unroll
            for (int g = 0; g < 8; g++) {
                float4 v = *(const float4*)&sh[g*128 + lane*4];
                bv[g*4+0]=v.x; bv[g*4+1]=v.y; bv[g*4+2]=v.z; bv[g*4+3]=v.w;
            }
            __syncthreads();
        }
    }
    if (rb == 0) {
        float c0=0, c1=0, c2=0, c3=0;
        #pragma unroll
        for (int w = 0; w < 16; w++) {
            float4 v = *(const float4*)&g_cpart[(size_t)(bb*16 + w)*NQ + col];
            c0 += v.x; c1 += v.y; c2 += v.z; c3 += v.w;
        }
        g_bfin[bb*NQ+col+0] = NU_P / c0; g_bfin[bb*NQ+col+1] = NU_P / c1;
        g_bfin[bb*NQ+col+2] = NU_P / c2; g_bfin[bb*NQ+col+3] = NU_P / c3;
    }
}

// x[n][b][c] = bfin_n * sum_m E[b][m][n] * (a_m * v[b][m][c])
__global__ __launch_bounds__(256) void k_xgemm() {
    __shared__ float As[2][8][128];
    __shared__ float Bs[2][8][128];
    const int bb = blockIdx.z, n0 = blockIdx.x * 128, c0 = blockIdx.y * 128;
    const int tid = threadIdx.x, tx = tid & 15, ty = tid >> 4;
    const int lr = tid >> 5, lc = (tid & 31) * 4;
    float acc[8][8];
    #pragma unroll
    for (int i = 0; i < 8; i++)
        #pragma unroll
        for (int j = 0; j < 8; j++) acc[i][j] = 0.0f;
    const float* Eb = g_E + (size_t)bb*MM*NQ;
    const float* Vb = g_v + (size_t)bb*MM*CC;
    {
        float4 ea = *(const float4*)(Eb + (size_t)lr*NQ + n0 + lc);
        float am = g_a[bb*MM + lr];
        float4 vb = *(const float4*)(Vb + (size_t)lr*CC + c0 + lc);
        *(float4*)&As[0][lr][lc] = ea;
        Bs[0][lr][lc+0]=vb.x*am; Bs[0][lr][lc+1]=vb.y*am; Bs[0][lr][lc+2]=vb.z*am; Bs[0][lr][lc+3]=vb.w*am;
    }
    __syncthreads();
    int buf = 0;
    for (int k0 = 8; k0 < MM; k0 += 8) {
        float4 ea = *(const float4*)(Eb + (size_t)(k0 + lr)*NQ + n0 + lc);
        float am = g_a[bb*MM + k0 + lr];
        float4 vb = *(const float4*)(Vb + (size_t)(k0 + lr)*CC + c0 + lc);
        #pragma unroll
        for (int kk = 0; kk < 8; kk++) {
            float ar[8], br[8];
            *(float4*)(ar)   = *(const float4*)&As[buf][kk][ty*8];
            *(float4*)(ar+4) = *(const float4*)&As[buf][kk][ty*8+4];
            *(float4*)(br)   = *(const float4*)&Bs[buf][kk][tx*8];
            *(float4*)(br+4) = *(const float4*)&Bs[buf][kk][tx*8+4];
            #pragma unroll
            for (int i = 0; i < 8; i++)
                #pragma unroll
                for (int j = 0; j < 8; j++) acc[i][j] += ar[i]*br[j];
        }
        int nbuf = buf ^ 1;
        *(float4*)&As[nbuf][lr][lc] = ea;
        Bs[nbuf][lr][lc+0]=vb.x*am; Bs[nbuf][lr][lc+1]=vb.y*am; Bs[nbuf][lr][lc+2]=vb.z*am; Bs[nbuf][lr][lc+3]=vb.w*am;
        __syncthreads();
        buf = nbuf;
    }
    #pragma unroll
    for (int kk = 0; kk < 8; kk++) {
        float ar[8], br[8];
        *(float4*)(ar)   = *(const float4*)&As[buf][kk][ty*8];
        *(float4*)(ar+4) = *(const float4*)&As[buf][kk][ty*8+4];
        *(float4*)(br)   = *(const float4*)&Bs[buf][kk][tx*8];
        *(float4*)(br+4) = *(const float4*)&Bs[buf][kk][tx*8+4];
        #pragma unroll
        for (int i = 0; i < 8; i++)
            #pragma unroll
            for (int j = 0; j < 8; j++) acc[i][j] += ar[i]*br[j];
    }
    #pragma unroll
    for (int i = 0; i < 8; i++) {
        int n = n0 + ty*8 + i;
        float bn = g_bfin[bb*NQ + n];
        #pragma unroll
        for (int j = 0; j < 8; j++)
            g_x[((size_t)n*NB + bb)*CC + c0 + tx*8 + j] = acc[i][j] * bn;
    }
}

__global__ void k_attn(float* outp) {
    const int warp = threadIdx.x >> 5, lane = threadIdx.x & 31;
    int r = blockIdx.x * 8 + warp;
    if (r >= RR) return;
    int bb = r >> 10;
    float val = 0.0f;
    if (g_maskb[r]) {
        const float* S = g_sim + (size_t)r * NQ;
        const float* E = g_E + (size_t)r * NQ;
        const float* bf = g_bfin + bb * NQ;
        float s = 0.0f;
        #pragma unroll
        for (int g = 0; g < 8; g++) {
            int n = g*128 + lane*4;
            float4 sv = *(const float4*)(S + n);
            float4 ev = *(const float4*)(E + n);
            float4 bv = *(const float4*)(bf + n);
            s += sv.x*ev.x*bv.x + sv.y*ev.y*bv.y + sv.z*ev.z*bv.z + sv.w*ev.w*bv.w;
        }
        #pragma unroll
        for (int o = 16; o; o >>= 1) s += __shfl_xor_sync(0xffffffffu, s, o);
        val = 1048576.0f * g_a[r] * s;
    }
    if (lane == 0) outp[r] = val;
}

extern "C" void kernel_launch(void* const* d_in, const int* in_sizes, int n_in,
                              void* d_out, int out_size) {
    const float* xq = (const float*)d_in[0];
    const float* xk = (const float*)d_in[1];
    const float* xv = (const float*)d_in[2];
    const void*  mk = d_in[3];
    const float* Wq = (const float*)d_in[4];
    const float* bq = (const float*)d_in[5];
    const float* Wk = (const float*)d_in[6];
    const float* bk = (const float*)d_in[7];
    const float* Wv = (const float*)d_in[8];
    const float* bv = (const float*)d_in[9];
    const float* Wp = (const float*)d_in[10];
    const float* bp = (const float*)d_in[11];
    float *qp, *kp, *vp, *xp;
    __nv_bfloat16 *a0, *a1, *b0, *b1, *q0, *q1, *ks0, *ks1;
    cudaGetSymbolAddress((void**)&qp, g_q);
    cudaGetSymbolAddress((void**)&kp, g_k);
    cudaGetSymbolAddress((void**)&vp, g_v);
    cudaGetSymbolAddress((void**)&xp, g_x);
    cudaGetSymbolAddress((void**)&a0, g_as0);
    cudaGetSymbolAddress((void**)&a1, g_as1);
    cudaGetSymbolAddress((void**)&b0, g_bs0);
    cudaGetSymbolAddress((void**)&b1, g_bs1);
    cudaGetSymbolAddress((void**)&q0, g_qs0);
    cudaGetSymbolAddress((void**)&q1, g_qs1);
    cudaGetSymbolAddress((void**)&ks0, g_ks0);
    cudaGetSymbolAddress((void**)&ks1, g_ks1);

    k_detect<<<1, 256>>>((const unsigned char*)mk);
    k_counts<<<NB, 256>>>(mk);
    k_init<<<(RR + 255)/256, 256>>>(mk);

    const int nA = RR*CC, nW = CC*CC;
    dim3 gmm(RR/128, CC/128);

    k_split2<<<(nA+255)/256, 256>>>(xq, a0, a1, nA);
    k_split2<<<(nW+255)/256, 256>>>(Wq, b0, b1, nW);
    k_gemm_mma<<<gmm, 256>>>(a0, a1, b0, b1, bq, qp);

    k_split2<<<(nA+255)/256, 256>>>(xk, a0, a1, nA);
    k_split2<<<(nW+255)/256, 256>>>(Wk, b0, b1, nW);
    k_gemm_mma<<<gmm, 256>>>(a0, a1, b0, b1, bk, kp);

    k_split2<<<(nA+255)/256, 256>>>(xv, a0, a1, nA);
    k_split2<<<(nW+255)/256, 256>>>(Wv, b0, b1, nW);
    k_gemm_mma<<<gmm, 256>>>(a0, a1, b0, b1, bv, vp);

    k_l2split<<<RR, 256>>>(qp, q0, q1);
    k_l2split<<<RR, 256>>>(kp, ks0, ks1);

    k_simE_mma<<<dim3(MM/128, NQ/128, NB), 256>>>();

    k_sink_pers<<<128, 256>>>();

    k_xgemm<<<dim3(NQ/128, CC/128, NB), 256>>>();

    k_split2<<<(nA+255)/256, 256>>>(xp, a0, a1, nA);
    k_split2<<<(nW+255)/256, 256>>>(Wp, b0, b1, nW);
    k_gemm_mma<<<gmm, 256>>>(a0, a1, b0, b1, bp, (float*)d_out);

    if (out_size >= RR*CC + RR)
        k_attn<<<RR/8, 256>>>((float*)d_out + (size_t)RR*CC);
}

// round 9
// speedup vs baseline: 1.6825x; 1.0637x over previous
#include <cuda_runtime.h>
#include <cuda_bf16.h>
#include <math.h>
#include <stdint.h>

#define NQ 1024
#define NB 8
#define MM 1024
#define CC 640
#define RR 8192
#define NITER 100
#define EPS_INV 20.0f
#define NU_P (1.0f/1024.0f + 1e-8f)

__device__ float g_q[RR*CC];
__device__ float g_k[RR*CC];
__device__ float g_v[RR*CC];
__device__ float g_x[RR*CC];
__device__ float g_sim[NB*MM*NQ];
__device__ float g_E[NB*MM*NQ];
__device__ float g_cpart[128*NQ];
__device__ float g_a[RR];
__device__ float g_mu[RR];
__device__ float g_bfin[RR];
__device__ unsigned char g_maskb[RR];
__device__ int g_counts[NB];
__device__ int g_mfmt;
__device__ unsigned int g_bar8[NB];
__device__ __nv_bfloat16 g_as0[RR*CC];
__device__ __nv_bfloat16 g_as1[RR*CC];
__device__ __nv_bfloat16 g_bs0[CC*CC];
__device__ __nv_bfloat16 g_bs1[CC*CC];
__device__ __nv_bfloat16 g_qs0[RR*CC];
__device__ __nv_bfloat16 g_qs1[RR*CC];
__device__ __nv_bfloat16 g_ks0[RR*CC];
__device__ __nv_bfloat16 g_ks1[RR*CC];

__device__ __forceinline__ int getmask_raw(const void* m, int idx, int fmt) {
    if (fmt == 1) return ((const int*)m)[idx] != 0;
    if (fmt == 2) return ((const float*)m)[idx] != 0.0f;
    return ((const unsigned char*)m)[idx] != 0;
}

__global__ void k_detect(const unsigned char* m) {
    __shared__ int cA, cB;
    if (threadIdx.x == 0) { cA = 0; cB = 0; }
    __syncthreads();
    int a = 0, b = 0;
    for (int i = threadIdx.x; i < RR; i += blockDim.x) {
        if (m[i] != 0) { if ((i & 3) == 0) a = 1; else b = 1; }
    }
    if (a) atomicOr(&cA, 1);
    if (b) atomicOr(&cB, 1);
    __syncthreads();
    if (threadIdx.x == 0) g_mfmt = (cB == 0) ? 1 : ((cA == 0) ? 2 : 0);
}

__global__ void k_counts(const void* mask) {
    __shared__ int sh[256];
    int fmt = g_mfmt, bb = blockIdx.x, s = 0;
    for (int m = threadIdx.x; m < MM; m += 256) s += getmask_raw(mask, bb*MM + m, fmt);
    sh[threadIdx.x] = s; __syncthreads();
    for (int o = 128; o; o >>= 1) { if (threadIdx.x < o) sh[threadIdx.x] += sh[threadIdx.x + o]; __syncthreads(); }
    if (threadIdx.x == 0) g_counts[bb] = (sh[0] > 0) ? sh[0] : 1;
}

__global__ void k_init(const void* mask) {
    int idx = blockIdx.x * blockDim.x + threadIdx.x;
    if (idx < NB) g_bar8[idx] = 0u;
    if (idx < RR) {
        int fmt = g_mfmt;
        int mk = getmask_raw(mask, idx, fmt);
        g_maskb[idx] = (unsigned char)mk;
        g_mu[idx] = mk ? (1.0f/(float)g_counts[idx >> 10] + 1e-8f) : 0.0f;
    }
}

__global__ void k_split2(const float* __restrict__ src,
                         __nv_bfloat16* __restrict__ d0,
                         __nv_bfloat16* __restrict__ d1, int n) {
    int i = blockIdx.x * blockDim.x + threadIdx.x;
    if (i >= n) return;
    float x = src[i];
    __nv_bfloat16 b0 = __float2bfloat16(x);
    float r = x - __bfloat162float(b0);
    d0[i] = b0; d1[i] = __float2bfloat16(r);
}

__global__ void k_l2split(const float* __restrict__ src,
                          __nv_bfloat16* __restrict__ d0,
                          __nv_bfloat16* __restrict__ d1) {
    __shared__ float sh[256];
    const float* row = src + (size_t)blockIdx.x * CC;
    float s = 0.0f;
    for (int i = threadIdx.x; i < CC; i += 256) { float v = row[i]; s += v*v; }
    sh[threadIdx.x] = s; __syncthreads();
    for (int o = 128; o; o >>= 1) { if (threadIdx.x < o) sh[threadIdx.x] += sh[threadIdx.x + o]; __syncthreads(); }
    float inv = 1.0f / fmaxf(sqrtf(sh[0]), 1e-12f);
    size_t base = (size_t)blockIdx.x * CC;
    for (int i = threadIdx.x; i < CC; i += 256) {
        float x = row[i] * inv;
        __nv_bfloat16 b0 = __float2bfloat16(x);
        float r = x - __bfloat162float(b0);
        d0[base + i] = b0; d1[base + i] = __float2bfloat16(r);
    }
}

#define SPAD 40
#define MMA_FRAGS \
    uint32_t af[2][4][4], bf[2][4][2]; \
    _Pragma("unroll") \
    for (int s = 0; s < 2; s++) { \
        _Pragma("unroll") \
        for (int mi = 0; mi < 4; mi++) { \
            int r0 = wm + mi*16 + g; \
            af[s][mi][0] = *(const uint32_t*)&As[s][r0][kk + tg*2]; \
            af[s][mi][1] = *(const uint32_t*)&As[s][r0+8][kk + tg*2]; \
            af[s][mi][2] = *(const uint32_t*)&As[s][r0][kk + tg*2 + 8]; \
            af[s][mi][3] = *(const uint32_t*)&As[s][r0+8][kk + tg*2 + 8]; \
        } \
        _Pragma("unroll") \
        for (int ni = 0; ni < 4; ni++) { \
            int c0 = wn + ni*8 + g; \
            bf[s][ni][0] = *(const uint32_t*)&Bs[s][c0][kk + tg*2]; \
            bf[s][ni][1] = *(const uint32_t*)&Bs[s][c0][kk + tg*2 + 8]; \
        } \
    } \
    _Pragma("unroll") \
    for (int p = 0; p < 3; p++) { \
        const int sa = (p == 2) ? 1 : 0, sb = (p == 1) ? 1 : 0; \
        _Pragma("unroll") \
        for (int mi = 0; mi < 4; mi++) \
            _Pragma("unroll") \
            for (int ni = 0; ni < 4; ni++) \
                asm volatile( \
                    "mma.sync.aligned.m16n8k16.row.col.f32.bf16.bf16.f32 " \
                    "{%0,%1,%2,%3}, {%4,%5,%6,%7}, {%8,%9}, {%0,%1,%2,%3};" \
                    : "+f"(acc[mi][ni][0]), "+f"(acc[mi][ni][1]), \
                      "+f"(acc[mi][ni][2]), "+f"(acc[mi][ni][3]) \
                    : "r"(af[sa][mi][0]), "r"(af[sa][mi][1]), \
                      "r"(af[sa][mi][2]), "r"(af[sa][mi][3]), \
                      "r"(bf[sb][ni][0]), "r"(bf[sb][ni][1])); \
    }

__global__ __launch_bounds__(256) void k_gemm_mma(
    const __nv_bfloat16* __restrict__ A0, const __nv_bfloat16* __restrict__ A1,
    const __nv_bfloat16* __restrict__ B0, const __nv_bfloat16* __restrict__ B1,
    const float* __restrict__ bias, float* __restrict__ Co) {
    __shared__ __nv_bfloat16 As[2][128][SPAD];
    __shared__ __nv_bfloat16 Bs[2][128][SPAD];
    const int tid = threadIdx.x, warp = tid >> 5, lane = tid & 31;
    const int g = lane >> 2, tg = lane & 3;
    const int i0 = blockIdx.x * 128, j0 = blockIdx.y * 128;
    const int wm = (warp & 1) * 64, wn = (warp >> 1) * 32;
    float acc[4][4][4];
    #pragma unroll
    for (int mi = 0; mi < 4; mi++)
        #pragma unroll
        for (int ni = 0; ni < 4; ni++)
            #pragma unroll
            for (int e = 0; e < 4; e++) acc[mi][ni][e] = 0.0f;
    const int lrow = tid >> 1, lseg = (tid & 1) * 2;
    for (int k0 = 0; k0 < CC; k0 += 32) {
        #pragma unroll
        for (int u = 0; u < 2; u++) {
            int seg = lseg + u;
            *(uint4*)&As[0][lrow][seg*8] = *(const uint4*)(A0 + (size_t)(i0+lrow)*CC + k0 + seg*8);
            *(uint4*)&As[1][lrow][seg*8] = *(const uint4*)(A1 + (size_t)(i0+lrow)*CC + k0 + seg*8);
            *(uint4*)&Bs[0][lrow][seg*8] = *(const uint4*)(B0 + (size_t)(j0+lrow)*CC + k0 + seg*8);
            *(uint4*)&Bs[1][lrow][seg*8] = *(const uint4*)(B1 + (size_t)(j0+lrow)*CC + k0 + seg*8);
        }
        __syncthreads();
        #pragma unroll
        for (int kk = 0; kk < 32; kk += 16) { MMA_FRAGS }
        __syncthreads();
    }
    #pragma unroll
    for (int mi = 0; mi < 4; mi++) {
        int r0 = i0 + wm + mi*16 + g;
        #pragma unroll
        for (int ni = 0; ni < 4; ni++) {
            int c = j0 + wn + ni*8 + tg*2;
            float b0v = bias[c], b1v = bias[c+1];
            Co[(size_t)r0*CC + c]       = acc[mi][ni][0] + b0v;
            Co[(size_t)r0*CC + c+1]     = acc[mi][ni][1] + b1v;
            Co[(size_t)(r0+8)*CC + c]   = acc[mi][ni][2] + b0v;
            Co[(size_t)(r0+8)*CC + c+1] = acc[mi][ni][3] + b1v;
        }
    }
}

__global__ __launch_bounds__(256) void k_simE_mma() {
    __shared__ __nv_bfloat16 As[2][128][SPAD];
    __shared__ __nv_bfloat16 Bs[2][128][SPAD];
    const int tid = threadIdx.x, warp = tid >> 5, lane = tid & 31;
    const int g = lane >> 2, tg = lane & 3;
    const int bb = blockIdx.z, m0 = blockIdx.x * 128, n0 = blockIdx.y * 128;
    const int wm = (warp & 1) * 64, wn = (warp >> 1) * 32;
    float acc[4][4][4];
    #pragma unroll
    for (int mi = 0; mi < 4; mi++)
        #pragma unroll
        for (int ni = 0; ni < 4; ni++)
            #pragma unroll
            for (int e = 0; e < 4; e++) acc[mi][ni][e] = 0.0f;
    const int lrow = tid >> 1, lseg = (tid & 1) * 2;
    const size_t abase = (size_t)(bb*MM + m0);
    for (int k0 = 0; k0 < CC; k0 += 32) {
        #pragma unroll
        for (int u = 0; u < 2; u++) {
            int seg = lseg + u;
            *(uint4*)&As[0][lrow][seg*8] = *(const uint4*)(g_ks0 + (abase + lrow)*CC + k0 + seg*8);
            *(uint4*)&As[1][lrow][seg*8] = *(const uint4*)(g_ks1 + (abase + lrow)*CC + k0 + seg*8);
            size_t qrow = (size_t)(n0 + lrow)*NB + bb;
            *(uint4*)&Bs[0][lrow][seg*8] = *(const uint4*)(g_qs0 + qrow*CC + k0 + seg*8);
            *(uint4*)&Bs[1][lrow][seg*8] = *(const uint4*)(g_qs1 + qrow*CC + k0 + seg*8);
        }
        __syncthreads();
        #pragma unroll
        for (int kk = 0; kk < 32; kk += 16) { MMA_FRAGS }
        __syncthreads();
    }
    #pragma unroll
    for (int mi = 0; mi < 4; mi++) {
        int mA = m0 + wm + mi*16 + g;
        int mB = mA + 8;
        int mkA = g_maskb[bb*MM + mA], mkB = g_maskb[bb*MM + mB];
        size_t baseA = ((size_t)bb*MM + mA) * NQ;
        size_t baseB = ((size_t)bb*MM + mB) * NQ;
        #pragma unroll
        for (int ni = 0; ni < 4; ni++) {
            int c = n0 + wn + ni*8 + tg*2;
            float s0 = acc[mi][ni][0], s1 = acc[mi][ni][1];
            float s2 = acc[mi][ni][2], s3 = acc[mi][ni][3];
            g_sim[baseA + c]   = s0; g_sim[baseA + c+1] = s1;
            g_sim[baseB + c]   = s2; g_sim[baseB + c+1] = s3;
            g_E[baseA + c]   = mkA ? expf((s0 - 1.0f) * EPS_INV) : 0.0f;
            g_E[baseA + c+1] = mkA ? expf((s1 - 1.0f) * EPS_INV) : 0.0f;
            g_E[baseB + c]   = mkB ? expf((s2 - 1.0f) * EPS_INV) : 0.0f;
            g_E[baseB + c+1] = mkB ? expf((s3 - 1.0f) * EPS_INV) : 0.0f;
        }
    }
}

// ---------- HMMA TN xgemm: x[n][b][c] = bfin_n * sum_m E[b][m][n]*(a_m*v[b][m][c]) ----------
// smem load phase transposes + splits fp32 -> bf16x2 on the fly.
__global__ __launch_bounds__(256) void k_xgemm_mma() {
    __shared__ __nv_bfloat16 As[2][128][SPAD];   // [n][m]
    __shared__ __nv_bfloat16 Bs[2][128][SPAD];   // [c][m]
    const int tid = threadIdx.x, warp = tid >> 5, lane = tid & 31;
    const int g = lane >> 2, tg = lane & 3;
    const int bb = blockIdx.z, n0 = blockIdx.x * 128, c0 = blockIdx.y * 128;
    const int wm = (warp & 1) * 64, wn = (warp >> 1) * 32;
    float acc[4][4][4];
    #pragma unroll
    for (int mi = 0; mi < 4; mi++)
        #pragma unroll
        for (int ni = 0; ni < 4; ni++)
            #pragma unroll
            for (int e = 0; e < 4; e++) acc[mi][ni][e] = 0.0f;
    const float* Eb = g_E + (size_t)bb*MM*NQ;
    const float* Vb = g_v + (size_t)bb*MM*CC;
    const int lm = tid & 31, lg = tid >> 5;      // lm: m-within-chunk, lg: 16-col group
    for (int k0 = 0; k0 < MM; k0 += 32) {
        int m = k0 + lm;
        float am = g_a[bb*MM + m];
        #pragma unroll
        for (int j = 0; j < 4; j++) {
            int n = lg*16 + j*4;
            float4 ev = *(const float4*)(Eb + (size_t)m*NQ + n0 + n);
            float4 vv = *(const float4*)(Vb + (size_t)m*CC + c0 + n);
            vv.x *= am; vv.y *= am; vv.z *= am; vv.w *= am;
            float ee[4] = {ev.x, ev.y, ev.z, ev.w};
            float va[4] = {vv.x, vv.y, vv.z, vv.w};
            #pragma unroll
            for (int q = 0; q < 4; q++) {
                __nv_bfloat16 h = __float2bfloat16(ee[q]);
                As[0][n + q][lm] = h;
                As[1][n + q][lm] = __float2bfloat16(ee[q] - __bfloat162float(h));
                __nv_bfloat16 hv = __float2bfloat16(va[q]);
                Bs[0][n + q][lm] = hv;
                Bs[1][n + q][lm] = __float2bfloat16(va[q] - __bfloat162float(hv));
            }
        }
        __syncthreads();
        #pragma unroll
        for (int kk = 0; kk < 32; kk += 16) { MMA_FRAGS }
        __syncthreads();
    }
    #pragma unroll
    for (int mi = 0; mi < 4; mi++) {
        int nA = n0 + wm + mi*16 + g;
        int nB = nA + 8;
        float bnA = g_bfin[bb*NQ + nA], bnB = g_bfin[bb*NQ + nB];
        #pragma unroll
        for (int ni = 0; ni < 4; ni++) {
            int c = c0 + wn + ni*8 + tg*2;
            g_x[((size_t)nA*NB + bb)*CC + c]   = acc[mi][ni][0] * bnA;
            g_x[((size_t)nA*NB + bb)*CC + c+1] = acc[mi][ni][1] * bnA;
            g_x[((size_t)nB*NB + bb)*CC + c]   = acc[mi][ni][2] * bnB;
            g_x[((size_t)nB*NB + bb)*CC + c+1] = acc[mi][ni][3] * bnB;
        }
    }
}

// persistent Sinkhorn: 128 blocks, per-batch 16-block barriers
__global__ __launch_bounds__(256) void k_sink_pers() {
    __shared__ float sh[8*1024];
    const int blk = blockIdx.x, bb = blk >> 4, rb = blk & 15;
    const int tid = threadIdx.x, warp = tid >> 5, lane = tid & 31;
    const float* Eb = g_E + (size_t)bb*MM*NQ;
    const int m0 = rb*64 + warp*8;
    const int col = tid * 4;
    float bv[32];
    #pragma unroll
    for (int q = 0; q < 32; q++) bv[q] = 1.0f;
    for (int it = 1; it <= NITER; it++) {
        float cacc[32];
        #pragma unroll
        for (int q = 0; q < 32; q++) cacc[q] = 0.0f;
        #pragma unroll
        for (int rr = 0; rr < 8; rr++) {
            int m = m0 + rr;
            if (!g_maskb[bb*MM + m]) {
                if (it == NITER && lane == 0) g_a[bb*MM + m] = 0.0f;
                continue;
            }
            const float4* er = (const float4*)(Eb + (size_t)m * NQ);
            float e[32], s = 0.0f;
            #pragma unroll
            for (int g = 0; g < 8; g++) {
                float4 v = __ldg(&er[g*32 + lane]);
                e[g*4+0]=v.x; e[g*4+1]=v.y; e[g*4+2]=v.z; e[g*4+3]=v.w;
                s += v.x*bv[g*4+0] + v.y*bv[g*4+1] + v.z*bv[g*4+2] + v.w*bv[g*4+3];
            }
            #pragma unroll
            for (int o = 16; o; o >>= 1) s += __shfl_xor_sync(0xffffffffu, s, o);
            float a = g_mu[bb*MM + m] / s;
            if (it == NITER && lane == 0) g_a[bb*MM + m] = a;
            #pragma unroll
            for (int q = 0; q < 32; q++) cacc[q] += a * e[q];
        }
        #pragma unroll
        for (int g = 0; g < 8; g++)
            *(float4*)&sh[warp*1024 + g*128 + lane*4] =
                make_float4(cacc[g*4], cacc[g*4+1], cacc[g*4+2], cacc[g*4+3]);
        __syncthreads();
        float s0=0, s1=0, s2=0, s3=0;
        #pragma unroll
        for (int w = 0; w < 8; w++) {
            float4 v = *(const float4*)&sh[w*1024 + col];
            s0 += v.x; s1 += v.y; s2 += v.z; s3 += v.w;
        }
        *(float4*)&g_cpart[(size_t)blk*NQ + col] = make_float4(s0, s1, s2, s3);
        __threadfence();
        __syncthreads();
        if (tid == 0) {
            atomicAdd(&g_bar8[bb], 1u);
            unsigned int target = (unsigned int)it * 16u;
            while (atomicAdd(&g_bar8[bb], 0u) < target) __nanosleep(64);
        }
        __syncthreads();
        __threadfence();
        if (it < NITER) {
            float c0=0, c1=0, c2=0, c3=0;
            #pragma unroll
            for (int w = 0; w < 16; w++) {
                float4 v = *(const float4*)&g_cpart[(size_t)(bb*16 + w)*NQ + col];
                c0 += v.x; c1 += v.y; c2 += v.z; c3 += v.w;
            }
            sh[col+0] = NU_P / c0; sh[col+1] = NU_P / c1;
            sh[col+2] = NU_P / c2; sh[col+3] = NU_P / c3;
            __syncthreads();
            #pragma unroll
            for (int g = 0; g < 8; g++) {
                float4 v = *(const float4*)&sh[g*128 + lane*4];
                bv[g*4+0]=v.x; bv[g*4+1]=v.y; bv[g*4+2]=v.z; bv[g*4+3]=v.w;
            }
            __syncthreads();
        }
    }
    if (rb == 0) {
        float c0=0, c1=0, c2=0, c3=0;
        #pragma unroll
        for (int w = 0; w < 16; w++) {
            float4 v = *(const float4*)&g_cpart[(size_t)(bb*16 + w)*NQ + col];
            c0 += v.x; c1 += v.y; c2 += v.z; c3 += v.w;
        }
        g_bfin[bb*NQ+col+0] = NU_P / c0; g_bfin[bb*NQ+col+1] = NU_P / c1;
        g_bfin[bb*NQ+col+2] = NU_P / c2; g_bfin[bb*NQ+col+3] = NU_P / c3;
    }
}

__global__ void k_attn(float* outp) {
    const int warp = threadIdx.x >> 5, lane = threadIdx.x & 31;
    int r = blockIdx.x * 8 + warp;
    if (r >= RR) return;
    int bb = r >> 10;
    float val = 0.0f;
    if (g_maskb[r]) {
        const float* S = g_sim + (size_t)r * NQ;
        const float* E = g_E + (size_t)r * NQ;
        const float* bf = g_bfin + bb * NQ;
        float s = 0.0f;
        #pragma unroll
        for (int g = 0; g < 8; g++) {
            int n = g*128 + lane*4;
            float4 sv = *(const float4*)(S + n);
            float4 ev = *(const float4*)(E + n);
            float4 bv = *(const float4*)(bf + n);
            s += sv.x*ev.x*bv.x + sv.y*ev.y*bv.y + sv.z*ev.z*bv.z + sv.w*ev.w*bv.w;
        }
        #pragma unroll
        for (int o = 16; o; o >>= 1) s += __shfl_xor_sync(0xffffffffu, s, o);
        val = 1048576.0f * g_a[r] * s;
    }
    if (lane == 0) outp[r] = val;
}

extern "C" void kernel_launch(void* const* d_in, const int* in_sizes, int n_in,
                              void* d_out, int out_size) {
    const float* xq = (const float*)d_in[0];
    const float* xk = (const float*)d_in[1];
    const float* xv = (const float*)d_in[2];
    const void*  mk = d_in[3];
    const float* Wq = (const float*)d_in[4];
    const float* bq = (const float*)d_in[5];
    const float* Wk = (const float*)d_in[6];
    const float* bk = (const float*)d_in[7];
    const float* Wv = (const float*)d_in[8];
    const float* bv = (const float*)d_in[9];
    const float* Wp = (const float*)d_in[10];
    const float* bp = (const float*)d_in[11];
    float *qp, *kp, *vp, *xp;
    __nv_bfloat16 *a0, *a1, *b0, *b1, *q0, *q1, *ks0, *ks1;
    cudaGetSymbolAddress((void**)&qp, g_q);
    cudaGetSymbolAddress((void**)&kp, g_k);
    cudaGetSymbolAddress((void**)&vp, g_v);
    cudaGetSymbolAddress((void**)&xp, g_x);
    cudaGetSymbolAddress((void**)&a0, g_as0);
    cudaGetSymbolAddress((void**)&a1, g_as1);
    cudaGetSymbolAddress((void**)&b0, g_bs0);
    cudaGetSymbolAddress((void**)&b1, g_bs1);
    cudaGetSymbolAddress((void**)&q0, g_qs0);
    cudaGetSymbolAddress((void**)&q1, g_qs1);
    cudaGetSymbolAddress((void**)&ks0, g_ks0);
    cudaGetSymbolAddress((void**)&ks1, g_ks1);

    k_detect<<<1, 256>>>((const unsigned char*)mk);
    k_counts<<<NB, 256>>>(mk);
    k_init<<<(RR + 255)/256, 256>>>(mk);

    const int nA = RR*CC, nW = CC*CC;
    dim3 gmm(RR/128, CC/128);

    k_split2<<<(nA+255)/256, 256>>>(xq, a0, a1, nA);
    k_split2<<<(nW+255)/256, 256>>>(Wq, b0, b1, nW);
    k_gemm_mma<<<gmm, 256>>>(a0, a1, b0, b1, bq, qp);

    k_split2<<<(nA+255)/256, 256>>>(xk, a0, a1, nA);
    k_split2<<<(nW+255)/256, 256>>>(Wk, b0, b1, nW);
    k_gemm_mma<<<gmm, 256>>>(a0, a1, b0, b1, bk, kp);

    k_split2<<<(nA+255)/256, 256>>>(xv, a0, a1, nA);
    k_split2<<<(nW+255)/256, 256>>>(Wv, b0, b1, nW);
    k_gemm_mma<<<gmm, 256>>>(a0, a1, b0, b1, bv, vp);

    k_l2split<<<RR, 256>>>(qp, q0, q1);
    k_l2split<<<RR, 256>>>(kp, ks0, ks1);

    k_simE_mma<<<dim3(MM/128, NQ/128, NB), 256>>>();

    k_sink_pers<<<128, 256>>>();

    k_xgemm_mma<<<dim3(NQ/128, CC/128, NB), 256>>>();

    k_split2<<<(nA+255)/256, 256>>>(xp, a0, a1, nA);
    k_split2<<<(nW+255)/256, 256>>>(Wp, b0, b1, nW);
    k_gemm_mma<<<gmm, 256>>>(a0, a1, b0, b1, bp, (float*)d_out);

    if (out_size >= RR*CC + RR)
        k_attn<<<RR/8, 256>>>((float*)d_out + (size_t)RR*CC);
}

// round 10
// speedup vs baseline: 1.7248x; 1.0252x over previous
#include <cuda_runtime.h>
#include <cuda_bf16.h>
#include <math.h>
#include <stdint.h>

#define NQ 1024
#define NB 8
#define MM 1024
#define CC 640
#define RR 8192
#define NITER 100
#define EPS_INV 20.0f
#define NU_P (1.0f/1024.0f + 1e-8f)

__device__ float g_q[RR*CC];
__device__ float g_k[RR*CC];
__device__ float g_v[RR*CC];
__device__ float g_x[RR*CC];
__device__ float g_sim[NB*MM*NQ];
__device__ float g_E[NB*MM*NQ];
__device__ __nv_bfloat16 g_Ebf[NB*MM*NQ];
__device__ float g_cpart[128*NQ];
__device__ float g_a[RR];
__device__ float g_mu[RR];
__device__ float g_bfin[RR];
__device__ unsigned char g_maskb[RR];
__device__ int g_counts[NB];
__device__ int g_mfmt;
__device__ unsigned int g_bar8[NB];
__device__ __nv_bfloat16 g_qs0[RR*CC];
__device__ __nv_bfloat16 g_qs1[RR*CC];
__device__ __nv_bfloat16 g_ks0[RR*CC];
__device__ __nv_bfloat16 g_ks1[RR*CC];

__device__ __forceinline__ int getmask_raw(const void* m, int idx, int fmt) {
    if (fmt == 1) return ((const int*)m)[idx] != 0;
    if (fmt == 2) return ((const float*)m)[idx] != 0.0f;
    return ((const unsigned char*)m)[idx] != 0;
}

__global__ void k_detect(const unsigned char* m) {
    __shared__ int cA, cB;
    if (threadIdx.x == 0) { cA = 0; cB = 0; }
    __syncthreads();
    int a = 0, b = 0;
    for (int i = threadIdx.x; i < RR; i += blockDim.x) {
        if (m[i] != 0) { if ((i & 3) == 0) a = 1; else b = 1; }
    }
    if (a) atomicOr(&cA, 1);
    if (b) atomicOr(&cB, 1);
    __syncthreads();
    if (threadIdx.x == 0) g_mfmt = (cB == 0) ? 1 : ((cA == 0) ? 2 : 0);
}

__global__ void k_counts(const void* mask) {
    __shared__ int sh[256];
    int fmt = g_mfmt, bb = blockIdx.x, s = 0;
    for (int m = threadIdx.x; m < MM; m += 256) s += getmask_raw(mask, bb*MM + m, fmt);
    sh[threadIdx.x] = s; __syncthreads();
    for (int o = 128; o; o >>= 1) { if (threadIdx.x < o) sh[threadIdx.x] += sh[threadIdx.x + o]; __syncthreads(); }
    if (threadIdx.x == 0) g_counts[bb] = (sh[0] > 0) ? sh[0] : 1;
}

__global__ void k_init(const void* mask) {
    int idx = blockIdx.x * blockDim.x + threadIdx.x;
    if (idx < NB) g_bar8[idx] = 0u;
    if (idx < RR) {
        int fmt = g_mfmt;
        int mk = getmask_raw(mask, idx, fmt);
        g_maskb[idx] = (unsigned char)mk;
        g_mu[idx] = mk ? (1.0f/(float)g_counts[idx >> 10] + 1e-8f) : 0.0f;
    }
}

// fused l2-normalize + bf16x2 split (one row per block)
__global__ void k_l2split(const float* __restrict__ src,
                          __nv_bfloat16* __restrict__ d0,
                          __nv_bfloat16* __restrict__ d1) {
    __shared__ float sh[256];
    const float* row = src + (size_t)blockIdx.x * CC;
    float s = 0.0f;
    for (int i = threadIdx.x; i < CC; i += 256) { float v = row[i]; s += v*v; }
    sh[threadIdx.x] = s; __syncthreads();
    for (int o = 128; o; o >>= 1) { if (threadIdx.x < o) sh[threadIdx.x] += sh[threadIdx.x + o]; __syncthreads(); }
    float inv = 1.0f / fmaxf(sqrtf(sh[0]), 1e-12f);
    size_t base = (size_t)blockIdx.x * CC;
    for (int i = threadIdx.x; i < CC; i += 256) {
        float x = row[i] * inv;
        __nv_bfloat16 b0 = __float2bfloat16(x);
        float r = x - __bfloat162float(b0);
        d0[base + i] = b0; d1[base + i] = __float2bfloat16(r);
    }
}

// split 8 contiguous fp32 into hi/lo bf16 octets, store as uint4 each
__device__ __forceinline__ void split8_store(float4 v0, float4 v1,
                                             __nv_bfloat16* dhi, __nv_bfloat16* dlo) {
    float f[8] = {v0.x, v0.y, v0.z, v0.w, v1.x, v1.y, v1.z, v1.w};
    uint32_t hw[4], lw[4];
    #pragma unroll
    for (int i = 0; i < 4; i++) {
        __nv_bfloat16 h0 = __float2bfloat16(f[2*i]);
        __nv_bfloat16 h1 = __float2bfloat16(f[2*i+1]);
        __nv_bfloat162 hp = __halves2bfloat162(h0, h1);
        hw[i] = *(uint32_t*)&hp;
        __nv_bfloat16 l0 = __float2bfloat16(f[2*i]   - __bfloat162float(h0));
        __nv_bfloat16 l1 = __float2bfloat16(f[2*i+1] - __bfloat162float(h1));
        __nv_bfloat162 lp = __halves2bfloat162(l0, l1);
        lw[i] = *(uint32_t*)&lp;
    }
    *(uint4*)dhi = make_uint4(hw[0], hw[1], hw[2], hw[3]);
    *(uint4*)dlo = make_uint4(lw[0], lw[1], lw[2], lw[3]);
}

#define SPAD 40
#define MMA_FRAGS \
    uint32_t af[2][4][4], bf[2][4][2]; \
    _Pragma("unroll") \
    for (int s = 0; s < 2; s++) { \
        _Pragma("unroll") \
        for (int mi = 0; mi < 4; mi++) { \
            int r0 = wm + mi*16 + g; \
            af[s][mi][0] = *(const uint32_t*)&As[s][r0][kk + tg*2]; \
            af[s][mi][1] = *(const uint32_t*)&As[s][r0+8][kk + tg*2]; \
            af[s][mi][2] = *(const uint32_t*)&As[s][r0][kk + tg*2 + 8]; \
            af[s][mi][3] = *(const uint32_t*)&As[s][r0+8][kk + tg*2 + 8]; \
        } \
        _Pragma("unroll") \
        for (int ni = 0; ni < 4; ni++) { \
            int c0 = wn + ni*8 + g; \
            bf[s][ni][0] = *(const uint32_t*)&Bs[s][c0][kk + tg*2]; \
            bf[s][ni][1] = *(const uint32_t*)&Bs[s][c0][kk + tg*2 + 8]; \
        } \
    } \
    _Pragma("unroll") \
    for (int p = 0; p < 3; p++) { \
        const int sa = (p == 2) ? 1 : 0, sb = (p == 1) ? 1 : 0; \
        _Pragma("unroll") \
        for (int mi = 0; mi < 4; mi++) \
            _Pragma("unroll") \
            for (int ni = 0; ni < 4; ni++) \
                asm volatile( \
                    "mma.sync.aligned.m16n8k16.row.col.f32.bf16.bf16.f32 " \
                    "{%0,%1,%2,%3}, {%4,%5,%6,%7}, {%8,%9}, {%0,%1,%2,%3};" \
                    : "+f"(acc[mi][ni][0]), "+f"(acc[mi][ni][1]), \
                      "+f"(acc[mi][ni][2]), "+f"(acc[mi][ni][3]) \
                    : "r"(af[sa][mi][0]), "r"(af[sa][mi][1]), \
                      "r"(af[sa][mi][2]), "r"(af[sa][mi][3]), \
                      "r"(bf[sb][ni][0]), "r"(bf[sb][ni][1])); \
    }

// HMMA bf16x2 NT GEMM reading fp32 directly (split fused into smem store):
// C[r][j] = sum_t A[r][t]*B[j][t] + bias[j]
__global__ __launch_bounds__(256) void k_gemm_mma(
    const float* __restrict__ A, const float* __restrict__ B,
    const float* __restrict__ bias, float* __restrict__ Co) {
    __shared__ __nv_bfloat16 As[2][128][SPAD];
    __shared__ __nv_bfloat16 Bs[2][128][SPAD];
    const int tid = threadIdx.x, warp = tid >> 5, lane = tid & 31;
    const int g = lane >> 2, tg = lane & 3;
    const int i0 = blockIdx.x * 128, j0 = blockIdx.y * 128;
    const int wm = (warp & 1) * 64, wn = (warp >> 1) * 32;
    float acc[4][4][4];
    #pragma unroll
    for (int mi = 0; mi < 4; mi++)
        #pragma unroll
        for (int ni = 0; ni < 4; ni++)
            #pragma unroll
            for (int e = 0; e < 4; e++) acc[mi][ni][e] = 0.0f;
    const int lrow = tid >> 1, lseg = (tid & 1) * 2;
    for (int k0 = 0; k0 < CC; k0 += 32) {
        #pragma unroll
        for (int u = 0; u < 2; u++) {
            int seg = lseg + u;
            const float* pa = A + (size_t)(i0+lrow)*CC + k0 + seg*8;
            const float* pb = B + (size_t)(j0+lrow)*CC + k0 + seg*8;
            float4 a0 = *(const float4*)pa, a1 = *(const float4*)(pa+4);
            float4 b0 = *(const float4*)pb, b1 = *(const float4*)(pb+4);
            split8_store(a0, a1, &As[0][lrow][seg*8], &As[1][lrow][seg*8]);
            split8_store(b0, b1, &Bs[0][lrow][seg*8], &Bs[1][lrow][seg*8]);
        }
        __syncthreads();
        #pragma unroll
        for (int kk = 0; kk < 32; kk += 16) { MMA_FRAGS }
        __syncthreads();
    }
    #pragma unroll
    for (int mi = 0; mi < 4; mi++) {
        int r0 = i0 + wm + mi*16 + g;
        #pragma unroll
        for (int ni = 0; ni < 4; ni++) {
            int c = j0 + wn + ni*8 + tg*2;
            float b0v = bias[c], b1v = bias[c+1];
            Co[(size_t)r0*CC + c]       = acc[mi][ni][0] + b0v;
            Co[(size_t)r0*CC + c+1]     = acc[mi][ni][1] + b1v;
            Co[(size_t)(r0+8)*CC + c]   = acc[mi][ni][2] + b0v;
            Co[(size_t)(r0+8)*CC + c+1] = acc[mi][ni][3] + b1v;
        }
    }
}

__global__ __launch_bounds__(256) void k_simE_mma() {
    __shared__ __nv_bfloat16 As[2][128][SPAD];
    __shared__ __nv_bfloat16 Bs[2][128][SPAD];
    const int tid = threadIdx.x, warp = tid >> 5, lane = tid & 31;
    const int g = lane >> 2, tg = lane & 3;
    const int bb = blockIdx.z, m0 = blockIdx.x * 128, n0 = blockIdx.y * 128;
    const int wm = (warp & 1) * 64, wn = (warp >> 1) * 32;
    float acc[4][4][4];
    #pragma unroll
    for (int mi = 0; mi < 4; mi++)
        #pragma unroll
        for (int ni = 0; ni < 4; ni++)
            #pragma unroll
            for (int e = 0; e < 4; e++) acc[mi][ni][e] = 0.0f;
    const int lrow = tid >> 1, lseg = (tid & 1) * 2;
    const size_t abase = (size_t)(bb*MM + m0);
    for (int k0 = 0; k0 < CC; k0 += 32) {
        #pragma unroll
        for (int u = 0; u < 2; u++) {
            int seg = lseg + u;
            *(uint4*)&As[0][lrow][seg*8] = *(const uint4*)(g_ks0 + (abase + lrow)*CC + k0 + seg*8);
            *(uint4*)&As[1][lrow][seg*8] = *(const uint4*)(g_ks1 + (abase + lrow)*CC + k0 + seg*8);
            size_t qrow = (size_t)(n0 + lrow)*NB + bb;
            *(uint4*)&Bs[0][lrow][seg*8] = *(const uint4*)(g_qs0 + qrow*CC + k0 + seg*8);
            *(uint4*)&Bs[1][lrow][seg*8] = *(const uint4*)(g_qs1 + qrow*CC + k0 + seg*8);
        }
        __syncthreads();
        #pragma unroll
        for (int kk = 0; kk < 32; kk += 16) { MMA_FRAGS }
        __syncthreads();
    }
    #pragma unroll
    for (int mi = 0; mi < 4; mi++) {
        int mA = m0 + wm + mi*16 + g;
        int mB = mA + 8;
        int mkA = g_maskb[bb*MM + mA], mkB = g_maskb[bb*MM + mB];
        size_t baseA = ((size_t)bb*MM + mA) * NQ;
        size_t baseB = ((size_t)bb*MM + mB) * NQ;
        #pragma unroll
        for (int ni = 0; ni < 4; ni++) {
            int c = n0 + wn + ni*8 + tg*2;
            float s0 = acc[mi][ni][0], s1 = acc[mi][ni][1];
            float s2 = acc[mi][ni][2], s3 = acc[mi][ni][3];
            g_sim[baseA + c]   = s0; g_sim[baseA + c+1] = s1;
            g_sim[baseB + c]   = s2; g_sim[baseB + c+1] = s3;
            float e0 = mkA ? expf((s0 - 1.0f) * EPS_INV) : 0.0f;
            float e1 = mkA ? expf((s1 - 1.0f) * EPS_INV) : 0.0f;
            float e2 = mkB ? expf((s2 - 1.0f) * EPS_INV) : 0.0f;
            float e3 = mkB ? expf((s3 - 1.0f) * EPS_INV) : 0.0f;
            g_E[baseA + c]   = e0; g_E[baseA + c+1] = e1;
            g_E[baseB + c]   = e2; g_E[baseB + c+1] = e3;
            g_Ebf[baseA + c]   = __float2bfloat16(e0);
            g_Ebf[baseA + c+1] = __float2bfloat16(e1);
            g_Ebf[baseB + c]   = __float2bfloat16(e2);
            g_Ebf[baseB + c+1] = __float2bfloat16(e3);
        }
    }
}

// HMMA TN xgemm: x[n][b][c] = bfin_n * sum_m E[b][m][n]*(a_m*v[b][m][c])
__global__ __launch_bounds__(256) void k_xgemm_mma() {
    __shared__ __nv_bfloat16 As[2][128][SPAD];
    __shared__ __nv_bfloat16 Bs[2][128][SPAD];
    const int tid = threadIdx.x, warp = tid >> 5, lane = tid & 31;
    const int g = lane >> 2, tg = lane & 3;
    const int bb = blockIdx.z, n0 = blockIdx.x * 128, c0 = blockIdx.y * 128;
    const int wm = (warp & 1) * 64, wn = (warp >> 1) * 32;
    float acc[4][4][4];
    #pragma unroll
    for (int mi = 0; mi < 4; mi++)
        #pragma unroll
        for (int ni = 0; ni < 4; ni++)
            #pragma unroll
            for (int e = 0; e < 4; e++) acc[mi][ni][e] = 0.0f;
    const float* Eb = g_E + (size_t)bb*MM*NQ;
    const float* Vb = g_v + (size_t)bb*MM*CC;
    const int lm = tid & 31, lg = tid >> 5;
    for (int k0 = 0; k0 < MM; k0 += 32) {
        int m = k0 + lm;
        float am = g_a[bb*MM + m];
        #pragma unroll
        for (int j = 0; j < 4; j++) {
            int n = lg*16 + j*4;
            float4 ev = *(const float4*)(Eb + (size_t)m*NQ + n0 + n);
            float4 vv = *(const float4*)(Vb + (size_t)m*CC + c0 + n);
            vv.x *= am; vv.y *= am; vv.z *= am; vv.w *= am;
            float ee[4] = {ev.x, ev.y, ev.z, ev.w};
            float va[4] = {vv.x, vv.y, vv.z, vv.w};
            #pragma unroll
            for (int q = 0; q < 4; q++) {
                __nv_bfloat16 h = __float2bfloat16(ee[q]);
                As[0][n + q][lm] = h;
                As[1][n + q][lm] = __float2bfloat16(ee[q] - __bfloat162float(h));
                __nv_bfloat16 hv = __float2bfloat16(va[q]);
                Bs[0][n + q][lm] = hv;
                Bs[1][n + q][lm] = __float2bfloat16(va[q] - __bfloat162float(hv));
            }
        }
        __syncthreads();
        #pragma unroll
        for (int kk = 0; kk < 32; kk += 16) { MMA_FRAGS }
        __syncthreads();
    }
    #pragma unroll
    for (int mi = 0; mi < 4; mi++) {
        int nA = n0 + wm + mi*16 + g;
        int nB = nA + 8;
        float bnA = g_bfin[bb*NQ + nA], bnB = g_bfin[bb*NQ + nB];
        #pragma unroll
        for (int ni = 0; ni < 4; ni++) {
            int c = c0 + wn + ni*8 + tg*2;
            g_x[((size_t)nA*NB + bb)*CC + c]   = acc[mi][ni][0] * bnA;
            g_x[((size_t)nA*NB + bb)*CC + c+1] = acc[mi][ni][1] * bnA;
            g_x[((size_t)nB*NB + bb)*CC + c]   = acc[mi][ni][2] * bnB;
            g_x[((size_t)nB*NB + bb)*CC + c+1] = acc[mi][ni][3] * bnB;
        }
    }
}

// persistent Sinkhorn over bf16 E: 128 blocks, per-batch 16-block barriers
__global__ __launch_bounds__(256) void k_sink_pers() {
    __shared__ float sh[8*1024];
    const int blk = blockIdx.x, bb = blk >> 4, rb = blk & 15;
    const int tid = threadIdx.x, warp = tid >> 5, lane = tid & 31;
    const __nv_bfloat16* Eb = g_Ebf + (size_t)bb*MM*NQ;
    const int m0 = rb*64 + warp*8;
    const int col = tid * 4;
    float bv[32];
    #pragma unroll
    for (int q = 0; q < 32; q++) bv[q] = 1.0f;
    for (int it = 1; it <= NITER; it++) {
        float cacc[32];
        #pragma unroll
        for (int q = 0; q < 32; q++) cacc[q] = 0.0f;
        #pragma unroll
        for (int rr = 0; rr < 8; rr++) {
            int m = m0 + rr;
            if (!g_maskb[bb*MM + m]) {
                if (it == NITER && lane == 0) g_a[bb*MM + m] = 0.0f;
                continue;
            }
            const __nv_bfloat16* er = Eb + (size_t)m * NQ;
            float e[32], s = 0.0f;
            #pragma unroll
            for (int g = 0; g < 8; g++) {
                uint2 w = *(const uint2*)(er + g*128 + lane*4);
                __nv_bfloat162 p0 = *(__nv_bfloat162*)&w.x;
                __nv_bfloat162 p1 = *(__nv_bfloat162*)&w.y;
                e[g*4+0] = __bfloat162float(__low2bfloat16(p0));
                e[g*4+1] = __bfloat162float(__high2bfloat16(p0));
                e[g*4+2] = __bfloat162float(__low2bfloat16(p1));
                e[g*4+3] = __bfloat162float(__high2bfloat16(p1));
                s += e[g*4+0]*bv[g*4+0] + e[g*4+1]*bv[g*4+1]
                   + e[g*4+2]*bv[g*4+2] + e[g*4+3]*bv[g*4+3];
            }
            #pragma unroll
            for (int o = 16; o; o >>= 1) s += __shfl_xor_sync(0xffffffffu, s, o);
            float a = g_mu[bb*MM + m] / s;
            if (it == NITER && lane == 0) g_a[bb*MM + m] = a;
            #pragma unroll
            for (int q = 0; q < 32; q++) cacc[q] += a * e[q];
        }
        #pragma unroll
        for (int g = 0; g < 8; g++)
            *(float4*)&sh[warp*1024 + g*128 + lane*4] =
                make_float4(cacc[g*4], cacc[g*4+1], cacc[g*4+2], cacc[g*4+3]);
        __syncthreads();
        float s0=0, s1=0, s2=0, s3=0;
        #pragma unroll
        for (int w = 0; w < 8; w++) {
            float4 v = *(const float4*)&sh[w*1024 + col];
            s0 += v.x; s1 += v.y; s2 += v.z; s3 += v.w;
        }
        *(float4*)&g_cpart[(size_t)blk*NQ + col] = make_float4(s0, s1, s2, s3);
        __threadfence();
        __syncthreads();
        if (tid == 0) {
            atomicAdd(&g_bar8[bb], 1u);
            unsigned int target = (unsigned int)it * 16u;
            while (atomicAdd(&g_bar8[bb], 0u) < target) __nanosleep(64);
        }
        __syncthreads();
        __threadfence();
        if (it < NITER) {
            float c0=0, c1=0, c2=0, c3=0;
            #pragma unroll
            for (int w = 0; w < 16; w++) {
                float4 v = *(const float4*)&g_cpart[(size_t)(bb*16 + w)*NQ + col];
                c0 += v.x; c1 += v.y; c2 += v.z; c3 += v.w;
            }
            sh[col+0] = NU_P / c0; sh[col+1] = NU_P / c1;
            sh[col+2] = NU_P / c2; sh[col+3] = NU_P / c3;
            __syncthreads();
            #pragma unroll
            for (int g = 0; g < 8; g++) {
                float4 v = *(const float4*)&sh[g*128 + lane*4];
                bv[g*4+0]=v.x; bv[g*4+1]=v.y; bv[g*4+2]=v.z; bv[g*4+3]=v.w;
            }
            __syncthreads();
        }
    }
    if (rb == 0) {
        float c0=0, c1=0, c2=0, c3=0;
        #pragma unroll
        for (int w = 0; w < 16; w++) {
            float4 v = *(const float4*)&g_cpart[(size_t)(bb*16 + w)*NQ + col];
            c0 += v.x; c1 += v.y; c2 += v.z; c3 += v.w;
        }
        g_bfin[bb*NQ+col+0] = NU_P / c0; g_bfin[bb*NQ+col+1] = NU_P / c1;
        g_bfin[bb*NQ+col+2] = NU_P / c2; g_bfin[bb*NQ+col+3] = NU_P / c3;
    }
}

__global__ void k_attn(float* outp) {
    const int warp = threadIdx.x >> 5, lane = threadIdx.x & 31;
    int r = blockIdx.x * 8 + warp;
    if (r >= RR) return;
    int bb = r >> 10;
    float val = 0.0f;
    if (g_maskb[r]) {
        const float* S = g_sim + (size_t)r * NQ;
        const float* E = g_E + (size_t)r * NQ;
        const float* bf = g_bfin + bb * NQ;
        float s = 0.0f;
        #pragma unroll
        for (int g = 0; g < 8; g++) {
            int n = g*128 + lane*4;
            float4 sv = *(const float4*)(S + n);
            float4 ev = *(const float4*)(E + n);
            float4 bv = *(const float4*)(bf + n);
            s += sv.x*ev.x*bv.x + sv.y*ev.y*bv.y + sv.z*ev.z*bv.z + sv.w*ev.w*bv.w;
        }
        #pragma unroll
        for (int o = 16; o; o >>= 1) s += __shfl_xor_sync(0xffffffffu, s, o);
        val = 1048576.0f * g_a[r] * s;
    }
    if (lane == 0) outp[r] = val;
}

extern "C" void kernel_launch(void* const* d_in, const int* in_sizes, int n_in,
                              void* d_out, int out_size) {
    const float* xq = (const float*)d_in[0];
    const float* xk = (const float*)d_in[1];
    const float* xv = (const float*)d_in[2];
    const void*  mk = d_in[3];
    const float* Wq = (const float*)d_in[4];
    const float* bq = (const float*)d_in[5];
    const float* Wk = (const float*)d_in[6];
    const float* bk = (const float*)d_in[7];
    const float* Wv = (const float*)d_in[8];
    const float* bv = (const float*)d_in[9];
    const float* Wp = (const float*)d_in[10];
    const float* bp = (const float*)d_in[11];
    float *qp, *kp, *vp, *xp;
    __nv_bfloat16 *q0, *q1, *ks0, *ks1;
    cudaGetSymbolAddress((void**)&qp, g_q);
    cudaGetSymbolAddress((void**)&kp, g_k);
    cudaGetSymbolAddress((void**)&vp, g_v);
    cudaGetSymbolAddress((void**)&xp, g_x);
    cudaGetSymbolAddress((void**)&q0, g_qs0);
    cudaGetSymbolAddress((void**)&q1, g_qs1);
    cudaGetSymbolAddress((void**)&ks0, g_ks0);
    cudaGetSymbolAddress((void**)&ks1, g_ks1);

    k_detect<<<1, 256>>>((const unsigned char*)mk);
    k_counts<<<NB, 256>>>(mk);
    k_init<<<(RR + 255)/256, 256>>>(mk);

    dim3 gmm(RR/128, CC/128);

    k_gemm_mma<<<gmm, 256>>>(xq, Wq, bq, qp);
    k_gemm_mma<<<gmm, 256>>>(xk, Wk, bk, kp);
    k_gemm_mma<<<gmm, 256>>>(xv, Wv, bv, vp);

    k_l2split<<<RR, 256>>>(qp, q0, q1);
    k_l2split<<<RR, 256>>>(kp, ks0, ks1);

    k_simE_mma<<<dim3(MM/128, NQ/128, NB), 256>>>();

    k_sink_pers<<<128, 256>>>();

    k_xgemm_mma<<<dim3(NQ/128, CC/128, NB), 256>>>();

    k_gemm_mma<<<gmm, 256>>>(xp, Wp, bp, (float*)d_out);

    if (out_size >= RR*CC + RR)
        k_attn<<<RR/8, 256>>>((float*)d_out + (size_t)RR*CC);
}

// round 11
// speedup vs baseline: 1.7496x; 1.0144x over previous
#include <cuda_runtime.h>
#include <cuda_bf16.h>
#include <math.h>
#include <stdint.h>

#define NQ 1024
#define NB 8
#define MM 1024
#define CC 640
#define RR 8192
#define NITER 100
#define EPS_INV 20.0f
#define NU_P (1.0f/1024.0f + 1e-8f)

__device__ float g_q[RR*CC];
__device__ float g_k[RR*CC];
__device__ float g_v[RR*CC];
__device__ float g_x[RR*CC];
__device__ float g_sim[NB*MM*NQ];
__device__ float g_E[NB*MM*NQ];
__device__ __nv_bfloat16 g_Ebf[NB*MM*NQ];
__device__ float g_cpart[128*NQ];
__device__ float g_a[RR];
__device__ float g_mu[RR];
__device__ float g_bfin[RR];
__device__ unsigned char g_maskb[RR];
__device__ int g_counts[NB];
__device__ int g_mfmt;
__device__ unsigned int g_bar8[NB];
__device__ __nv_bfloat16 g_qs0[RR*CC];
__device__ __nv_bfloat16 g_qs1[RR*CC];
__device__ __nv_bfloat16 g_ks0[RR*CC];
__device__ __nv_bfloat16 g_ks1[RR*CC];

__device__ __forceinline__ int getmask_raw(const void* m, int idx, int fmt) {
    if (fmt == 1) return ((const int*)m)[idx] != 0;
    if (fmt == 2) return ((const float*)m)[idx] != 0.0f;
    return ((const unsigned char*)m)[idx] != 0;
}

__global__ void k_detect(const unsigned char* m) {
    __shared__ int cA, cB;
    if (threadIdx.x == 0) { cA = 0; cB = 0; }
    __syncthreads();
    int a = 0, b = 0;
    for (int i = threadIdx.x; i < RR; i += blockDim.x) {
        if (m[i] != 0) { if ((i & 3) == 0) a = 1; else b = 1; }
    }
    if (a) atomicOr(&cA, 1);
    if (b) atomicOr(&cB, 1);
    __syncthreads();
    if (threadIdx.x == 0) g_mfmt = (cB == 0) ? 1 : ((cA == 0) ? 2 : 0);
}

__global__ void k_counts(const void* mask) {
    __shared__ int sh[256];
    int fmt = g_mfmt, bb = blockIdx.x, s = 0;
    for (int m = threadIdx.x; m < MM; m += 256) s += getmask_raw(mask, bb*MM + m, fmt);
    sh[threadIdx.x] = s; __syncthreads();
    for (int o = 128; o; o >>= 1) { if (threadIdx.x < o) sh[threadIdx.x] += sh[threadIdx.x + o]; __syncthreads(); }
    if (threadIdx.x == 0) g_counts[bb] = (sh[0] > 0) ? sh[0] : 1;
}

__global__ void k_init(const void* mask) {
    int idx = blockIdx.x * blockDim.x + threadIdx.x;
    if (idx < NB) g_bar8[idx] = 0u;
    if (idx < RR) {
        int fmt = g_mfmt;
        int mk = getmask_raw(mask, idx, fmt);
        g_maskb[idx] = (unsigned char)mk;
        g_mu[idx] = mk ? (1.0f/(float)g_counts[idx >> 10] + 1e-8f) : 0.0f;
    }
}

__global__ void k_l2split(const float* __restrict__ src,
                          __nv_bfloat16* __restrict__ d0,
                          __nv_bfloat16* __restrict__ d1) {
    __shared__ float sh[256];
    const float* row = src + (size_t)blockIdx.x * CC;
    float s = 0.0f;
    for (int i = threadIdx.x; i < CC; i += 256) { float v = row[i]; s += v*v; }
    sh[threadIdx.x] = s; __syncthreads();
    for (int o = 128; o; o >>= 1) { if (threadIdx.x < o) sh[threadIdx.x] += sh[threadIdx.x + o]; __syncthreads(); }
    float inv = 1.0f / fmaxf(sqrtf(sh[0]), 1e-12f);
    size_t base = (size_t)blockIdx.x * CC;
    for (int i = threadIdx.x; i < CC; i += 256) {
        float x = row[i] * inv;
        __nv_bfloat16 b0 = __float2bfloat16(x);
        float r = x - __bfloat162float(b0);
        d0[base + i] = b0; d1[base + i] = __float2bfloat16(r);
    }
}

__device__ __forceinline__ void split8_store(float4 v0, float4 v1,
                                             __nv_bfloat16* dhi, __nv_bfloat16* dlo) {
    float f[8] = {v0.x, v0.y, v0.z, v0.w, v1.x, v1.y, v1.z, v1.w};
    uint32_t hw[4], lw[4];
    #pragma unroll
    for (int i = 0; i < 4; i++) {
        __nv_bfloat16 h0 = __float2bfloat16(f[2*i]);
        __nv_bfloat16 h1 = __float2bfloat16(f[2*i+1]);
        __nv_bfloat162 hp = __halves2bfloat162(h0, h1);
        hw[i] = *(uint32_t*)&hp;
        __nv_bfloat16 l0 = __float2bfloat16(f[2*i]   - __bfloat162float(h0));
        __nv_bfloat16 l1 = __float2bfloat16(f[2*i+1] - __bfloat162float(h1));
        __nv_bfloat162 lp = __halves2bfloat162(l0, l1);
        lw[i] = *(uint32_t*)&lp;
    }
    *(uint4*)dhi = make_uint4(hw[0], hw[1], hw[2], hw[3]);
    *(uint4*)dlo = make_uint4(lw[0], lw[1], lw[2], lw[3]);
}

// dynamic-smem layout for chunk-64 kernels: stride 72 bf16, 128 rows, 2 splits, A then B
#define DSTRIDE 72
#define DMAT (128*DSTRIDE)
#define ASD(s,r,c) dyn[(s)*DMAT + (r)*DSTRIDE + (c)]
#define BSD(s,r,c) dyn[2*DMAT + (s)*DMAT + (r)*DSTRIDE + (c)]
#define DYN_BYTES (4*DMAT*2)

#define MMA_FRAGS_D \
    uint32_t af[2][4][4], bfr[2][4][2]; \
    _Pragma("unroll") \
    for (int s = 0; s < 2; s++) { \
        _Pragma("unroll") \
        for (int mi = 0; mi < 4; mi++) { \
            int r0 = wm + mi*16 + g; \
            af[s][mi][0] = *(const uint32_t*)&ASD(s, r0,   kk + tg*2); \
            af[s][mi][1] = *(const uint32_t*)&ASD(s, r0+8, kk + tg*2); \
            af[s][mi][2] = *(const uint32_t*)&ASD(s, r0,   kk + tg*2 + 8); \
            af[s][mi][3] = *(const uint32_t*)&ASD(s, r0+8, kk + tg*2 + 8); \
        } \
        _Pragma("unroll") \
        for (int ni = 0; ni < 4; ni++) { \
            int c0 = wn + ni*8 + g; \
            bfr[s][ni][0] = *(const uint32_t*)&BSD(s, c0, kk + tg*2); \
            bfr[s][ni][1] = *(const uint32_t*)&BSD(s, c0, kk + tg*2 + 8); \
        } \
    } \
    _Pragma("unroll") \
    for (int p = 0; p < 3; p++) { \
        const int sa = (p == 2) ? 1 : 0, sb = (p == 1) ? 1 : 0; \
        _Pragma("unroll") \
        for (int mi = 0; mi < 4; mi++) \
            _Pragma("unroll") \
            for (int ni = 0; ni < 4; ni++) \
                asm volatile( \
                    "mma.sync.aligned.m16n8k16.row.col.f32.bf16.bf16.f32 " \
                    "{%0,%1,%2,%3}, {%4,%5,%6,%7}, {%8,%9}, {%0,%1,%2,%3};" \
                    : "+f"(acc[mi][ni][0]), "+f"(acc[mi][ni][1]), \
                      "+f"(acc[mi][ni][2]), "+f"(acc[mi][ni][3]) \
                    : "r"(af[sa][mi][0]), "r"(af[sa][mi][1]), \
                      "r"(af[sa][mi][2]), "r"(af[sa][mi][3]), \
                      "r"(bfr[sb][ni][0]), "r"(bfr[sb][ni][1])); \
    }

// NT GEMM body (chunk 64, fp32 in, split fused): C[r][j] = sum_t A[r][t]B[j][t] + bias[j]
__device__ __forceinline__ void gemm_body(const float* __restrict__ A,
                                          const float* __restrict__ B,
                                          const float* __restrict__ bias,
                                          float* __restrict__ Co,
                                          __nv_bfloat16* dyn) {
    const int tid = threadIdx.x, warp = tid >> 5, lane = tid & 31;
    const int g = lane >> 2, tg = lane & 3;
    const int i0 = blockIdx.x * 128, j0 = blockIdx.y * 128;
    const int wm = (warp & 1) * 64, wn = (warp >> 1) * 32;
    float acc[4][4][4];
    #pragma unroll
    for (int mi = 0; mi < 4; mi++)
        #pragma unroll
        for (int ni = 0; ni < 4; ni++)
            #pragma unroll
            for (int e = 0; e < 4; e++) acc[mi][ni][e] = 0.0f;
    const int lrow = tid >> 1, half = tid & 1;
    for (int k0 = 0; k0 < CC; k0 += 64) {
        #pragma unroll
        for (int u = 0; u < 4; u++) {
            int seg = half*4 + u;
            const float* pa = A + (size_t)(i0+lrow)*CC + k0 + seg*8;
            const float* pb = B + (size_t)(j0+lrow)*CC + k0 + seg*8;
            float4 a0 = *(const float4*)pa, a1 = *(const float4*)(pa+4);
            float4 b0 = *(const float4*)pb, b1 = *(const float4*)(pb+4);
            split8_store(a0, a1, &ASD(0, lrow, seg*8), &ASD(1, lrow, seg*8));
            split8_store(b0, b1, &BSD(0, lrow, seg*8), &BSD(1, lrow, seg*8));
        }
        __syncthreads();
        #pragma unroll
        for (int kk = 0; kk < 64; kk += 16) { MMA_FRAGS_D }
        __syncthreads();
    }
    #pragma unroll
    for (int mi = 0; mi < 4; mi++) {
        int r0 = i0 + wm + mi*16 + g;
        #pragma unroll
        for (int ni = 0; ni < 4; ni++) {
            int c = j0 + wn + ni*8 + tg*2;
            float b0v = bias[c], b1v = bias[c+1];
            Co[(size_t)r0*CC + c]       = acc[mi][ni][0] + b0v;
            Co[(size_t)r0*CC + c+1]     = acc[mi][ni][1] + b1v;
            Co[(size_t)(r0+8)*CC + c]   = acc[mi][ni][2] + b0v;
            Co[(size_t)(r0+8)*CC + c+1] = acc[mi][ni][3] + b1v;
        }
    }
}

// 3 projection GEMMs in one launch (z selects q/k/v)
__global__ __launch_bounds__(256) void k_gemm3(
    const float* xq, const float* Wq, const float* bq, float* oq,
    const float* xk, const float* Wk, const float* bk, float* ok,
    const float* xv, const float* Wv, const float* bv, float* ov) {
    extern __shared__ __nv_bfloat16 dyn[];
    if (blockIdx.z == 0)      gemm_body(xq, Wq, bq, oq, dyn);
    else if (blockIdx.z == 1) gemm_body(xk, Wk, bk, ok, dyn);
    else                      gemm_body(xv, Wv, bv, ov, dyn);
}

__global__ __launch_bounds__(256) void k_gemm1(
    const float* A, const float* B, const float* bias, float* Co) {
    extern __shared__ __nv_bfloat16 dyn[];
    gemm_body(A, B, bias, Co, dyn);
}

// HMMA simE (chunk 64): sim = k.q; E = mask ? exp((sim-1)*20) : 0 (fp32 + bf16 copies)
__global__ __launch_bounds__(256) void k_simE_mma() {
    extern __shared__ __nv_bfloat16 dyn[];
    const int tid = threadIdx.x, warp = tid >> 5, lane = tid & 31;
    const int g = lane >> 2, tg = lane & 3;
    const int bb = blockIdx.z, m0 = blockIdx.x * 128, n0 = blockIdx.y * 128;
    const int wm = (warp & 1) * 64, wn = (warp >> 1) * 32;
    float acc[4][4][4];
    #pragma unroll
    for (int mi = 0; mi < 4; mi++)
        #pragma unroll
        for (int ni = 0; ni < 4; ni++)
            #pragma unroll
            for (int e = 0; e < 4; e++) acc[mi][ni][e] = 0.0f;
    const int lrow = tid >> 1, half = tid & 1;
    const size_t abase = (size_t)(bb*MM + m0);
    for (int k0 = 0; k0 < CC; k0 += 64) {
        #pragma unroll
        for (int u = 0; u < 4; u++) {
            int seg = half*4 + u;
            *(uint4*)&ASD(0, lrow, seg*8) = *(const uint4*)(g_ks0 + (abase + lrow)*CC + k0 + seg*8);
            *(uint4*)&ASD(1, lrow, seg*8) = *(const uint4*)(g_ks1 + (abase + lrow)*CC + k0 + seg*8);
            size_t qrow = (size_t)(n0 + lrow)*NB + bb;
            *(uint4*)&BSD(0, lrow, seg*8) = *(const uint4*)(g_qs0 + qrow*CC + k0 + seg*8);
            *(uint4*)&BSD(1, lrow, seg*8) = *(const uint4*)(g_qs1 + qrow*CC + k0 + seg*8);
        }
        __syncthreads();
        #pragma unroll
        for (int kk = 0; kk < 64; kk += 16) { MMA_FRAGS_D }
        __syncthreads();
    }
    #pragma unroll
    for (int mi = 0; mi < 4; mi++) {
        int mA = m0 + wm + mi*16 + g;
        int mB = mA + 8;
        int mkA = g_maskb[bb*MM + mA], mkB = g_maskb[bb*MM + mB];
        size_t baseA = ((size_t)bb*MM + mA) * NQ;
        size_t baseB = ((size_t)bb*MM + mB) * NQ;
        #pragma unroll
        for (int ni = 0; ni < 4; ni++) {
            int c = n0 + wn + ni*8 + tg*2;
            float s0 = acc[mi][ni][0], s1 = acc[mi][ni][1];
            float s2 = acc[mi][ni][2], s3 = acc[mi][ni][3];
            g_sim[baseA + c]   = s0; g_sim[baseA + c+1] = s1;
            g_sim[baseB + c]   = s2; g_sim[baseB + c+1] = s3;
            float e0 = mkA ? expf((s0 - 1.0f) * EPS_INV) : 0.0f;
            float e1 = mkA ? expf((s1 - 1.0f) * EPS_INV) : 0.0f;
            float e2 = mkB ? expf((s2 - 1.0f) * EPS_INV) : 0.0f;
            float e3 = mkB ? expf((s3 - 1.0f) * EPS_INV) : 0.0f;
            g_E[baseA + c]   = e0; g_E[baseA + c+1] = e1;
            g_E[baseB + c]   = e2; g_E[baseB + c+1] = e3;
            g_Ebf[baseA + c]   = __float2bfloat16(e0);
            g_Ebf[baseA + c+1] = __float2bfloat16(e1);
            g_Ebf[baseB + c]   = __float2bfloat16(e2);
            g_Ebf[baseB + c+1] = __float2bfloat16(e3);
        }
    }
}

// HMMA TN xgemm (static smem, chunk 32, as validated in R8/R9)
#define SPAD 40
#define MMA_FRAGS_S \
    uint32_t af[2][4][4], bfr[2][4][2]; \
    _Pragma("unroll") \
    for (int s = 0; s < 2; s++) { \
        _Pragma("unroll") \
        for (int mi = 0; mi < 4; mi++) { \
            int r0 = wm + mi*16 + g; \
            af[s][mi][0] = *(const uint32_t*)&As[s][r0][kk + tg*2]; \
            af[s][mi][1] = *(const uint32_t*)&As[s][r0+8][kk + tg*2]; \
            af[s][mi][2] = *(const uint32_t*)&As[s][r0][kk + tg*2 + 8]; \
            af[s][mi][3] = *(const uint32_t*)&As[s][r0+8][kk + tg*2 + 8]; \
        } \
        _Pragma("unroll") \
        for (int ni = 0; ni < 4; ni++) { \
            int c0 = wn + ni*8 + g; \
            bfr[s][ni][0] = *(const uint32_t*)&Bs[s][c0][kk + tg*2]; \
            bfr[s][ni][1] = *(const uint32_t*)&Bs[s][c0][kk + tg*2 + 8]; \
        } \
    } \
    _Pragma("unroll") \
    for (int p = 0; p < 3; p++) { \
        const int sa = (p == 2) ? 1 : 0, sb = (p == 1) ? 1 : 0; \
        _Pragma("unroll") \
        for (int mi = 0; mi < 4; mi++) \
            _Pragma("unroll") \
            for (int ni = 0; ni < 4; ni++) \
                asm volatile( \
                    "mma.sync.aligned.m16n8k16.row.col.f32.bf16.bf16.f32 " \
                    "{%0,%1,%2,%3}, {%4,%5,%6,%7}, {%8,%9}, {%0,%1,%2,%3};" \
                    : "+f"(acc[mi][ni][0]), "+f"(acc[mi][ni][1]), \
                      "+f"(acc[mi][ni][2]), "+f"(acc[mi][ni][3]) \
                    : "r"(af[sa][mi][0]), "r"(af[sa][mi][1]), \
                      "r"(af[sa][mi][2]), "r"(af[sa][mi][3]), \
                      "r"(bfr[sb][ni][0]), "r"(bfr[sb][ni][1])); \
    }

__global__ __launch_bounds__(256) void k_xgemm_mma() {
    __shared__ __nv_bfloat16 As[2][128][SPAD];
    __shared__ __nv_bfloat16 Bs[2][128][SPAD];
    const int tid = threadIdx.x, warp = tid >> 5, lane = tid & 31;
    const int g = lane >> 2, tg = lane & 3;
    const int bb = blockIdx.z, n0 = blockIdx.x * 128, c0 = blockIdx.y * 128;
    const int wm = (warp & 1) * 64, wn = (warp >> 1) * 32;
    float acc[4][4][4];
    #pragma unroll
    for (int mi = 0; mi < 4; mi++)
        #pragma unroll
        for (int ni = 0; ni < 4; ni++)
            #pragma unroll
            for (int e = 0; e < 4; e++) acc[mi][ni][e] = 0.0f;
    const float* Eb = g_E + (size_t)bb*MM*NQ;
    const float* Vb = g_v + (size_t)bb*MM*CC;
    const int lm = tid & 31, lg = tid >> 5;
    for (int k0 = 0; k0 < MM; k0 += 32) {
        int m = k0 + lm;
        float am = g_a[bb*MM + m];
        #pragma unroll
        for (int j = 0; j < 4; j++) {
            int n = lg*16 + j*4;
            float4 ev = *(const float4*)(Eb + (size_t)m*NQ + n0 + n);
            float4 vv = *(const float4*)(Vb + (size_t)m*CC + c0 + n);
            vv.x *= am; vv.y *= am; vv.z *= am; vv.w *= am;
            float ee[4] = {ev.x, ev.y, ev.z, ev.w};
            float va[4] = {vv.x, vv.y, vv.z, vv.w};
            #pragma unroll
            for (int q = 0; q < 4; q++) {
                __nv_bfloat16 h = __float2bfloat16(ee[q]);
                As[0][n + q][lm] = h;
                As[1][n + q][lm] = __float2bfloat16(ee[q] - __bfloat162float(h));
                __nv_bfloat16 hv = __float2bfloat16(va[q]);
                Bs[0][n + q][lm] = hv;
                Bs[1][n + q][lm] = __float2bfloat16(va[q] - __bfloat162float(hv));
            }
        }
        __syncthreads();
        #pragma unroll
        for (int kk = 0; kk < 32; kk += 16) { MMA_FRAGS_S }
        __syncthreads();
    }
    #pragma unroll
    for (int mi = 0; mi < 4; mi++) {
        int nA = n0 + wm + mi*16 + g;
        int nB = nA + 8;
        float bnA = g_bfin[bb*NQ + nA], bnB = g_bfin[bb*NQ + nB];
        #pragma unroll
        for (int ni = 0; ni < 4; ni++) {
            int c = c0 + wn + ni*8 + tg*2;
            g_x[((size_t)nA*NB + bb)*CC + c]   = acc[mi][ni][0] * bnA;
            g_x[((size_t)nA*NB + bb)*CC + c+1] = acc[mi][ni][1] * bnA;
            g_x[((size_t)nB*NB + bb)*CC + c]   = acc[mi][ni][2] * bnB;
            g_x[((size_t)nB*NB + bb)*CC + c+1] = acc[mi][ni][3] * bnB;
        }
    }
}

// persistent Sinkhorn with smem-resident bf16 E (64 rows = 128KB) + 32KB reduce buffer
#define SINK_SMEM (64*NQ*2 + 8*NQ*4)
__global__ __launch_bounds__(256) void k_sink_pers() {
    extern __shared__ char dsm[];
    __nv_bfloat16* Es = (__nv_bfloat16*)dsm;
    float* shred = (float*)(dsm + 64*NQ*2);
    const int blk = blockIdx.x, bb = blk >> 4, rb = blk & 15;
    const int tid = threadIdx.x, warp = tid >> 5, lane = tid & 31;
    const int col = tid * 4;
    // load my 64 E rows into smem (flat copy)
    {
        const uint4* src = (const uint4*)(g_Ebf + ((size_t)bb*MM + rb*64) * NQ);
        uint4* dst = (uint4*)Es;
        for (int i = tid; i < 64*NQ/8; i += 256) dst[i] = src[i];
    }
    __syncthreads();
    float bv[32];
    #pragma unroll
    for (int q = 0; q < 32; q++) bv[q] = 1.0f;
    for (int it = 1; it <= NITER; it++) {
        float cacc[32];
        #pragma unroll
        for (int q = 0; q < 32; q++) cacc[q] = 0.0f;
        #pragma unroll
        for (int rr = 0; rr < 8; rr++) {
            int lr = warp*8 + rr;              // local row 0..63
            int m = rb*64 + lr;                // row within batch
            if (!g_maskb[bb*MM + m]) {
                if (it == NITER && lane == 0) g_a[bb*MM + m] = 0.0f;
                continue;
            }
            const __nv_bfloat16* er = Es + (size_t)lr * NQ;
            float e[32], s = 0.0f;
            #pragma unroll
            for (int g = 0; g < 8; g++) {
                uint2 w = *(const uint2*)(er + g*128 + lane*4);
                __nv_bfloat162 p0 = *(__nv_bfloat162*)&w.x;
                __nv_bfloat162 p1 = *(__nv_bfloat162*)&w.y;
                e[g*4+0] = __bfloat162float(__low2bfloat16(p0));
                e[g*4+1] = __bfloat162float(__high2bfloat16(p0));
                e[g*4+2] = __bfloat162float(__low2bfloat16(p1));
                e[g*4+3] = __bfloat162float(__high2bfloat16(p1));
                s += e[g*4+0]*bv[g*4+0] + e[g*4+1]*bv[g*4+1]
                   + e[g*4+2]*bv[g*4+2] + e[g*4+3]*bv[g*4+3];
            }
            #pragma unroll
            for (int o = 16; o; o >>= 1) s += __shfl_xor_sync(0xffffffffu, s, o);
            float a = g_mu[bb*MM + m] / s;
            if (it == NITER && lane == 0) g_a[bb*MM + m] = a;
            #pragma unroll
            for (int q = 0; q < 32; q++) cacc[q] += a * e[q];
        }
        #pragma unroll
        for (int g = 0; g < 8; g++)
            *(float4*)&shred[warp*1024 + g*128 + lane*4] =
                make_float4(cacc[g*4], cacc[g*4+1], cacc[g*4+2], cacc[g*4+3]);
        __syncthreads();
        float s0=0, s1=0, s2=0, s3=0;
        #pragma unroll
        for (int w = 0; w < 8; w++) {
            float4 v = *(const float4*)&shred[w*1024 + col];
            s0 += v.x; s1 += v.y; s2 += v.z; s3 += v.w;
        }
        *(float4*)&g_cpart[(size_t)blk*NQ + col] = make_float4(s0, s1, s2, s3);
        __threadfence();
        __syncthreads();
        if (tid == 0) {
            atomicAdd(&g_bar8[bb], 1u);
            unsigned int target = (unsigned int)it * 16u;
            while (atomicAdd(&g_bar8[bb], 0u) < target) __nanosleep(64);
        }
        __syncthreads();
        __threadfence();
        if (it < NITER) {
            float c0=0, c1=0, c2=0, c3=0;
            #pragma unroll
            for (int w = 0; w < 16; w++) {
                float4 v = *(const float4*)&g_cpart[(size_t)(bb*16 + w)*NQ + col];
                c0 += v.x; c1 += v.y; c2 += v.z; c3 += v.w;
            }
            shred[col+0] = NU_P / c0; shred[col+1] = NU_P / c1;
            shred[col+2] = NU_P / c2; shred[col+3] = NU_P / c3;
            __syncthreads();
            #pragma unroll
            for (int g = 0; g < 8; g++) {
                float4 v = *(const float4*)&shred[g*128 + lane*4];
                bv[g*4+0]=v.x; bv[g*4+1]=v.y; bv[g*4+2]=v.z; bv[g*4+3]=v.w;
            }
            __syncthreads();
        }
    }
    if (rb == 0) {
        float c0=0, c1=0, c2=0, c3=0;
        #pragma unroll
        for (int w = 0; w < 16; w++) {
            float4 v = *(const float4*)&g_cpart[(size_t)(bb*16 + w)*NQ + col];
            c0 += v.x; c1 += v.y; c2 += v.z; c3 += v.w;
        }
        g_bfin[bb*NQ+col+0] = NU_P / c0; g_bfin[bb*NQ+col+1] = NU_P / c1;
        g_bfin[bb*NQ+col+2] = NU_P / c2; g_bfin[bb*NQ+col+3] = NU_P / c3;
    }
}

__global__ void k_attn(float* outp) {
    const int warp = threadIdx.x >> 5, lane = threadIdx.x & 31;
    int r = blockIdx.x * 8 + warp;
    if (r >= RR) return;
    int bb = r >> 10;
    float val = 0.0f;
    if (g_maskb[r]) {
        const float* S = g_sim + (size_t)r * NQ;
        const float* E = g_E + (size_t)r * NQ;
        const float* bf = g_bfin + bb * NQ;
        float s = 0.0f;
        #pragma unroll
        for (int g = 0; g < 8; g++) {
            int n = g*128 + lane*4;
            float4 sv = *(const float4*)(S + n);
            float4 ev = *(const float4*)(E + n);
            float4 bv = *(const float4*)(bf + n);
            s += sv.x*ev.x*bv.x + sv.y*ev.y*bv.y + sv.z*ev.z*bv.z + sv.w*ev.w*bv.w;
        }
        #pragma unroll
        for (int o = 16; o; o >>= 1) s += __shfl_xor_sync(0xffffffffu, s, o);
        val = 1048576.0f * g_a[r] * s;
    }
    if (lane == 0) outp[r] = val;
}

extern "C" void kernel_launch(void* const* d_in, const int* in_sizes, int n_in,
                              void* d_out, int out_size) {
    const float* xq = (const float*)d_in[0];
    const float* xk = (const float*)d_in[1];
    const float* xv = (const float*)d_in[2];
    const void*  mk = d_in[3];
    const float* Wq = (const float*)d_in[4];
    const float* bq = (const float*)d_in[5];
    const float* Wk = (const float*)d_in[6];
    const float* bk = (const float*)d_in[7];
    const float* Wv = (const float*)d_in[8];
    const float* bv = (const float*)d_in[9];
    const float* Wp = (const float*)d_in[10];
    const float* bp = (const float*)d_in[11];
    float *qp, *kp, *vp, *xp;
    __nv_bfloat16 *q0, *q1, *ks0, *ks1;
    cudaGetSymbolAddress((void**)&qp, g_q);
    cudaGetSymbolAddress((void**)&kp, g_k);
    cudaGetSymbolAddress((void**)&vp, g_v);
    cudaGetSymbolAddress((void**)&xp, g_x);
    cudaGetSymbolAddress((void**)&q0, g_qs0);
    cudaGetSymbolAddress((void**)&q1, g_qs1);
    cudaGetSymbolAddress((void**)&ks0, g_ks0);
    cudaGetSymbolAddress((void**)&ks1, g_ks1);
    cudaFuncSetAttribute(k_gemm3, cudaFuncAttributeMaxDynamicSharedMemorySize, DYN_BYTES);
    cudaFuncSetAttribute(k_gemm1, cudaFuncAttributeMaxDynamicSharedMemorySize, DYN_BYTES);
    cudaFuncSetAttribute(k_simE_mma, cudaFuncAttributeMaxDynamicSharedMemorySize, DYN_BYTES);
    cudaFuncSetAttribute(k_sink_pers, cudaFuncAttributeMaxDynamicSharedMemorySize, SINK_SMEM);

    k_detect<<<1, 256>>>((const unsigned char*)mk);
    k_counts<<<NB, 256>>>(mk);
    k_init<<<(RR + 255)/256, 256>>>(mk);

    k_gemm3<<<dim3(RR/128, CC/128, 3), 256, DYN_BYTES>>>(
        xq, Wq, bq, qp, xk, Wk, bk, kp, xv, Wv, bv, vp);

    k_l2split<<<RR, 256>>>(qp, q0, q1);
    k_l2split<<<RR, 256>>>(kp, ks0, ks1);

    k_simE_mma<<<dim3(MM/128, NQ/128, NB), 256, DYN_BYTES>>>();

    k_sink_pers<<<128, 256, SINK_SMEM>>>();

    k_xgemm_mma<<<dim3(NQ/128, CC/128, NB), 256>>>();

    k_gemm1<<<dim3(RR/128, CC/128), 256, DYN_BYTES>>>(xp, Wp, bp, (float*)d_out);

    if (out_size >= RR*CC + RR)
        k_attn<<<RR/8, 256>>>((float*)d_out + (size_t)RR*CC);
}

// round 13
// speedup vs baseline: 1.8722x; 1.0701x over previous
#include <cuda_runtime.h>
#include <cuda_bf16.h>
#include <math.h>
#include <stdint.h>

#define NQ 1024
#define NB 8
#define MM 1024
#define CC 640
#define RR 8192
#define NITER 100
#define EPS_INV 20.0f
#define NU_P (1.0f/1024.0f + 1e-8f)

__device__ float g_q[RR*CC];
__device__ float g_k[RR*CC];
__device__ float g_v[RR*CC];
__device__ float g_x[RR*CC];
__device__ float g_sim[NB*MM*NQ];
__device__ float g_E[NB*MM*NQ];
__device__ __nv_bfloat16 g_Ebf[NB*MM*NQ];
__device__ float g_cpart[128*NQ];
__device__ float g_a[RR];
__device__ float g_mu[RR];
__device__ float g_bfin[RR];
__device__ unsigned char g_maskb[RR];
__device__ int g_counts[NB];
__device__ int g_mfmt;
__device__ unsigned int g_bar8[NB];
__device__ __nv_bfloat16 g_qs0[RR*CC];
__device__ __nv_bfloat16 g_qs1[RR*CC];
__device__ __nv_bfloat16 g_ks0[RR*CC];
__device__ __nv_bfloat16 g_ks1[RR*CC];

__device__ __forceinline__ int getmask_raw(const void* m, int idx, int fmt) {
    if (fmt == 1) return ((const int*)m)[idx] != 0;
    if (fmt == 2) return ((const float*)m)[idx] != 0.0f;
    return ((const unsigned char*)m)[idx] != 0;
}

__global__ void k_detect(const unsigned char* m) {
    __shared__ int cA, cB;
    if (threadIdx.x == 0) { cA = 0; cB = 0; }
    __syncthreads();
    int a = 0, b = 0;
    for (int i = threadIdx.x; i < RR; i += blockDim.x) {
        if (m[i] != 0) { if ((i & 3) == 0) a = 1; else b = 1; }
    }
    if (a) atomicOr(&cA, 1);
    if (b) atomicOr(&cB, 1);
    __syncthreads();
    if (threadIdx.x == 0) g_mfmt = (cB == 0) ? 1 : ((cA == 0) ? 2 : 0);
}

__global__ void k_counts(const void* mask) {
    __shared__ int sh[256];
    int fmt = g_mfmt, bb = blockIdx.x, s = 0;
    for (int m = threadIdx.x; m < MM; m += 256) s += getmask_raw(mask, bb*MM + m, fmt);
    sh[threadIdx.x] = s; __syncthreads();
    for (int o = 128; o; o >>= 1) { if (threadIdx.x < o) sh[threadIdx.x] += sh[threadIdx.x + o]; __syncthreads(); }
    if (threadIdx.x == 0) g_counts[bb] = (sh[0] > 0) ? sh[0] : 1;
}

__global__ void k_init(const void* mask) {
    int idx = blockIdx.x * blockDim.x + threadIdx.x;
    if (idx < NB) g_bar8[idx] = 0u;
    if (idx < RR) {
        int fmt = g_mfmt;
        int mk = getmask_raw(mask, idx, fmt);
        g_maskb[idx] = (unsigned char)mk;
        g_mu[idx] = mk ? (1.0f/(float)g_counts[idx >> 10] + 1e-8f) : 0.0f;
    }
}

__global__ void k_l2split(const float* __restrict__ src,
                          __nv_bfloat16* __restrict__ d0,
                          __nv_bfloat16* __restrict__ d1) {
    __shared__ float sh[256];
    const float* row = src + (size_t)blockIdx.x * CC;
    float s = 0.0f;
    for (int i = threadIdx.x; i < CC; i += 256) { float v = row[i]; s += v*v; }
    sh[threadIdx.x] = s; __syncthreads();
    for (int o = 128; o; o >>= 1) { if (threadIdx.x < o) sh[threadIdx.x] += sh[threadIdx.x + o]; __syncthreads(); }
    float inv = 1.0f / fmaxf(sqrtf(sh[0]), 1e-12f);
    size_t base = (size_t)blockIdx.x * CC;
    for (int i = threadIdx.x; i < CC; i += 256) {
        float x = row[i] * inv;
        __nv_bfloat16 b0 = __float2bfloat16(x);
        float r = x - __bfloat162float(b0);
        d0[base + i] = b0; d1[base + i] = __float2bfloat16(r);
    }
}

__device__ __forceinline__ void split8_store(float4 v0, float4 v1,
                                             __nv_bfloat16* dhi, __nv_bfloat16* dlo) {
    float f[8] = {v0.x, v0.y, v0.z, v0.w, v1.x, v1.y, v1.z, v1.w};
    uint32_t hw[4], lw[4];
    #pragma unroll
    for (int i = 0; i < 4; i++) {
        __nv_bfloat16 h0 = __float2bfloat16(f[2*i]);
        __nv_bfloat16 h1 = __float2bfloat16(f[2*i+1]);
        __nv_bfloat162 hp = __halves2bfloat162(h0, h1);
        hw[i] = *(uint32_t*)&hp;
        __nv_bfloat16 l0 = __float2bfloat16(f[2*i]   - __bfloat162float(h0));
        __nv_bfloat16 l1 = __float2bfloat16(f[2*i+1] - __bfloat162float(h1));
        __nv_bfloat162 lp = __halves2bfloat162(l0, l1);
        lw[i] = *(uint32_t*)&lp;
    }
    *(uint4*)dhi = make_uint4(hw[0], hw[1], hw[2], hw[3]);
    *(uint4*)dlo = make_uint4(lw[0], lw[1], lw[2], lw[3]);
}

// ---- pipelined chunk-32 double-buffered smem layout ----
#define SPAD 40
#define BOFF (4*128*SPAD)
#define ASP(b,s,r,c) dyn[(((b)*2+(s))*128 + (r))*SPAD + (c)]
#define BSP(b,s,r,c) dyn[BOFF + (((b)*2+(s))*128 + (r))*SPAD + (c)]
#define DYN_BYTES (2*BOFF*2)

#define MMA_FRAGS_P(B) \
    uint32_t af[2][4][4], bfr[2][4][2]; \
    _Pragma("unroll") \
    for (int s = 0; s < 2; s++) { \
        _Pragma("unroll") \
        for (int mi = 0; mi < 4; mi++) { \
            int r0 = wm + mi*16 + g; \
            af[s][mi][0] = *(const uint32_t*)&ASP(B, s, r0,   kk + tg*2); \
            af[s][mi][1] = *(const uint32_t*)&ASP(B, s, r0+8, kk + tg*2); \
            af[s][mi][2] = *(const uint32_t*)&ASP(B, s, r0,   kk + tg*2 + 8); \
            af[s][mi][3] = *(const uint32_t*)&ASP(B, s, r0+8, kk + tg*2 + 8); \
        } \
        _Pragma("unroll") \
        for (int ni = 0; ni < 4; ni++) { \
            int c0 = wn + ni*8 + g; \
            bfr[s][ni][0] = *(const uint32_t*)&BSP(B, s, c0, kk + tg*2); \
            bfr[s][ni][1] = *(const uint32_t*)&BSP(B, s, c0, kk + tg*2 + 8); \
        } \
    } \
    _Pragma("unroll") \
    for (int p = 0; p < 3; p++) { \
        const int sa = (p == 2) ? 1 : 0, sb = (p == 1) ? 1 : 0; \
        _Pragma("unroll") \
        for (int mi = 0; mi < 4; mi++) \
            _Pragma("unroll") \
            for (int ni = 0; ni < 4; ni++) \
                asm volatile( \
                    "mma.sync.aligned.m16n8k16.row.col.f32.bf16.bf16.f32 " \
                    "{%0,%1,%2,%3}, {%4,%5,%6,%7}, {%8,%9}, {%0,%1,%2,%3};" \
                    : "+f"(acc[mi][ni][0]), "+f"(acc[mi][ni][1]), \
                      "+f"(acc[mi][ni][2]), "+f"(acc[mi][ni][3]) \
                    : "r"(af[sa][mi][0]), "r"(af[sa][mi][1]), \
                      "r"(af[sa][mi][2]), "r"(af[sa][mi][3]), \
                      "r"(bfr[sb][ni][0]), "r"(bfr[sb][ni][1])); \
    }

// pipelined NT GEMM body (fp32 in, fused split): C[r][j] = sum_t A[r][t]B[j][t] + bias[j]
__device__ __forceinline__ void gemm_body(const float* __restrict__ A,
                                          const float* __restrict__ B,
                                          const float* __restrict__ bias,
                                          float* __restrict__ Co,
                                          __nv_bfloat16* dyn) {
    const int tid = threadIdx.x, warp = tid >> 5, lane = tid & 31;
    const int g = lane >> 2, tg = lane & 3;
    const int i0 = blockIdx.x * 128, j0 = blockIdx.y * 128;
    const int wm = (warp & 1) * 64, wn = (warp >> 1) * 32;
    float acc[4][4][4];
    #pragma unroll
    for (int mi = 0; mi < 4; mi++)
        #pragma unroll
        for (int ni = 0; ni < 4; ni++)
            #pragma unroll
            for (int e = 0; e < 4; e++) acc[mi][ni][e] = 0.0f;
    const int lrow = tid >> 1, half = tid & 1;
    const float* Abase = A + (size_t)(i0 + lrow) * CC;
    const float* Bbase = B + (size_t)(j0 + lrow) * CC;
    #pragma unroll
    for (int u = 0; u < 2; u++) {
        int seg = half*2 + u;
        split8_store(*(const float4*)(Abase + seg*8), *(const float4*)(Abase + seg*8 + 4),
                     &ASP(0,0,lrow,seg*8), &ASP(0,1,lrow,seg*8));
        split8_store(*(const float4*)(Bbase + seg*8), *(const float4*)(Bbase + seg*8 + 4),
                     &BSP(0,0,lrow,seg*8), &BSP(0,1,lrow,seg*8));
    }
    __syncthreads();
    const int NCH = CC/32;
    for (int ci = 0; ci < NCH; ci++) {
        const int cur = ci & 1;
        float4 ra[4], rb[4];
        if (ci + 1 < NCH) {
            int k0 = (ci+1)*32;
            #pragma unroll
            for (int u = 0; u < 2; u++) {
                int seg = half*2 + u;
                ra[2*u+0] = *(const float4*)(Abase + k0 + seg*8);
                ra[2*u+1] = *(const float4*)(Abase + k0 + seg*8 + 4);
                rb[2*u+0] = *(const float4*)(Bbase + k0 + seg*8);
                rb[2*u+1] = *(const float4*)(Bbase + k0 + seg*8 + 4);
            }
        }
        #pragma unroll
        for (int kk = 0; kk < 32; kk += 16) { MMA_FRAGS_P(cur) }
        if (ci + 1 < NCH) {
            int nb = cur ^ 1;
            #pragma unroll
            for (int u = 0; u < 2; u++) {
                int seg = half*2 + u;
                split8_store(ra[2*u], ra[2*u+1], &ASP(nb,0,lrow,seg*8), &ASP(nb,1,lrow,seg*8));
                split8_store(rb[2*u], rb[2*u+1], &BSP(nb,0,lrow,seg*8), &BSP(nb,1,lrow,seg*8));
            }
        }
        __syncthreads();
    }
    #pragma unroll
    for (int mi = 0; mi < 4; mi++) {
        int r0 = i0 + wm + mi*16 + g;
        #pragma unroll
        for (int ni = 0; ni < 4; ni++) {
            int c = j0 + wn + ni*8 + tg*2;
            float b0v = bias[c], b1v = bias[c+1];
            Co[(size_t)r0*CC + c]       = acc[mi][ni][0] + b0v;
            Co[(size_t)r0*CC + c+1]     = acc[mi][ni][1] + b1v;
            Co[(size_t)(r0+8)*CC + c]   = acc[mi][ni][2] + b0v;
            Co[(size_t)(r0+8)*CC + c+1] = acc[mi][ni][3] + b1v;
        }
    }
}

__global__ __launch_bounds__(256) void k_gemm3(
    const float* xq, const float* Wq, const float* bq, float* oq,
    const float* xk, const float* Wk, const float* bk, float* ok,
    const float* xv, const float* Wv, const float* bv, float* ov) {
    extern __shared__ __nv_bfloat16 dyn[];
    if (blockIdx.z == 0)      gemm_body(xq, Wq, bq, oq, dyn);
    else if (blockIdx.z == 1) gemm_body(xk, Wk, bk, ok, dyn);
    else                      gemm_body(xv, Wv, bv, ov, dyn);
}

__global__ __launch_bounds__(256) void k_gemm1(
    const float* A, const float* B, const float* bias, float* Co) {
    extern __shared__ __nv_bfloat16 dyn[];
    gemm_body(A, B, bias, Co, dyn);
}

// pipelined HMMA simE (bf16 inputs, straight uint4 prefetch)
__global__ __launch_bounds__(256) void k_simE_mma() {
    extern __shared__ __nv_bfloat16 dyn[];
    const int tid = threadIdx.x, warp = tid >> 5, lane = tid & 31;
    const int g = lane >> 2, tg = lane & 3;
    const int bb = blockIdx.z, m0 = blockIdx.x * 128, n0 = blockIdx.y * 128;
    const int wm = (warp & 1) * 64, wn = (warp >> 1) * 32;
    float acc[4][4][4];
    #pragma unroll
    for (int mi = 0; mi < 4; mi++)
        #pragma unroll
        for (int ni = 0; ni < 4; ni++)
            #pragma unroll
            for (int e = 0; e < 4; e++) acc[mi][ni][e] = 0.0f;
    const int lrow = tid >> 1, half = tid & 1;
    const __nv_bfloat16* K0 = g_ks0 + (size_t)(bb*MM + m0 + lrow) * CC;
    const __nv_bfloat16* K1 = g_ks1 + (size_t)(bb*MM + m0 + lrow) * CC;
    const __nv_bfloat16* Q0 = g_qs0 + ((size_t)(n0 + lrow)*NB + bb) * CC;
    const __nv_bfloat16* Q1 = g_qs1 + ((size_t)(n0 + lrow)*NB + bb) * CC;
    #pragma unroll
    for (int u = 0; u < 2; u++) {
        int seg = half*2 + u;
        *(uint4*)&ASP(0,0,lrow,seg*8) = *(const uint4*)(K0 + seg*8);
        *(uint4*)&ASP(0,1,lrow,seg*8) = *(const uint4*)(K1 + seg*8);
        *(uint4*)&BSP(0,0,lrow,seg*8) = *(const uint4*)(Q0 + seg*8);
        *(uint4*)&BSP(0,1,lrow,seg*8) = *(const uint4*)(Q1 + seg*8);
    }
    __syncthreads();
    const int NCH = CC/32;
    for (int ci = 0; ci < NCH; ci++) {
        const int cur = ci & 1;
        uint4 rk0[2], rk1[2], rq0[2], rq1[2];
        if (ci + 1 < NCH) {
            int k0 = (ci+1)*32;
            #pragma unroll
            for (int u = 0; u < 2; u++) {
                int seg = half*2 + u;
                rk0[u] = *(const uint4*)(K0 + k0 + seg*8);
                rk1[u] = *(const uint4*)(K1 + k0 + seg*8);
                rq0[u] = *(const uint4*)(Q0 + k0 + seg*8);
                rq1[u] = *(const uint4*)(Q1 + k0 + seg*8);
            }
        }
        #pragma unroll
        for (int kk = 0; kk < 32; kk += 16) { MMA_FRAGS_P(cur) }
        if (ci + 1 < NCH) {
            int nb = cur ^ 1;
            #pragma unroll
            for (int u = 0; u < 2; u++) {
                int seg = half*2 + u;
                *(uint4*)&ASP(nb,0,lrow,seg*8) = rk0[u];
                *(uint4*)&ASP(nb,1,lrow,seg*8) = rk1[u];
                *(uint4*)&BSP(nb,0,lrow,seg*8) = rq0[u];
                *(uint4*)&BSP(nb,1,lrow,seg*8) = rq1[u];
            }
        }
        __syncthreads();
    }
    #pragma unroll
    for (int mi = 0; mi < 4; mi++) {
        int mA = m0 + wm + mi*16 + g;
        int mB = mA + 8;
        int mkA = g_maskb[bb*MM + mA], mkB = g_maskb[bb*MM + mB];
        size_t baseA = ((size_t)bb*MM + mA) * NQ;
        size_t baseB = ((size_t)bb*MM + mB) * NQ;
        #pragma unroll
        for (int ni = 0; ni < 4; ni++) {
            int c = n0 + wn + ni*8 + tg*2;
            float s0 = acc[mi][ni][0], s1 = acc[mi][ni][1];
            float s2 = acc[mi][ni][2], s3 = acc[mi][ni][3];
            g_sim[baseA + c]   = s0; g_sim[baseA + c+1] = s1;
            g_sim[baseB + c]   = s2; g_sim[baseB + c+1] = s3;
            float e0 = mkA ? expf((s0 - 1.0f) * EPS_INV) : 0.0f;
            float e1 = mkA ? expf((s1 - 1.0f) * EPS_INV) : 0.0f;
            float e2 = mkB ? expf((s2 - 1.0f) * EPS_INV) : 0.0f;
            float e3 = mkB ? expf((s3 - 1.0f) * EPS_INV) : 0.0f;
            g_E[baseA + c]   = e0; g_E[baseA + c+1] = e1;
            g_E[baseB + c]   = e2; g_E[baseB + c+1] = e3;
            g_Ebf[baseA + c]   = __float2bfloat16(e0);
            g_Ebf[baseA + c+1] = __float2bfloat16(e1);
            g_Ebf[baseB + c]   = __float2bfloat16(e2);
            g_Ebf[baseB + c+1] = __float2bfloat16(e3);
        }
    }
}

// HMMA TN xgemm (static smem, chunk 32 — unchanged from R9/R10)
#define MMA_FRAGS_S \
    uint32_t af[2][4][4], bfr[2][4][2]; \
    _Pragma("unroll") \
    for (int s = 0; s < 2; s++) { \
        _Pragma("unroll") \
        for (int mi = 0; mi < 4; mi++) { \
            int r0 = wm + mi*16 + g; \
            af[s][mi][0] = *(const uint32_t*)&As[s][r0][kk + tg*2]; \
            af[s][mi][1] = *(const uint32_t*)&As[s][r0+8][kk + tg*2]; \
            af[s][mi][2] = *(const uint32_t*)&As[s][r0][kk + tg*2 + 8]; \
            af[s][mi][3] = *(const uint32_t*)&As[s][r0+8][kk + tg*2 + 8]; \
        } \
        _Pragma("unroll") \
        for (int ni = 0; ni < 4; ni++) { \
            int c0 = wn + ni*8 + g; \
            bfr[s][ni][0] = *(const uint32_t*)&Bs[s][c0][kk + tg*2]; \
            bfr[s][ni][1] = *(const uint32_t*)&Bs[s][c0][kk + tg*2 + 8]; \
        } \
    } \
    _Pragma("unroll") \
    for (int p = 0; p < 3; p++) { \
        const int sa = (p == 2) ? 1 : 0, sb = (p == 1) ? 1 : 0; \
        _Pragma("unroll") \
        for (int mi = 0; mi < 4; mi++) \
            _Pragma("unroll") \
            for (int ni = 0; ni < 4; ni++) \
                asm volatile( \
                    "mma.sync.aligned.m16n8k16.row.col.f32.bf16.bf16.f32 " \
                    "{%0,%1,%2,%3}, {%4,%5,%6,%7}, {%8,%9}, {%0,%1,%2,%3};" \
                    : "+f"(acc[mi][ni][0]), "+f"(acc[mi][ni][1]), \
                      "+f"(acc[mi][ni][2]), "+f"(acc[mi][ni][3]) \
                    : "r"(af[sa][mi][0]), "r"(af[sa][mi][1]), \
                      "r"(af[sa][mi][2]), "r"(af[sa][mi][3]), \
                      "r"(bfr[sb][ni][0]), "r"(bfr[sb][ni][1])); \
    }

__global__ __launch_bounds__(256) void k_xgemm_mma() {
    __shared__ __nv_bfloat16 As[2][128][SPAD];
    __shared__ __nv_bfloat16 Bs[2][128][SPAD];
    const int tid = threadIdx.x, warp = tid >> 5, lane = tid & 31;
    const int g = lane >> 2, tg = lane & 3;
    const int bb = blockIdx.z, n0 = blockIdx.x * 128, c0 = blockIdx.y * 128;
    const int wm = (warp & 1) * 64, wn = (warp >> 1) * 32;
    float acc[4][4][4];
    #pragma unroll
    for (int mi = 0; mi < 4; mi++)
        #pragma unroll
        for (int ni = 0; ni < 4; ni++)
            #pragma unroll
            for (int e = 0; e < 4; e++) acc[mi][ni][e] = 0.0f;
    const float* Eb = g_E + (size_t)bb*MM*NQ;
    const float* Vb = g_v + (size_t)bb*MM*CC;
    const int lm = tid & 31, lg = tid >> 5;
    for (int k0 = 0; k0 < MM; k0 += 32) {
        int m = k0 + lm;
        float am = g_a[bb*MM + m];
        #pragma unroll
        for (int j = 0; j < 4; j++) {
            int n = lg*16 + j*4;
            float4 ev = *(const float4*)(Eb + (size_t)m*NQ + n0 + n);
            float4 vv = *(const float4*)(Vb + (size_t)m*CC + c0 + n);
            vv.x *= am; vv.y *= am; vv.z *= am; vv.w *= am;
            float ee[4] = {ev.x, ev.y, ev.z, ev.w};
            float va[4] = {vv.x, vv.y, vv.z, vv.w};
            #pragma unroll
            for (int q = 0; q < 4; q++) {
                __nv_bfloat16 h = __float2bfloat16(ee[q]);
                As[0][n + q][lm] = h;
                As[1][n + q][lm] = __float2bfloat16(ee[q] - __bfloat162float(h));
                __nv_bfloat16 hv = __float2bfloat16(va[q]);
                Bs[0][n + q][lm] = hv;
                Bs[1][n + q][lm] = __float2bfloat16(va[q] - __bfloat162float(hv));
            }
        }
        __syncthreads();
        #pragma unroll
        for (int kk = 0; kk < 32; kk += 16) { MMA_FRAGS_S }
        __syncthreads();
    }
    #pragma unroll
    for (int mi = 0; mi < 4; mi++) {
        int nA = n0 + wm + mi*16 + g;
        int nB = nA + 8;
        float bnA = g_bfin[bb*NQ + nA], bnB = g_bfin[bb*NQ + nB];
        #pragma unroll
        for (int ni = 0; ni < 4; ni++) {
            int c = c0 + wn + ni*8 + tg*2;
            g_x[((size_t)nA*NB + bb)*CC + c]   = acc[mi][ni][0] * bnA;
            g_x[((size_t)nA*NB + bb)*CC + c+1] = acc[mi][ni][1] * bnA;
            g_x[((size_t)nB*NB + bb)*CC + c]   = acc[mi][ni][2] * bnB;
            g_x[((size_t)nB*NB + bb)*CC + c+1] = acc[mi][ni][3] * bnB;
        }
    }
}

// persistent Sinkhorn with smem-resident bf16 E
#define SINK_SMEM (64*NQ*2 + 8*NQ*4)
__global__ __launch_bounds__(256) void k_sink_pers() {
    extern __shared__ char dsm[];
    __nv_bfloat16* Es = (__nv_bfloat16*)dsm;
    float* shred = (float*)(dsm + 64*NQ*2);
    const int blk = blockIdx.x, bb = blk >> 4, rb = blk & 15;
    const int tid = threadIdx.x, warp = tid >> 5, lane = tid & 31;
    const int col = tid * 4;
    {
        const uint4* src = (const uint4*)(g_Ebf + ((size_t)bb*MM + rb*64) * NQ);
        uint4* dst = (uint4*)Es;
        for (int i = tid; i < 64*NQ/8; i += 256) dst[i] = src[i];
    }
    __syncthreads();
    float bv[32];
    #pragma unroll
    for (int q = 0; q < 32; q++) bv[q] = 1.0f;
    for (int it = 1; it <= NITER; it++) {
        float cacc[32];
        #pragma unroll
        for (int q = 0; q < 32; q++) cacc[q] = 0.0f;
        #pragma unroll
        for (int rr = 0; rr < 8; rr++) {
            int lr = warp*8 + rr;
            int m = rb*64 + lr;
            if (!g_maskb[bb*MM + m]) {
                if (it == NITER && lane == 0) g_a[bb*MM + m] = 0.0f;
                continue;
            }
            const __nv_bfloat16* er = Es + (size_t)lr * NQ;
            float e[32], s = 0.0f;
            #pragma unroll
            for (int g = 0; g < 8; g++) {
                uint2 w = *(const uint2*)(er + g*128 + lane*4);
                __nv_bfloat162 p0 = *(__nv_bfloat162*)&w.x;
                __nv_bfloat162 p1 = *(__nv_bfloat162*)&w.y;
                e[g*4+0] = __bfloat162float(__low2bfloat16(p0));
                e[g*4+1] = __bfloat162float(__high2bfloat16(p0));
                e[g*4+2] = __bfloat162float(__low2bfloat16(p1));
                e[g*4+3] = __bfloat162float(__high2bfloat16(p1));
                s += e[g*4+0]*bv[g*4+0] + e[g*4+1]*bv[g*4+1]
                   + e[g*4+2]*bv[g*4+2] + e[g*4+3]*bv[g*4+3];
            }
            #pragma unroll
            for (int o = 16; o; o >>= 1) s += __shfl_xor_sync(0xffffffffu, s, o);
            float a = g_mu[bb*MM + m] / s;
            if (it == NITER && lane == 0) g_a[bb*MM + m] = a;
            #pragma unroll
            for (int q = 0; q < 32; q++) cacc[q] += a * e[q];
        }
        #pragma unroll
        for (int g = 0; g < 8; g++)
            *(float4*)&shred[warp*1024 + g*128 + lane*4] =
                make_float4(cacc[g*4], cacc[g*4+1], cacc[g*4+2], cacc[g*4+3]);
        __syncthreads();
        float s0=0, s1=0, s2=0, s3=0;
        #pragma unroll
        for (int w = 0; w < 8; w++) {
            float4 v = *(const float4*)&shred[w*1024 + col];
            s0 += v.x; s1 += v.y; s2 += v.z; s3 += v.w;
        }
        *(float4*)&g_cpart[(size_t)blk*NQ + col] = make_float4(s0, s1, s2, s3);
        __threadfence();
        __syncthreads();
        if (tid == 0) {
            atomicAdd(&g_bar8[bb], 1u);
            unsigned int target = (unsigned int)it * 16u;
            while (atomicAdd(&g_bar8[bb], 0u) < target) __nanosleep(64);
        }
        __syncthreads();
        __threadfence();
        if (it < NITER) {
            float c0=0, c1=0, c2=0, c3=0;
            #pragma unroll
            for (int w = 0; w < 16; w++) {
                float4 v = *(const float4*)&g_cpart[(size_t)(bb*16 + w)*NQ + col];
                c0 += v.x; c1 += v.y; c2 += v.z; c3 += v.w;
            }
            shred[col+0] = NU_P / c0; shred[col+1] = NU_P / c1;
            shred[col+2] = NU_P / c2; shred[col+3] = NU_P / c3;
            __syncthreads();
            #pragma unroll
            for (int g = 0; g < 8; g++) {
                float4 v = *(const float4*)&shred[g*128 + lane*4];
                bv[g*4+0]=v.x; bv[g*4+1]=v.y; bv[g*4+2]=v.z; bv[g*4+3]=v.w;
            }
            __syncthreads();
        }
    }
    if (rb == 0) {
        float c0=0, c1=0, c2=0, c3=0;
        #pragma unroll
        for (int w = 0; w < 16; w++) {
            float4 v = *(const float4*)&g_cpart[(size_t)(bb*16 + w)*NQ + col];
            c0 += v.x; c1 += v.y; c2 += v.z; c3 += v.w;
        }
        g_bfin[bb*NQ+col+0] = NU_P / c0; g_bfin[bb*NQ+col+1] = NU_P / c1;
        g_bfin[bb*NQ+col+2] = NU_P / c2; g_bfin[bb*NQ+col+3] = NU_P / c3;
    }
}

__global__ void k_attn(float* outp) {
    const int warp = threadIdx.x >> 5, lane = threadIdx.x & 31;
    int r = blockIdx.x * 8 + warp;
    if (r >= RR) return;
    int bb = r >> 10;
    float val = 0.0f;
    if (g_maskb[r]) {
        const float* S = g_sim + (size_t)r * NQ;
        const float* E = g_E + (size_t)r * NQ;
        const float* bf = g_bfin + bb * NQ;
        float s = 0.0f;
        #pragma unroll
        for (int g = 0; g < 8; g++) {
            int n = g*128 + lane*4;
            float4 sv = *(const float4*)(S + n);
            float4 ev = *(const float4*)(E + n);
            float4 bv = *(const float4*)(bf + n);
            s += sv.x*ev.x*bv.x + sv.y*ev.y*bv.y + sv.z*ev.z*bv.z + sv.w*ev.w*bv.w;
        }
        #pragma unroll
        for (int o = 16; o; o >>= 1) s += __shfl_xor_sync(0xffffffffu, s, o);
        val = 1048576.0f * g_a[r] * s;
    }
    if (lane == 0) outp[r] = val;
}

extern "C" void kernel_launch(void* const* d_in, const int* in_sizes, int n_in,
                              void* d_out, int out_size) {
    const float* xq = (const float*)d_in[0];
    const float* xk = (const float*)d_in[1];
    const float* xv = (const float*)d_in[2];
    const void*  mk = d_in[3];
    const float* Wq = (const float*)d_in[4];
    const float* bq = (const float*)d_in[5];
    const float* Wk = (const float*)d_in[6];
    const float* bk = (const float*)d_in[7];
    const float* Wv = (const float*)d_in[8];
    const float* bv = (const float*)d_in[9];
    const float* Wp = (const float*)d_in[10];
    const float* bp = (const float*)d_in[11];
    float *qp, *kp, *vp, *xp;
    __nv_bfloat16 *q0, *q1, *ks0, *ks1;
    cudaGetSymbolAddress((void**)&qp, g_q);
    cudaGetSymbolAddress((void**)&kp, g_k);
    cudaGetSymbolAddress((void**)&vp, g_v);
    cudaGetSymbolAddress((void**)&xp, g_x);
    cudaGetSymbolAddress((void**)&q0, g_qs0);
    cudaGetSymbolAddress((void**)&q1, g_qs1);
    cudaGetSymbolAddress((void**)&ks0, g_ks0);
    cudaGetSymbolAddress((void**)&ks1, g_ks1);
    cudaFuncSetAttribute(k_gemm3, cudaFuncAttributeMaxDynamicSharedMemorySize, DYN_BYTES);
    cudaFuncSetAttribute(k_gemm1, cudaFuncAttributeMaxDynamicSharedMemorySize, DYN_BYTES);
    cudaFuncSetAttribute(k_simE_mma, cudaFuncAttributeMaxDynamicSharedMemorySize, DYN_BYTES);
    cudaFuncSetAttribute(k_sink_pers, cudaFuncAttributeMaxDynamicSharedMemorySize, SINK_SMEM);

    k_detect<<<1, 256>>>((const unsigned char*)mk);
    k_counts<<<NB, 256>>>(mk);
    k_init<<<(RR + 255)/256, 256>>>(mk);

    k_gemm3<<<dim3(RR/128, CC/128, 3), 256, DYN_BYTES>>>(
        xq, Wq, bq, qp, xk, Wk, bk, kp, xv, Wv, bv, vp);

    k_l2split<<<RR, 256>>>(qp, q0, q1);
    k_l2split<<<RR, 256>>>(kp, ks0, ks1);

    k_simE_mma<<<dim3(MM/128, NQ/128, NB), 256, DYN_BYTES>>>();

    k_sink_pers<<<128, 256, SINK_SMEM>>>();

    k_xgemm_mma<<<dim3(NQ/128, CC/128, NB), 256>>>();

    k_gemm1<<<dim3(RR/128, CC/128), 256, DYN_BYTES>>>(xp, Wp, bp, (float*)d_out);

    if (out_size >= RR*CC + RR)
        k_attn<<<RR/8, 256>>>((float*)d_out + (size_t)RR*CC);
}